// round 3
// baseline (speedup 1.0000x reference)
#include <cuda_runtime.h>
#include <math.h>

#define N_TOK 1024
#define DM    512
#define H     8
#define DK    64
#define NH    8192          // N_TOK * H
#define SCALE 0.125f        // 1/sqrt(64)

// ---------------- scratch (device globals; no allocation) ----------------
__device__ float g_q[N_TOK * DM];
__device__ float g_k[N_TOK * DM];
__device__ float g_v[N_TOK * DM];
__device__ float g_scores[(size_t)N_TOK * H * N_TOK];  // [i][h][j], 33.5 MB
__device__ float g_accv[N_TOK * DM];                   // [i][h][d]
__device__ float g_acct[N_TOK * DM];                   // [i][h][e]
__device__ float g_outpre[N_TOK * DM];

// ---------------- generic GEMM: C = act(A[M,K] @ B[K,N] + bias) ----------
// BM=64, BN=64, BK=16, 256 threads, 4x4 register tile per thread
template <bool RELU>
__global__ void gemm_bias_kernel(const float* __restrict__ A,
                                 const float* __restrict__ B,
                                 const float* __restrict__ bias,
                                 float* __restrict__ C,
                                 int M, int N, int K) {
    __shared__ float As[16][68];  // [k][m] (transposed), pitch 68 = 17 float4
    __shared__ float Bs[16][68];  // [k][n]
    int t  = threadIdx.x;
    int tx = t % 16;              // n quad
    int ty = t / 16;              // m quad
    int m0 = blockIdx.y * 64;
    int n0 = blockIdx.x * 64;

    float acc[4][4] = {};
    for (int k0 = 0; k0 < K; k0 += 16) {
        {   // A tile 64m x 16k -> As[k][m]
            int m  = t / 4;
            int k4 = (t % 4) * 4;
            float4 av = *(const float4*)(A + (size_t)(m0 + m) * K + k0 + k4);
            As[k4 + 0][m] = av.x; As[k4 + 1][m] = av.y;
            As[k4 + 2][m] = av.z; As[k4 + 3][m] = av.w;
        }
        {   // B tile 16k x 64n -> Bs[k][n]
            int k  = t / 16;
            int n4 = (t % 16) * 4;
            *(float4*)&Bs[k][n4] = *(const float4*)(B + (size_t)(k0 + k) * N + n0 + n4);
        }
        __syncthreads();
#pragma unroll
        for (int k = 0; k < 16; k++) {
            float4 av = *(const float4*)&As[k][ty * 4];
            float4 bv = *(const float4*)&Bs[k][tx * 4];
            acc[0][0] += av.x * bv.x; acc[0][1] += av.x * bv.y; acc[0][2] += av.x * bv.z; acc[0][3] += av.x * bv.w;
            acc[1][0] += av.y * bv.x; acc[1][1] += av.y * bv.y; acc[1][2] += av.y * bv.z; acc[1][3] += av.y * bv.w;
            acc[2][0] += av.z * bv.x; acc[2][1] += av.z * bv.y; acc[2][2] += av.z * bv.z; acc[2][3] += av.z * bv.w;
            acc[3][0] += av.w * bv.x; acc[3][1] += av.w * bv.y; acc[3][2] += av.w * bv.z; acc[3][3] += av.w * bv.w;
        }
        __syncthreads();
    }
    float4 bb = *(const float4*)(bias + n0 + tx * 4);
#pragma unroll
    for (int mi = 0; mi < 4; mi++) {
        float4 o;
        o.x = acc[mi][0] + bb.x; o.y = acc[mi][1] + bb.y;
        o.z = acc[mi][2] + bb.z; o.w = acc[mi][3] + bb.w;
        if (RELU) {
            o.x = fmaxf(o.x, 0.f); o.y = fmaxf(o.y, 0.f);
            o.z = fmaxf(o.z, 0.f); o.w = fmaxf(o.w, 0.f);
        }
        *(float4*)(C + (size_t)(m0 + ty * 4 + mi) * N + n0 + tx * 4) = o;
    }
}

// ---------------- K2: scores1[i][h][j] = q[i,h,:] . k[j,h,:] -------------
__global__ void qk_kernel(const float* __restrict__ q, const float* __restrict__ kk) {
    __shared__ float Qs[64][68];  // [e][i]
    __shared__ float Ks[64][68];  // [e][j]
    int h  = blockIdx.z;
    int i0 = blockIdx.y * 64;
    int j0 = blockIdx.x * 64;
    int t  = threadIdx.x;
    int tx = t % 16, ty = t / 16;

#pragma unroll
    for (int r = 0; r < 4; r++) {
        int fidx = r * 256 + t;
        int row  = fidx / 16;
        int e4   = (fidx % 16) * 4;
        float4 qv = *(const float4*)(q  + (size_t)(i0 + row) * DM + h * DK + e4);
        Qs[e4 + 0][row] = qv.x; Qs[e4 + 1][row] = qv.y; Qs[e4 + 2][row] = qv.z; Qs[e4 + 3][row] = qv.w;
        float4 kv = *(const float4*)(kk + (size_t)(j0 + row) * DM + h * DK + e4);
        Ks[e4 + 0][row] = kv.x; Ks[e4 + 1][row] = kv.y; Ks[e4 + 2][row] = kv.z; Ks[e4 + 3][row] = kv.w;
    }
    __syncthreads();

    float acc[4][4] = {};
#pragma unroll 8
    for (int e = 0; e < 64; e++) {
        float4 qv = *(const float4*)&Qs[e][ty * 4];
        float4 kv = *(const float4*)&Ks[e][tx * 4];
        acc[0][0] += qv.x * kv.x; acc[0][1] += qv.x * kv.y; acc[0][2] += qv.x * kv.z; acc[0][3] += qv.x * kv.w;
        acc[1][0] += qv.y * kv.x; acc[1][1] += qv.y * kv.y; acc[1][2] += qv.y * kv.z; acc[1][3] += qv.y * kv.w;
        acc[2][0] += qv.z * kv.x; acc[2][1] += qv.z * kv.y; acc[2][2] += qv.z * kv.z; acc[2][3] += qv.z * kv.w;
        acc[3][0] += qv.w * kv.x; acc[3][1] += qv.w * kv.y; acc[3][2] += qv.w * kv.z; acc[3][3] += qv.w * kv.w;
    }
#pragma unroll
    for (int mi = 0; mi < 4; mi++) {
        float4 o = make_float4(acc[mi][0], acc[mi][1], acc[mi][2], acc[mi][3]);
        *(float4*)(g_scores + (size_t)(i0 + ty * 4 + mi) * NH + h * N_TOK + j0 + tx * 4) = o;
    }
}

// ---------------- K3: structure-key scores (dominant kernel) -------------
// per block: one i. scores[i][h][j] = (scores1 + q[i,h,:].relu(S[i,j,:]@Wsk+bsk)) * SCALE
__global__ void sscore_kernel(const float* __restrict__ S,
                              const float* __restrict__ q,
                              const float* __restrict__ Wsk,
                              const float* __restrict__ bsk) {
    __shared__ float Wsh[64 * 64];   // [c][e]
    __shared__ float qsh[8 * 64];    // [h][e]
    __shared__ float Ssh[32 * 68];   // [j][c], pitch 68
    __shared__ float sksh[32 * 68];  // [j][e], pitch 68 (17 float4, odd => conflict-free cols)
    int i = blockIdx.x;
    int t = threadIdx.x;

#pragma unroll
    for (int r = 0; r < 4; r++) {
        int f = r * 256 + t;
        *(float4*)&Wsh[f * 4] = *(const float4*)(Wsk + f * 4);
    }
    if (t < 128) *(float4*)&qsh[t * 4] = *(const float4*)(q + (size_t)i * DM + t * 4);

    const int e4 = (t % 16) * 4;   // sk-phase: 4 consecutive e
    const int j2 = (t / 16) * 2;   // sk-phase: 2 consecutive j
    float4 bias4 = *(const float4*)(bsk + e4);
    const int sh = t >> 5;         // score-phase h
    const int sj = t & 31;         // score-phase j

    for (int j0 = 0; j0 < N_TOK; j0 += 32) {
        __syncthreads();  // previous-iter readers done
#pragma unroll
        for (int r = 0; r < 2; r++) {
            int f  = r * 256 + t;          // 0..511
            int j  = f / 16;
            int c4 = (f % 16) * 4;
            *(float4*)&Ssh[j * 68 + c4] =
                *(const float4*)(S + ((size_t)i * N_TOK + j0 + j) * 64 + c4);
        }
        __syncthreads();

        // sk = relu(S @ Wsk + b) for this thread's 2j x 4e block
        float4 a0 = make_float4(0.f, 0.f, 0.f, 0.f);
        float4 a1 = make_float4(0.f, 0.f, 0.f, 0.f);
#pragma unroll 16
        for (int c = 0; c < 64; c++) {
            float4 w = *(const float4*)&Wsh[c * 64 + e4];
            float s0 = Ssh[j2 * 68 + c];
            float s1 = Ssh[(j2 + 1) * 68 + c];
            a0.x += s0 * w.x; a0.y += s0 * w.y; a0.z += s0 * w.z; a0.w += s0 * w.w;
            a1.x += s1 * w.x; a1.y += s1 * w.y; a1.z += s1 * w.z; a1.w += s1 * w.w;
        }
        a0.x = fmaxf(a0.x + bias4.x, 0.f); a0.y = fmaxf(a0.y + bias4.y, 0.f);
        a0.z = fmaxf(a0.z + bias4.z, 0.f); a0.w = fmaxf(a0.w + bias4.w, 0.f);
        a1.x = fmaxf(a1.x + bias4.x, 0.f); a1.y = fmaxf(a1.y + bias4.y, 0.f);
        a1.z = fmaxf(a1.z + bias4.z, 0.f); a1.w = fmaxf(a1.w + bias4.w, 0.f);
        *(float4*)&sksh[j2 * 68 + e4]       = a0;
        *(float4*)&sksh[(j2 + 1) * 68 + e4] = a1;
        __syncthreads();

        // scores: one (h, j) per thread
        float acc = 0.f;
#pragma unroll
        for (int ee = 0; ee < 64; ee += 4) {
            float4 sv = *(const float4*)&sksh[sj * 68 + ee];
            float4 qv = *(const float4*)&qsh[sh * 64 + ee];
            acc += sv.x * qv.x + sv.y * qv.y + sv.z * qv.z + sv.w * qv.w;
        }
        size_t idx = (size_t)i * NH + sh * N_TOK + j0 + sj;
        g_scores[idx] = (g_scores[idx] + acc) * SCALE;
    }
}

// ---------------- K4: row softmax in place -------------------------------
__global__ void softmax_kernel() {
    int row = blockIdx.x;            // i*8 + h
    float* p = g_scores + (size_t)row * N_TOK;
    int t = threadIdx.x;
    int lane = t & 31, warp = t >> 5;
    __shared__ float red[32];

    float4 v = *(float4*)(p + t * 4);
    float m = fmaxf(fmaxf(v.x, v.y), fmaxf(v.z, v.w));
#pragma unroll
    for (int o = 16; o; o >>= 1) m = fmaxf(m, __shfl_xor_sync(0xffffffffu, m, o));
    if (lane == 0) red[warp] = m;
    __syncthreads();
    if (t < 32) {
        float mm = (t < 8) ? red[t] : -1e30f;
#pragma unroll
        for (int o = 4; o; o >>= 1) mm = fmaxf(mm, __shfl_xor_sync(0xffffffffu, mm, o));
        if (t == 0) red[0] = mm;
    }
    __syncthreads();
    float bm = red[0];
    __syncthreads();                 // everyone has read red[0]

    v.x = __expf(v.x - bm); v.y = __expf(v.y - bm);
    v.z = __expf(v.z - bm); v.w = __expf(v.w - bm);
    float s = v.x + v.y + v.z + v.w;
#pragma unroll
    for (int o = 16; o; o >>= 1) s += __shfl_xor_sync(0xffffffffu, s, o);
    if (lane == 0) red[warp] = s;
    __syncthreads();
    if (t < 32) {
        float ss = (t < 8) ? red[t] : 0.f;
#pragma unroll
        for (int o = 4; o; o >>= 1) ss += __shfl_xor_sync(0xffffffffu, ss, o);
        if (t == 0) red[0] = ss;
    }
    __syncthreads();
    float inv = 1.0f / red[0];
    v.x *= inv; v.y *= inv; v.z *= inv; v.w *= inv;
    *(float4*)(p + t * 4) = v;
}

// ---------------- K5a: acc_v[i,h,d] = sum_j p[i,h,j] * v[j,h,d] ----------
__global__ void accv_kernel(const float* __restrict__ v) {
    __shared__ float Ps[32][68];  // [j][i]
    __shared__ float Vs[32][68];  // [j][d]
    int i0 = blockIdx.x * 64;
    int h  = blockIdx.y;
    int t  = threadIdx.x;
    int tx = t % 16, ty = t / 16;

    float acc[4][4] = {};
    for (int j0 = 0; j0 < N_TOK; j0 += 32) {
#pragma unroll
        for (int r = 0; r < 2; r++) {
            int f  = r * 256 + t;
            int ii = f / 8;
            int j4 = (f % 8) * 4;
            float4 pv = *(const float4*)(g_scores + (size_t)(i0 + ii) * NH + h * N_TOK + j0 + j4);
            Ps[j4 + 0][ii] = pv.x; Ps[j4 + 1][ii] = pv.y; Ps[j4 + 2][ii] = pv.z; Ps[j4 + 3][ii] = pv.w;
        }
#pragma unroll
        for (int r = 0; r < 2; r++) {
            int f  = r * 256 + t;
            int j  = f / 16;
            int d4 = (f % 16) * 4;
            *(float4*)&Vs[j][d4] = *(const float4*)(v + (size_t)(j0 + j) * DM + h * DK + d4);
        }
        __syncthreads();
#pragma unroll 8
        for (int j = 0; j < 32; j++) {
            float4 pv = *(const float4*)&Ps[j][ty * 4];
            float4 vv = *(const float4*)&Vs[j][tx * 4];
            acc[0][0] += pv.x * vv.x; acc[0][1] += pv.x * vv.y; acc[0][2] += pv.x * vv.z; acc[0][3] += pv.x * vv.w;
            acc[1][0] += pv.y * vv.x; acc[1][1] += pv.y * vv.y; acc[1][2] += pv.y * vv.z; acc[1][3] += pv.y * vv.w;
            acc[2][0] += pv.z * vv.x; acc[2][1] += pv.z * vv.y; acc[2][2] += pv.z * vv.z; acc[2][3] += pv.z * vv.w;
            acc[3][0] += pv.w * vv.x; acc[3][1] += pv.w * vv.y; acc[3][2] += pv.w * vv.z; acc[3][3] += pv.w * vv.w;
        }
        __syncthreads();
    }
#pragma unroll
    for (int mi = 0; mi < 4; mi++) {
        float4 o = make_float4(acc[mi][0], acc[mi][1], acc[mi][2], acc[mi][3]);
        *(float4*)(g_accv + (size_t)(i0 + ty * 4 + mi) * DM + h * DK + tx * 4) = o;
    }
}

// ---------------- K5b: acc_t[i,h,e] = sum_j p[i,h,j] * S[i,j,e] ----------
__global__ void acct_kernel(const float* __restrict__ S) {
    __shared__ float Ssh[64 * 68];   // [j][e]
    __shared__ float psh[8 * 64];    // [h][j-tile]
    __shared__ float red[8 * 64];
    int i = blockIdx.x;
    int t = threadIdx.x;
    const int e4 = (t % 16) * 4;
    const int h  = (t / 16) % 8;
    const int jh = t / 128;          // j half: 0 or 1

    float4 acc = make_float4(0.f, 0.f, 0.f, 0.f);
    for (int j0 = 0; j0 < N_TOK; j0 += 64) {
        __syncthreads();
#pragma unroll
        for (int r = 0; r < 4; r++) {
            int f  = r * 256 + t;
            int j  = f / 16;
            int c4 = (f % 16) * 4;
            *(float4*)&Ssh[j * 68 + c4] =
                *(const float4*)(S + ((size_t)i * N_TOK + j0 + j) * 64 + c4);
        }
        if (t < 128) {
            int hh = t / 16;
            int j4 = (t % 16) * 4;
            *(float4*)&psh[hh * 64 + j4] =
                *(const float4*)(g_scores + (size_t)i * NH + hh * N_TOK + j0 + j4);
        }
        __syncthreads();
        int jb = jh * 32;
#pragma unroll 8
        for (int j = jb; j < jb + 32; j++) {
            float4 s = *(const float4*)&Ssh[j * 68 + e4];
            float  pp = psh[h * 64 + j];
            acc.x += pp * s.x; acc.y += pp * s.y; acc.z += pp * s.z; acc.w += pp * s.w;
        }
    }
    __syncthreads();
    if (jh == 1) *(float4*)&red[h * 64 + e4] = acc;
    __syncthreads();
    if (jh == 0) {
        float4 o = *(const float4*)&red[h * 64 + e4];
        o.x += acc.x; o.y += acc.y; o.z += acc.z; o.w += acc.w;
        *(float4*)(g_acct + (size_t)i * DM + h * DK + e4) = o;
    }
}

// ---------------- K6: out_pre = acc_v + acc_t @ Wsv + bsv ----------------
__global__ void combine_kernel(const float* __restrict__ Wsv, const float* __restrict__ bsv) {
    __shared__ float Wsh[64 * 64];  // [e][d]
    __shared__ float tsh[8 * 64];   // [h][e]
    int i = blockIdx.x;
    int t = threadIdx.x;
#pragma unroll
    for (int r = 0; r < 4; r++) {
        int f = r * 256 + t;
        *(float4*)&Wsh[f * 4] = *(const float4*)(Wsv + f * 4);
    }
    if (t < 128) *(float4*)&tsh[t * 4] = *(const float4*)(g_acct + (size_t)i * DM + t * 4);
    __syncthreads();
    int d  = t % 64;
    int h0 = t / 64;
    float bd = bsv[d];
#pragma unroll
    for (int r = 0; r < 2; r++) {
        int h = h0 + r * 4;
        float a = 0.f;
#pragma unroll 16
        for (int e = 0; e < 64; e++) a += tsh[h * 64 + e] * Wsh[e * 64 + d];
        g_outpre[(size_t)i * DM + h * DK + d] =
            g_accv[(size_t)i * DM + h * DK + d] + a + bd;
    }
}

// ---------------- launch ----------------
extern "C" void kernel_launch(void* const* d_in, const int* in_sizes, int n_in,
                              void* d_out, int out_size) {
    const float* x   = (const float*)d_in[0];
    const float* S   = (const float*)d_in[1];
    const float* Wq  = (const float*)d_in[2];  const float* bq  = (const float*)d_in[3];
    const float* Wk  = (const float*)d_in[4];  const float* bk  = (const float*)d_in[5];
    const float* Wv  = (const float*)d_in[6];  const float* bv  = (const float*)d_in[7];
    const float* Wo  = (const float*)d_in[8];  const float* bo  = (const float*)d_in[9];
    const float* Wsk = (const float*)d_in[10]; const float* bsk = (const float*)d_in[11];
    const float* Wsv = (const float*)d_in[12]; const float* bsv = (const float*)d_in[13];
    float* out = (float*)d_out;

    void *pq, *pk, *pv, *pop;
    cudaGetSymbolAddress(&pq,  g_q);
    cudaGetSymbolAddress(&pk,  g_k);
    cudaGetSymbolAddress(&pv,  g_v);
    cudaGetSymbolAddress(&pop, g_outpre);

    dim3 gemm_grid(DM / 64, N_TOK / 64);
    gemm_bias_kernel<true ><<<gemm_grid, 256>>>(x, Wq, bq, (float*)pq, N_TOK, DM, DM);
    gemm_bias_kernel<true ><<<gemm_grid, 256>>>(x, Wk, bk, (float*)pk, N_TOK, DM, DM);
    gemm_bias_kernel<false><<<gemm_grid, 256>>>(x, Wv, bv, (float*)pv, N_TOK, DM, DM);

    qk_kernel<<<dim3(16, 16, 8), 256>>>((const float*)pq, (const float*)pk);

    sscore_kernel<<<N_TOK, 256>>>(S, (const float*)pq, Wsk, bsk);

    softmax_kernel<<<NH, 256>>>();

    accv_kernel<<<dim3(16, 8), 256>>>((const float*)pv);
    acct_kernel<<<N_TOK, 256>>>(S);

    combine_kernel<<<N_TOK, 256>>>(Wsv, bsv);

    gemm_bias_kernel<false><<<gemm_grid, 256>>>((const float*)pop, Wo, bo, out, N_TOK, DM, DM);
}

// round 5
// speedup vs baseline: 1.7059x; 1.7059x over previous
#include <cuda_runtime.h>
#include <cuda_bf16.h>
#include <math.h>
#include <stdint.h>

#define N_TOK 1024
#define DM    512
#define H     8
#define DK    64
#define NH    8192          // N_TOK * H
#define SCALE 0.125f        // 1/sqrt(64)

// ---------------- scratch (device globals; no allocation) ----------------
__device__ float g_q[N_TOK * DM];
__device__ float g_k[N_TOK * DM];
__device__ float g_v[N_TOK * DM];
__device__ float g_scores[(size_t)N_TOK * H * N_TOK];  // [i][h][j], 33.5 MB
__device__ float g_accv[N_TOK * DM];                   // [i][h][d]
__device__ float g_acct[N_TOK * DM];                   // [i][h][e]
__device__ float g_outpre[N_TOK * DM];

// ---------------- small asm helpers ----------------
__device__ __forceinline__ uint32_t sptr(const void* p) {
    uint32_t r;
    asm("{ .reg .u64 t; cvta.to.shared.u64 t, %1; cvt.u32.u64 %0, t; }" : "=r"(r) : "l"(p));
    return r;
}
__device__ __forceinline__ void ldsm_x4(uint32_t& a0, uint32_t& a1, uint32_t& a2, uint32_t& a3, uint32_t addr) {
    asm volatile("ldmatrix.sync.aligned.m8n8.x4.shared.b16 {%0,%1,%2,%3}, [%4];"
                 : "=r"(a0), "=r"(a1), "=r"(a2), "=r"(a3) : "r"(addr));
}
__device__ __forceinline__ void ldsm_x2(uint32_t& b0, uint32_t& b1, uint32_t addr) {
    asm volatile("ldmatrix.sync.aligned.m8n8.x2.shared.b16 {%0,%1}, [%2];"
                 : "=r"(b0), "=r"(b1) : "r"(addr));
}
__device__ __forceinline__ void mma_bf16(float& c0, float& c1, float& c2, float& c3,
                                         uint32_t a0, uint32_t a1, uint32_t a2, uint32_t a3,
                                         uint32_t b0, uint32_t b1) {
    asm volatile("mma.sync.aligned.m16n8k16.row.col.f32.bf16.bf16.f32 "
                 "{%0,%1,%2,%3}, {%4,%5,%6,%7}, {%8,%9}, {%0,%1,%2,%3};"
                 : "+f"(c0), "+f"(c1), "+f"(c2), "+f"(c3)
                 : "r"(a0), "r"(a1), "r"(a2), "r"(a3), "r"(b0), "r"(b1));
}
// pack {lo, hi} floats -> bf16x2 (lo in low half)
__device__ __forceinline__ uint32_t pack_bf16x2(float lo, float hi) {
    uint32_t p;
    asm("cvt.rn.bf16x2.f32 %0, %1, %2;" : "=r"(p) : "f"(hi), "f"(lo));
    return p;
}

// ---------------- generic GEMM: C = act(A[M,K] @ B[K,N] + bias) ----------
template <bool RELU>
__global__ void gemm_bias_kernel(const float* __restrict__ A,
                                 const float* __restrict__ B,
                                 const float* __restrict__ bias,
                                 float* __restrict__ C,
                                 int M, int N, int K) {
    __shared__ float As[16][68];
    __shared__ float Bs[16][68];
    int t  = threadIdx.x;
    int tx = t % 16;
    int ty = t / 16;
    int m0 = blockIdx.y * 64;
    int n0 = blockIdx.x * 64;

    float acc[4][4] = {};
    for (int k0 = 0; k0 < K; k0 += 16) {
        {
            int m  = t / 4;
            int k4 = (t % 4) * 4;
            float4 av = *(const float4*)(A + (size_t)(m0 + m) * K + k0 + k4);
            As[k4 + 0][m] = av.x; As[k4 + 1][m] = av.y;
            As[k4 + 2][m] = av.z; As[k4 + 3][m] = av.w;
        }
        {
            int k  = t / 16;
            int n4 = (t % 16) * 4;
            *(float4*)&Bs[k][n4] = *(const float4*)(B + (size_t)(k0 + k) * N + n0 + n4);
        }
        __syncthreads();
#pragma unroll
        for (int k = 0; k < 16; k++) {
            float4 av = *(const float4*)&As[k][ty * 4];
            float4 bv = *(const float4*)&Bs[k][tx * 4];
            acc[0][0] += av.x * bv.x; acc[0][1] += av.x * bv.y; acc[0][2] += av.x * bv.z; acc[0][3] += av.x * bv.w;
            acc[1][0] += av.y * bv.x; acc[1][1] += av.y * bv.y; acc[1][2] += av.y * bv.z; acc[1][3] += av.y * bv.w;
            acc[2][0] += av.z * bv.x; acc[2][1] += av.z * bv.y; acc[2][2] += av.z * bv.z; acc[2][3] += av.z * bv.w;
            acc[3][0] += av.w * bv.x; acc[3][1] += av.w * bv.y; acc[3][2] += av.w * bv.z; acc[3][3] += av.w * bv.w;
        }
        __syncthreads();
    }
    float4 bb = *(const float4*)(bias + n0 + tx * 4);
#pragma unroll
    for (int mi = 0; mi < 4; mi++) {
        float4 o;
        o.x = acc[mi][0] + bb.x; o.y = acc[mi][1] + bb.y;
        o.z = acc[mi][2] + bb.z; o.w = acc[mi][3] + bb.w;
        if (RELU) {
            o.x = fmaxf(o.x, 0.f); o.y = fmaxf(o.y, 0.f);
            o.z = fmaxf(o.z, 0.f); o.w = fmaxf(o.w, 0.f);
        }
        *(float4*)(C + (size_t)(m0 + ty * 4 + mi) * N + n0 + tx * 4) = o;
    }
}

// ---------------- K2: scores1[i][h][j] = q[i,h,:] . k[j,h,:] -------------
__global__ void qk_kernel(const float* __restrict__ q, const float* __restrict__ kk) {
    __shared__ float Qs[64][68];
    __shared__ float Ks[64][68];
    int h  = blockIdx.z;
    int i0 = blockIdx.y * 64;
    int j0 = blockIdx.x * 64;
    int t  = threadIdx.x;
    int tx = t % 16, ty = t / 16;

#pragma unroll
    for (int r = 0; r < 4; r++) {
        int fidx = r * 256 + t;
        int row  = fidx / 16;
        int e4   = (fidx % 16) * 4;
        float4 qv = *(const float4*)(q  + (size_t)(i0 + row) * DM + h * DK + e4);
        Qs[e4 + 0][row] = qv.x; Qs[e4 + 1][row] = qv.y; Qs[e4 + 2][row] = qv.z; Qs[e4 + 3][row] = qv.w;
        float4 kv = *(const float4*)(kk + (size_t)(j0 + row) * DM + h * DK + e4);
        Ks[e4 + 0][row] = kv.x; Ks[e4 + 1][row] = kv.y; Ks[e4 + 2][row] = kv.z; Ks[e4 + 3][row] = kv.w;
    }
    __syncthreads();

    float acc[4][4] = {};
#pragma unroll 8
    for (int e = 0; e < 64; e++) {
        float4 qv = *(const float4*)&Qs[e][ty * 4];
        float4 kv = *(const float4*)&Ks[e][tx * 4];
        acc[0][0] += qv.x * kv.x; acc[0][1] += qv.x * kv.y; acc[0][2] += qv.x * kv.z; acc[0][3] += qv.x * kv.w;
        acc[1][0] += qv.y * kv.x; acc[1][1] += qv.y * kv.y; acc[1][2] += qv.y * kv.z; acc[1][3] += qv.y * kv.w;
        acc[2][0] += qv.z * kv.x; acc[2][1] += qv.z * kv.y; acc[2][2] += qv.z * kv.z; acc[2][3] += qv.z * kv.w;
        acc[3][0] += qv.w * kv.x; acc[3][1] += qv.w * kv.y; acc[3][2] += qv.w * kv.z; acc[3][3] += qv.w * kv.w;
    }
#pragma unroll
    for (int mi = 0; mi < 4; mi++) {
        float4 o = make_float4(acc[mi][0], acc[mi][1], acc[mi][2], acc[mi][3]);
        *(float4*)(g_scores + (size_t)(i0 + ty * 4 + mi) * NH + h * N_TOK + j0 + tx * 4) = o;
    }
}

// ---------------- K3: structure-key scores via bf16 tensor-core mma ------
// per CTA: one i. scores[i][h][j] = (qk + q[i,h,:].relu(S[i,j,:]@Wsk+bsk)) * SCALE
// mma1: sk[16j x 64e] = S_tile @ Wsk  (A: S bf16, B: Wsk^T layout, fp32 acc, bias+relu)
// mma2: sc[16j x 8h]  = sk @ q^T      (A: repacked C frags, B: q bf16)
__global__ __launch_bounds__(256, 2) void sscore_kernel(
        const float* __restrict__ S,
        const float* __restrict__ q,
        const float* __restrict__ Wsk,
        const float* __restrict__ bsk) {
    // padded row stride 72 halfs = 144B -> conflict-free ldmatrix
    __shared__ __align__(16) uint16_t S_sh[128 * 72];   // [j][c] bf16
    __shared__ __align__(16) uint16_t W_sh[64 * 72];    // [e][c] bf16 (transposed Wsk)
    __shared__ __align__(16) uint16_t q_sh[8 * 72];     // [h][e] bf16
    __shared__ float bsk_sh[64];
    __shared__ __align__(16) float sc_sh[8 * 132];      // [h][j-tile(128)], pad 132

    const int i    = blockIdx.x;
    const int t    = threadIdx.x;
    const int lane = t & 31;
    const int w    = t >> 5;   // warp 0..7, handles j rows [w*16, w*16+16)

    // ---- setup: Wsk^T -> W_sh, q -> q_sh, bsk -> bsk_sh ----
#pragma unroll
    for (int r = 0; r < 16; r++) {
        int f = r * 256 + t;           // 0..4095
        int c = f >> 6, e = f & 63;
        __nv_bfloat16 b = __float2bfloat16(Wsk[f]);
        W_sh[e * 72 + c] = *(uint16_t*)&b;
    }
    if (t < 128) {
        int h = t >> 4, e4 = (t & 15) * 4;
        float4 v = *(const float4*)(q + (size_t)i * DM + h * DK + e4);
        uint32_t lo = pack_bf16x2(v.x, v.y);
        uint32_t hi = pack_bf16x2(v.z, v.w);
        *(uint2*)&q_sh[h * 72 + e4] = make_uint2(lo, hi);
    }
    if (t < 64) bsk_sh[t] = bsk[t];
    __syncthreads();

    // per-thread ldmatrix byte offsets
    const uint32_t Sbase = sptr(S_sh);
    const uint32_t Wbase = sptr(W_sh);
    const uint32_t qbase = sptr(q_sh);
    // A (x4): lanes 0-7 rows j0-7 @c, 8-15 rows j8-15 @c, 16-23 rows j0-7 @c+8, 24-31 j8-15 @c+8
    const uint32_t offA = ((w * 16 + (lane & 15)) * 72 + ((lane >> 4) << 3)) * 2;
    // B (x2): lanes 0-7 rows r0-7 @c, 8-15 rows r0-7 @c+8
    const uint32_t offB = ((lane & 7) * 72 + (((lane >> 3) & 1) << 3)) * 2;

    // prefetch q B-fragments (4 k-steps over e)
    uint32_t qb[4][2];
#pragma unroll
    for (int ek = 0; ek < 4; ek++)
        ldsm_x2(qb[ek][0], qb[ek][1], qbase + offB + ek * 32);

    // bias values for this thread's C columns (per e-tile)
    const int ecol = 2 * (lane & 3);

    const float* Srow = S + (size_t)i * N_TOK * 64;
    float* gsc = g_scores + (size_t)i * NH;

    for (int j0 = 0; j0 < N_TOK; j0 += 128) {
        __syncthreads();   // protect S_sh / sc_sh from previous iteration
        // load + convert S tile [128j x 64c] -> bf16 smem
#pragma unroll
        for (int r = 0; r < 8; r++) {
            int f  = r * 256 + t;          // float4 index 0..2047
            int jj = f >> 4;
            int c4 = (f & 15) * 4;
            float4 v = *(const float4*)(Srow + (size_t)(j0 + jj) * 64 + c4);
            uint32_t lo = pack_bf16x2(v.x, v.y);
            uint32_t hi = pack_bf16x2(v.z, v.w);
            *(uint2*)&S_sh[jj * 72 + c4] = make_uint2(lo, hi);
        }
        __syncthreads();

        // ---- mma1 + relu/pack + mma2, per warp (16 j rows) ----
        uint32_t sa[4][4];
#pragma unroll
        for (int ck = 0; ck < 4; ck++)
            ldsm_x4(sa[ck][0], sa[ck][1], sa[ck][2], sa[ck][3], Sbase + offA + ck * 32);

        uint32_t skl[8], skh[8];   // packed bf16 sk fragments per e-tile
#pragma unroll
        for (int et = 0; et < 8; et++) {
            float c0 = 0.f, c1 = 0.f, c2 = 0.f, c3 = 0.f;
#pragma unroll
            for (int ck = 0; ck < 4; ck++) {
                uint32_t b0, b1;
                ldsm_x2(b0, b1, Wbase + offB + et * (8 * 72 * 2) + ck * 32);
                mma_bf16(c0, c1, c2, c3, sa[ck][0], sa[ck][1], sa[ck][2], sa[ck][3], b0, b1);
            }
            float blo = bsk_sh[et * 8 + ecol];
            float bhi = bsk_sh[et * 8 + ecol + 1];
            c0 = fmaxf(c0 + blo, 0.f); c1 = fmaxf(c1 + bhi, 0.f);
            c2 = fmaxf(c2 + blo, 0.f); c3 = fmaxf(c3 + bhi, 0.f);
            skl[et] = pack_bf16x2(c0, c1);   // rows j..j, cols (e,e+1)
            skh[et] = pack_bf16x2(c2, c3);   // rows j+8
        }

        float s0 = 0.f, s1 = 0.f, s2 = 0.f, s3 = 0.f;
#pragma unroll
        for (int ek = 0; ek < 4; ek++)
            mma_bf16(s0, s1, s2, s3,
                     skl[2 * ek], skh[2 * ek], skl[2 * ek + 1], skh[2 * ek + 1],
                     qb[ek][0], qb[ek][1]);

        // stage scores C frags: sc_sh[h][j-in-tile]
        {
            int jw = w * 16 + (lane >> 2);
            int h0 = 2 * (lane & 3);
            sc_sh[h0 * 132 + jw]           = s0;
            sc_sh[(h0 + 1) * 132 + jw]     = s1;
            sc_sh[h0 * 132 + jw + 8]       = s2;
            sc_sh[(h0 + 1) * 132 + jw + 8] = s3;
        }
        __syncthreads();

        // coalesced RMW: scores = (qk + s) * SCALE
        {
            int h  = t >> 5;            // 0..7
            int j4 = (t & 31) * 4;      // 0..124
            float4 g = *(float4*)(gsc + (size_t)h * N_TOK + j0 + j4);
            float4 s = *(const float4*)&sc_sh[h * 132 + j4];
            g.x = (g.x + s.x) * SCALE; g.y = (g.y + s.y) * SCALE;
            g.z = (g.z + s.z) * SCALE; g.w = (g.w + s.w) * SCALE;
            *(float4*)(gsc + (size_t)h * N_TOK + j0 + j4) = g;
        }
    }
}

// ---------------- K4: row softmax in place -------------------------------
__global__ void softmax_kernel() {
    int row = blockIdx.x;            // i*8 + h
    float* p = g_scores + (size_t)row * N_TOK;
    int t = threadIdx.x;
    int lane = t & 31, warp = t >> 5;
    __shared__ float red[32];

    float4 v = *(float4*)(p + t * 4);
    float m = fmaxf(fmaxf(v.x, v.y), fmaxf(v.z, v.w));
#pragma unroll
    for (int o = 16; o; o >>= 1) m = fmaxf(m, __shfl_xor_sync(0xffffffffu, m, o));
    if (lane == 0) red[warp] = m;
    __syncthreads();
    if (t < 32) {
        float mm = (t < 8) ? red[t] : -1e30f;
#pragma unroll
        for (int o = 4; o; o >>= 1) mm = fmaxf(mm, __shfl_xor_sync(0xffffffffu, mm, o));
        if (t == 0) red[0] = mm;
    }
    __syncthreads();
    float bm = red[0];
    __syncthreads();

    v.x = __expf(v.x - bm); v.y = __expf(v.y - bm);
    v.z = __expf(v.z - bm); v.w = __expf(v.w - bm);
    float s = v.x + v.y + v.z + v.w;
#pragma unroll
    for (int o = 16; o; o >>= 1) s += __shfl_xor_sync(0xffffffffu, s, o);
    if (lane == 0) red[warp] = s;
    __syncthreads();
    if (t < 32) {
        float ss = (t < 8) ? red[t] : 0.f;
#pragma unroll
        for (int o = 4; o; o >>= 1) ss += __shfl_xor_sync(0xffffffffu, ss, o);
        if (t == 0) red[0] = ss;
    }
    __syncthreads();
    float inv = 1.0f / red[0];
    v.x *= inv; v.y *= inv; v.z *= inv; v.w *= inv;
    *(float4*)(p + t * 4) = v;
}

// ---------------- K5a: acc_v[i,h,d] = sum_j p[i,h,j] * v[j,h,d] ----------
__global__ void accv_kernel(const float* __restrict__ v) {
    __shared__ float Ps[32][68];
    __shared__ float Vs[32][68];
    int i0 = blockIdx.x * 64;
    int h  = blockIdx.y;
    int t  = threadIdx.x;
    int tx = t % 16, ty = t / 16;

    float acc[4][4] = {};
    for (int j0 = 0; j0 < N_TOK; j0 += 32) {
#pragma unroll
        for (int r = 0; r < 2; r++) {
            int f  = r * 256 + t;
            int ii = f / 8;
            int j4 = (f % 8) * 4;
            float4 pv = *(const float4*)(g_scores + (size_t)(i0 + ii) * NH + h * N_TOK + j0 + j4);
            Ps[j4 + 0][ii] = pv.x; Ps[j4 + 1][ii] = pv.y; Ps[j4 + 2][ii] = pv.z; Ps[j4 + 3][ii] = pv.w;
        }
#pragma unroll
        for (int r = 0; r < 2; r++) {
            int f  = r * 256 + t;
            int j  = f / 16;
            int d4 = (f % 16) * 4;
            *(float4*)&Vs[j][d4] = *(const float4*)(v + (size_t)(j0 + j) * DM + h * DK + d4);
        }
        __syncthreads();
#pragma unroll 8
        for (int j = 0; j < 32; j++) {
            float4 pv = *(const float4*)&Ps[j][ty * 4];
            float4 vv = *(const float4*)&Vs[j][tx * 4];
            acc[0][0] += pv.x * vv.x; acc[0][1] += pv.x * vv.y; acc[0][2] += pv.x * vv.z; acc[0][3] += pv.x * vv.w;
            acc[1][0] += pv.y * vv.x; acc[1][1] += pv.y * vv.y; acc[1][2] += pv.y * vv.z; acc[1][3] += pv.y * vv.w;
            acc[2][0] += pv.z * vv.x; acc[2][1] += pv.z * vv.y; acc[2][2] += pv.z * vv.z; acc[2][3] += pv.z * vv.w;
            acc[3][0] += pv.w * vv.x; acc[3][1] += pv.w * vv.y; acc[3][2] += pv.w * vv.z; acc[3][3] += pv.w * vv.w;
        }
        __syncthreads();
    }
#pragma unroll
    for (int mi = 0; mi < 4; mi++) {
        float4 o = make_float4(acc[mi][0], acc[mi][1], acc[mi][2], acc[mi][3]);
        *(float4*)(g_accv + (size_t)(i0 + ty * 4 + mi) * DM + h * DK + tx * 4) = o;
    }
}

// ---------------- K5b: acc_t[i,h,e] = sum_j p[i,h,j] * S[i,j,e] ----------
__global__ void acct_kernel(const float* __restrict__ S) {
    __shared__ float Ssh[64 * 68];
    __shared__ float psh[8 * 64];
    __shared__ float red[8 * 64];
    int i = blockIdx.x;
    int t = threadIdx.x;
    const int e4 = (t % 16) * 4;
    const int h  = (t / 16) % 8;
    const int jh = t / 128;

    float4 acc = make_float4(0.f, 0.f, 0.f, 0.f);
    for (int j0 = 0; j0 < N_TOK; j0 += 64) {
        __syncthreads();
#pragma unroll
        for (int r = 0; r < 4; r++) {
            int f  = r * 256 + t;
            int j  = f / 16;
            int c4 = (f % 16) * 4;
            *(float4*)&Ssh[j * 68 + c4] =
                *(const float4*)(S + ((size_t)i * N_TOK + j0 + j) * 64 + c4);
        }
        if (t < 128) {
            int hh = t / 16;
            int j4 = (t % 16) * 4;
            *(float4*)&psh[hh * 64 + j4] =
                *(const float4*)(g_scores + (size_t)i * NH + hh * N_TOK + j0 + j4);
        }
        __syncthreads();
        int jb = jh * 32;
#pragma unroll 8
        for (int j = jb; j < jb + 32; j++) {
            float4 s = *(const float4*)&Ssh[j * 68 + e4];
            float  pp = psh[h * 64 + j];
            acc.x += pp * s.x; acc.y += pp * s.y; acc.z += pp * s.z; acc.w += pp * s.w;
        }
    }
    __syncthreads();
    if (jh == 1) *(float4*)&red[h * 64 + e4] = acc;
    __syncthreads();
    if (jh == 0) {
        float4 o = *(const float4*)&red[h * 64 + e4];
        o.x += acc.x; o.y += acc.y; o.z += acc.z; o.w += acc.w;
        *(float4*)(g_acct + (size_t)i * DM + h * DK + e4) = o;
    }
}

// ---------------- K6: out_pre = acc_v + acc_t @ Wsv + bsv ----------------
__global__ void combine_kernel(const float* __restrict__ Wsv, const float* __restrict__ bsv) {
    __shared__ float Wsh[64 * 64];
    __shared__ float tsh[8 * 64];
    int i = blockIdx.x;
    int t = threadIdx.x;
#pragma unroll
    for (int r = 0; r < 4; r++) {
        int f = r * 256 + t;
        *(float4*)&Wsh[f * 4] = *(const float4*)(Wsv + f * 4);
    }
    if (t < 128) *(float4*)&tsh[t * 4] = *(const float4*)(g_acct + (size_t)i * DM + t * 4);
    __syncthreads();
    int d  = t % 64;
    int h0 = t / 64;
    float bd = bsv[d];
#pragma unroll
    for (int r = 0; r < 2; r++) {
        int h = h0 + r * 4;
        float a = 0.f;
#pragma unroll 16
        for (int e = 0; e < 64; e++) a += tsh[h * 64 + e] * Wsh[e * 64 + d];
        g_outpre[(size_t)i * DM + h * DK + d] =
            g_accv[(size_t)i * DM + h * DK + d] + a + bd;
    }
}

// ---------------- launch ----------------
extern "C" void kernel_launch(void* const* d_in, const int* in_sizes, int n_in,
                              void* d_out, int out_size) {
    const float* x   = (const float*)d_in[0];
    const float* S   = (const float*)d_in[1];
    const float* Wq  = (const float*)d_in[2];  const float* bq  = (const float*)d_in[3];
    const float* Wk  = (const float*)d_in[4];  const float* bk  = (const float*)d_in[5];
    const float* Wv  = (const float*)d_in[6];  const float* bv  = (const float*)d_in[7];
    const float* Wo  = (const float*)d_in[8];  const float* bo  = (const float*)d_in[9];
    const float* Wsk = (const float*)d_in[10]; const float* bsk = (const float*)d_in[11];
    const float* Wsv = (const float*)d_in[12]; const float* bsv = (const float*)d_in[13];
    float* out = (float*)d_out;

    void *pq, *pk, *pv, *pop;
    cudaGetSymbolAddress(&pq,  g_q);
    cudaGetSymbolAddress(&pk,  g_k);
    cudaGetSymbolAddress(&pv,  g_v);
    cudaGetSymbolAddress(&pop, g_outpre);

    dim3 gemm_grid(DM / 64, N_TOK / 64);
    gemm_bias_kernel<true ><<<gemm_grid, 256>>>(x, Wq, bq, (float*)pq, N_TOK, DM, DM);
    gemm_bias_kernel<true ><<<gemm_grid, 256>>>(x, Wk, bk, (float*)pk, N_TOK, DM, DM);
    gemm_bias_kernel<false><<<gemm_grid, 256>>>(x, Wv, bv, (float*)pv, N_TOK, DM, DM);

    qk_kernel<<<dim3(16, 16, 8), 256>>>((const float*)pq, (const float*)pk);

    sscore_kernel<<<N_TOK, 256>>>(S, (const float*)pq, Wsk, bsk);

    softmax_kernel<<<NH, 256>>>();

    accv_kernel<<<dim3(16, 8), 256>>>((const float*)pv);
    acct_kernel<<<N_TOK, 256>>>(S);

    combine_kernel<<<N_TOK, 256>>>(Wsv, bsv);

    gemm_bias_kernel<false><<<gemm_grid, 256>>>((const float*)pop, Wo, bo, out, N_TOK, DM, DM);
}

// round 11
// speedup vs baseline: 2.1790x; 1.2773x over previous
#include <cuda_runtime.h>
#include <cuda_bf16.h>
#include <math.h>
#include <stdint.h>

#define N_TOK 1024
#define DM    512
#define H     8
#define DK    64
#define NH    8192          // N_TOK * H
#define SCALE 0.125f        // 1/sqrt(64)

// ---------------- scratch (device globals; no allocation) ----------------
__device__ __nv_bfloat16 g_xb[N_TOK * DM];            // x in bf16
__device__ __nv_bfloat16 g_wt[DM * DM];               // transposed weight scratch [n][k]
__device__ __nv_bfloat16 g_qb[N_TOK * DM];            // relu(q) bf16 (logit path only)
__device__ __nv_bfloat16 g_kb[N_TOK * DM];            // relu(k) bf16 (logit path only)
__device__ float g_v[N_TOK * DM];                     // v fp32 (output path, exact)
__device__ float g_scores[(size_t)N_TOK * H * N_TOK]; // qk scores -> then p (fp32, in place)
__device__ float g_accv[N_TOK * DM];
__device__ float g_acct[N_TOK * DM];
__device__ float g_outpre[N_TOK * DM];

// ---------------- asm helpers ----------------
__device__ __forceinline__ uint32_t sptr(const void* p) {
    uint32_t r;
    asm("{ .reg .u64 t; cvta.to.shared.u64 t, %1; cvt.u32.u64 %0, t; }" : "=r"(r) : "l"(p));
    return r;
}
__device__ __forceinline__ void ldsm_x4(uint32_t& a0, uint32_t& a1, uint32_t& a2, uint32_t& a3, uint32_t addr) {
    asm volatile("ldmatrix.sync.aligned.m8n8.x4.shared.b16 {%0,%1,%2,%3}, [%4];"
                 : "=r"(a0), "=r"(a1), "=r"(a2), "=r"(a3) : "r"(addr));
}
__device__ __forceinline__ void ldsm_x2(uint32_t& b0, uint32_t& b1, uint32_t addr) {
    asm volatile("ldmatrix.sync.aligned.m8n8.x2.shared.b16 {%0,%1}, [%2];"
                 : "=r"(b0), "=r"(b1) : "r"(addr));
}
__device__ __forceinline__ void mma_bf16(float& c0, float& c1, float& c2, float& c3,
                                         uint32_t a0, uint32_t a1, uint32_t a2, uint32_t a3,
                                         uint32_t b0, uint32_t b1) {
    asm volatile("mma.sync.aligned.m16n8k16.row.col.f32.bf16.bf16.f32 "
                 "{%0,%1,%2,%3}, {%4,%5,%6,%7}, {%8,%9}, {%0,%1,%2,%3};"
                 : "+f"(c0), "+f"(c1), "+f"(c2), "+f"(c3)
                 : "r"(a0), "r"(a1), "r"(a2), "r"(a3), "r"(b0), "r"(b1));
}
__device__ __forceinline__ uint32_t pack_bf16x2(float lo, float hi) {
    uint32_t p;
    asm("cvt.rn.bf16x2.f32 %0, %1, %2;" : "=r"(p) : "f"(hi), "f"(lo));
    return p;
}

// ---------------- K0a: x -> bf16 ----------------
__global__ void xconv_kernel(const float* __restrict__ x, __nv_bfloat16* __restrict__ xb) {
    int idx = (blockIdx.x * 256 + threadIdx.x) * 4;
    float4 v = *(const float4*)(x + idx);
    uint32_t lo = pack_bf16x2(v.x, v.y);
    uint32_t hi = pack_bf16x2(v.z, v.w);
    *(uint2*)(xb + idx) = make_uint2(lo, hi);
}

// ---------------- K0b: W [K][N] fp32 -> Wt [N][K] bf16 ----------------
__global__ void wtrans_kernel(const float* __restrict__ W, __nv_bfloat16* __restrict__ Wt) {
    __shared__ float tile[32][33];
    int k0 = blockIdx.y * 32, n0 = blockIdx.x * 32;
    int x = threadIdx.x & 31, y = threadIdx.x >> 5;   // y 0..7
#pragma unroll
    for (int r = 0; r < 4; r++)
        tile[y * 4 + r][x] = W[(size_t)(k0 + y * 4 + r) * DM + n0 + x];
    __syncthreads();
#pragma unroll
    for (int r = 0; r < 4; r++)
        Wt[(size_t)(n0 + y * 4 + r) * DM + k0 + x] = __float2bfloat16(tile[x][y * 4 + r]);
}

// ---------------- K1: projection GEMM bf16 mma (logit path: q, k) --------
// X [M, K=DM] bf16 row-major, Wt [N=DM, K] bf16, C [M, N] bf16, relu
__global__ __launch_bounds__(256) void proj_gemm_bf16(
        const __nv_bfloat16* __restrict__ X,
        const __nv_bfloat16* __restrict__ Wt,
        const float* __restrict__ bias,
        __nv_bfloat16* __restrict__ C) {
    __shared__ __align__(16) uint16_t Xs[64 * 72];
    __shared__ __align__(16) uint16_t Ws[64 * 72];
    int t = threadIdx.x, lane = t & 31, w = t >> 5;
    int m0 = blockIdx.y * 64, n0 = blockIdx.x * 64;
    int mblk = (w & 3) * 16, nhalf = (w >> 2) * 32;
    uint32_t Xb = sptr(Xs), Wb = sptr(Ws);
    float c[4][4] = {};

    for (int k0 = 0; k0 < DM; k0 += 64) {
        __syncthreads();
#pragma unroll
        for (int r = 0; r < 2; r++) {
            int f = r * 256 + t;
            int row = f >> 3, c8 = (f & 7) * 8;
            *(uint4*)&Xs[row * 72 + c8] = *(const uint4*)(X  + (size_t)(m0 + row) * DM + k0 + c8);
            *(uint4*)&Ws[row * 72 + c8] = *(const uint4*)(Wt + (size_t)(n0 + row) * DM + k0 + c8);
        }
        __syncthreads();
#pragma unroll
        for (int ks = 0; ks < 4; ks++) {
            uint32_t a0, a1, a2, a3;
            ldsm_x4(a0, a1, a2, a3, Xb + ((mblk + (lane & 15)) * 72 + ks * 16 + ((lane >> 4) << 3)) * 2);
#pragma unroll
            for (int nb = 0; nb < 2; nb++) {
                uint32_t b0, b1, b2, b3;
                int row = nhalf + nb * 16 + ((lane & 7) | ((lane >> 1) & 8));
                int col = ks * 16 + ((lane & 8) ? 8 : 0);
                ldsm_x4(b0, b1, b2, b3, Wb + (row * 72 + col) * 2);
                mma_bf16(c[nb*2][0], c[nb*2][1], c[nb*2][2], c[nb*2][3], a0, a1, a2, a3, b0, b1);
                mma_bf16(c[nb*2+1][0], c[nb*2+1][1], c[nb*2+1][2], c[nb*2+1][3], a0, a1, a2, a3, b2, b3);
            }
        }
    }
    int r = lane >> 2, cc = 2 * (lane & 3);
#pragma unroll
    for (int nb = 0; nb < 4; nb++) {
        int n = n0 + nhalf + nb * 8 + cc;
        float b0 = bias[n], b1 = bias[n + 1];
        float v0 = fmaxf(c[nb][0] + b0, 0.f), v1 = fmaxf(c[nb][1] + b1, 0.f);
        float v2 = fmaxf(c[nb][2] + b0, 0.f), v3 = fmaxf(c[nb][3] + b1, 0.f);
        *(uint32_t*)(C + (size_t)(m0 + mblk + r) * DM + n)     = pack_bf16x2(v0, v1);
        *(uint32_t*)(C + (size_t)(m0 + mblk + r + 8) * DM + n) = pack_bf16x2(v2, v3);
    }
}

// ---------------- K2: qk scores via bf16 mma ----------------
__global__ __launch_bounds__(256) void qk_mma_kernel(
        const __nv_bfloat16* __restrict__ Q, const __nv_bfloat16* __restrict__ K) {
    __shared__ __align__(16) uint16_t Qs[64 * 72];   // [i][e]
    __shared__ __align__(16) uint16_t Ks[64 * 72];   // [j][e]
    int h = blockIdx.z, i0 = blockIdx.y * 64, j0 = blockIdx.x * 64;
    int t = threadIdx.x, lane = t & 31, w = t >> 5;
    int iblk = (w & 3) * 16, jhalf = (w >> 2) * 32;
    uint32_t Qb = sptr(Qs), Kb = sptr(Ks);

#pragma unroll
    for (int r = 0; r < 2; r++) {
        int f = r * 256 + t;
        int row = f >> 3, c8 = (f & 7) * 8;
        *(uint4*)&Qs[row * 72 + c8] = *(const uint4*)(Q + (size_t)(i0 + row) * DM + h * DK + c8);
        *(uint4*)&Ks[row * 72 + c8] = *(const uint4*)(K + (size_t)(j0 + row) * DM + h * DK + c8);
    }
    __syncthreads();

    float c[4][4] = {};
#pragma unroll
    for (int ks = 0; ks < 4; ks++) {
        uint32_t a0, a1, a2, a3;
        ldsm_x4(a0, a1, a2, a3, Qb + ((iblk + (lane & 15)) * 72 + ks * 16 + ((lane >> 4) << 3)) * 2);
#pragma unroll
        for (int nb = 0; nb < 2; nb++) {
            uint32_t b0, b1, b2, b3;
            int row = jhalf + nb * 16 + ((lane & 7) | ((lane >> 1) & 8));
            int col = ks * 16 + ((lane & 8) ? 8 : 0);
            ldsm_x4(b0, b1, b2, b3, Kb + (row * 72 + col) * 2);
            mma_bf16(c[nb*2][0], c[nb*2][1], c[nb*2][2], c[nb*2][3], a0, a1, a2, a3, b0, b1);
            mma_bf16(c[nb*2+1][0], c[nb*2+1][1], c[nb*2+1][2], c[nb*2+1][3], a0, a1, a2, a3, b2, b3);
        }
    }
    int r = lane >> 2, cc = 2 * (lane & 3);
#pragma unroll
    for (int nb = 0; nb < 4; nb++) {
        int j = j0 + jhalf + nb * 8 + cc;
        *(float2*)(g_scores + (size_t)(i0 + iblk + r) * NH + h * N_TOK + j)     = make_float2(c[nb][0], c[nb][1]);
        *(float2*)(g_scores + (size_t)(i0 + iblk + r + 8) * NH + h * N_TOK + j) = make_float2(c[nb][2], c[nb][3]);
    }
}

// ---------------- K3: fused structure-scores + softmax -> p fp32 ---------
// p written back IN PLACE into g_scores.
#define SS_SMEM 61824
__global__ __launch_bounds__(256, 2) void sscore_kernel(
        const float* __restrict__ S,
        const __nv_bfloat16* __restrict__ qb,
        const float* __restrict__ Wsk,
        const float* __restrict__ bsk) {
    extern __shared__ __align__(16) char dyn[];
    uint16_t* S_sh  = (uint16_t*)dyn;              // [128 j][72 c]
    uint16_t* W_sh  = (uint16_t*)(dyn + 18432);    // [64 e][72 c]
    uint16_t* q_sh  = (uint16_t*)(dyn + 27648);    // [8 h][72 e]
    float*    bsk_sh = (float*)(dyn + 28800);      // 64
    float*    p_sh  = (float*)(dyn + 29056);       // [8 h][1024 j]

    const int i    = blockIdx.x;
    const int t    = threadIdx.x;
    const int lane = t & 31;
    const int w    = t >> 5;

    // Wsk^T -> W_sh bf16
#pragma unroll
    for (int r = 0; r < 16; r++) {
        int f = r * 256 + t;
        int c = f >> 6, e = f & 63;
        __nv_bfloat16 b = __float2bfloat16(Wsk[f]);
        W_sh[e * 72 + c] = *(uint16_t*)&b;
    }
    if (t < 64) {
        int h = t >> 3, e8 = (t & 7) * 8;
        *(uint4*)&q_sh[h * 72 + e8] = *(const uint4*)(qb + (size_t)i * DM + h * DK + e8);
        bsk_sh[t] = bsk[t];
    }
    __syncthreads();

    const uint32_t Sbase = sptr(S_sh);
    const uint32_t Wbase = sptr(W_sh);
    const uint32_t qbase = sptr(q_sh);
    const uint32_t offA = ((w * 16 + (lane & 15)) * 72 + ((lane >> 4) << 3)) * 2;
    const uint32_t offB = ((lane & 7) * 72 + (((lane >> 3) & 1) << 3)) * 2;

    uint32_t qf[4][2];
#pragma unroll
    for (int ek = 0; ek < 4; ek++)
        ldsm_x2(qf[ek][0], qf[ek][1], qbase + offB + ek * 32);

    const int ecol = 2 * (lane & 3);
    const float* Srow = S + (size_t)i * N_TOK * 64;

    for (int j0 = 0; j0 < N_TOK; j0 += 128) {
        __syncthreads();
#pragma unroll
        for (int r = 0; r < 8; r++) {
            int f  = r * 256 + t;
            int jj = f >> 4;
            int c4 = (f & 15) * 4;
            float4 v = *(const float4*)(Srow + (size_t)(j0 + jj) * 64 + c4);
            uint32_t lo = pack_bf16x2(v.x, v.y);
            uint32_t hi = pack_bf16x2(v.z, v.w);
            *(uint2*)&S_sh[jj * 72 + c4] = make_uint2(lo, hi);
        }
        __syncthreads();

        uint32_t sa[4][4];
#pragma unroll
        for (int ck = 0; ck < 4; ck++)
            ldsm_x4(sa[ck][0], sa[ck][1], sa[ck][2], sa[ck][3], Sbase + offA + ck * 32);

        uint32_t skl[8], skh[8];
#pragma unroll
        for (int et = 0; et < 8; et++) {
            float c0 = 0.f, c1 = 0.f, c2 = 0.f, c3 = 0.f;
#pragma unroll
            for (int ck = 0; ck < 4; ck++) {
                uint32_t b0, b1;
                ldsm_x2(b0, b1, Wbase + offB + et * (8 * 72 * 2) + ck * 32);
                mma_bf16(c0, c1, c2, c3, sa[ck][0], sa[ck][1], sa[ck][2], sa[ck][3], b0, b1);
            }
            float blo = bsk_sh[et * 8 + ecol];
            float bhi = bsk_sh[et * 8 + ecol + 1];
            c0 = fmaxf(c0 + blo, 0.f); c1 = fmaxf(c1 + bhi, 0.f);
            c2 = fmaxf(c2 + blo, 0.f); c3 = fmaxf(c3 + bhi, 0.f);
            skl[et] = pack_bf16x2(c0, c1);
            skh[et] = pack_bf16x2(c2, c3);
        }

        float s0 = 0.f, s1 = 0.f, s2 = 0.f, s3 = 0.f;
#pragma unroll
        for (int ek = 0; ek < 4; ek++)
            mma_bf16(s0, s1, s2, s3,
                     skl[2*ek], skh[2*ek], skl[2*ek+1], skh[2*ek+1],
                     qf[ek][0], qf[ek][1]);

        int jw = j0 + w * 16 + (lane >> 2);
        int h0 = 2 * (lane & 3);
        p_sh[h0 * N_TOK + jw]           = s0;
        p_sh[(h0 + 1) * N_TOK + jw]     = s1;
        p_sh[h0 * N_TOK + jw + 8]       = s2;
        p_sh[(h0 + 1) * N_TOK + jw + 8] = s3;
    }
    __syncthreads();

    // softmax: warp w owns row h=w; p written back to g_scores (fp32)
    {
        float* row = p_sh + w * N_TOK;
        float* gsc = g_scores + (size_t)i * NH + w * N_TOK;
        float mx = -1e30f;
#pragma unroll
        for (int rr = 0; rr < 8; rr++) {
            int idx = rr * 128 + lane * 4;
            float4 g = *(const float4*)(gsc + idx);
            float4 p = *(float4*)(row + idx);
            p.x = (p.x + g.x) * SCALE; p.y = (p.y + g.y) * SCALE;
            p.z = (p.z + g.z) * SCALE; p.w = (p.w + g.w) * SCALE;
            *(float4*)(row + idx) = p;
            mx = fmaxf(mx, fmaxf(fmaxf(p.x, p.y), fmaxf(p.z, p.w)));
        }
#pragma unroll
        for (int o = 16; o; o >>= 1) mx = fmaxf(mx, __shfl_xor_sync(0xffffffffu, mx, o));
        float sum = 0.f;
#pragma unroll
        for (int rr = 0; rr < 8; rr++) {
            int idx = rr * 128 + lane * 4;
            float4 p = *(float4*)(row + idx);
            p.x = __expf(p.x - mx); p.y = __expf(p.y - mx);
            p.z = __expf(p.z - mx); p.w = __expf(p.w - mx);
            *(float4*)(row + idx) = p;
            sum += p.x + p.y + p.z + p.w;
        }
#pragma unroll
        for (int o = 16; o; o >>= 1) sum += __shfl_xor_sync(0xffffffffu, sum, o);
        float inv = 1.0f / sum;
#pragma unroll
        for (int rr = 0; rr < 8; rr++) {
            int idx = rr * 128 + lane * 4;
            float4 p = *(float4*)(row + idx);
            p.x *= inv; p.y *= inv; p.z *= inv; p.w *= inv;
            *(float4*)(gsc + idx) = p;
        }
    }
}

// ---------------- K5a: acc_v[i,h,d] = sum_j p[i,h,j] * v[j,h,d] (fp32) ---
__global__ void accv_kernel(const float* __restrict__ v) {
    __shared__ float Ps[32][68];
    __shared__ float Vs[32][68];
    int i0 = blockIdx.x * 64;
    int h  = blockIdx.y;
    int t  = threadIdx.x;
    int tx = t % 16, ty = t / 16;

    float acc[4][4] = {};
    for (int j0 = 0; j0 < N_TOK; j0 += 32) {
#pragma unroll
        for (int r = 0; r < 2; r++) {
            int f  = r * 256 + t;
            int ii = f / 8;
            int j4 = (f % 8) * 4;
            float4 pv = *(const float4*)(g_scores + (size_t)(i0 + ii) * NH + h * N_TOK + j0 + j4);
            Ps[j4 + 0][ii] = pv.x; Ps[j4 + 1][ii] = pv.y; Ps[j4 + 2][ii] = pv.z; Ps[j4 + 3][ii] = pv.w;
        }
#pragma unroll
        for (int r = 0; r < 2; r++) {
            int f  = r * 256 + t;
            int j  = f / 16;
            int d4 = (f % 16) * 4;
            *(float4*)&Vs[j][d4] = *(const float4*)(v + (size_t)(j0 + j) * DM + h * DK + d4);
        }
        __syncthreads();
#pragma unroll 8
        for (int j = 0; j < 32; j++) {
            float4 pv = *(const float4*)&Ps[j][ty * 4];
            float4 vv = *(const float4*)&Vs[j][tx * 4];
            acc[0][0] += pv.x * vv.x; acc[0][1] += pv.x * vv.y; acc[0][2] += pv.x * vv.z; acc[0][3] += pv.x * vv.w;
            acc[1][0] += pv.y * vv.x; acc[1][1] += pv.y * vv.y; acc[1][2] += pv.y * vv.z; acc[1][3] += pv.y * vv.w;
            acc[2][0] += pv.z * vv.x; acc[2][1] += pv.z * vv.y; acc[2][2] += pv.z * vv.z; acc[2][3] += pv.z * vv.w;
            acc[3][0] += pv.w * vv.x; acc[3][1] += pv.w * vv.y; acc[3][2] += pv.w * vv.z; acc[3][3] += pv.w * vv.w;
        }
        __syncthreads();
    }
#pragma unroll
    for (int mi = 0; mi < 4; mi++) {
        float4 o = make_float4(acc[mi][0], acc[mi][1], acc[mi][2], acc[mi][3]);
        *(float4*)(g_accv + (size_t)(i0 + ty * 4 + mi) * DM + h * DK + tx * 4) = o;
    }
}

// ---------------- K5b: acc_t[i,h,e] = sum_j p[i,h,j] * S[i,j,e] ----------
__global__ void acct_kernel(const float* __restrict__ S) {
    __shared__ float Ssh[64 * 68];
    __shared__ float psh[8 * 64];
    __shared__ float red[8 * 64];
    int i = blockIdx.x;
    int t = threadIdx.x;
    const int e4 = (t % 16) * 4;
    const int h  = (t / 16) % 8;
    const int jh = t / 128;

    float4 acc = make_float4(0.f, 0.f, 0.f, 0.f);
    for (int j0 = 0; j0 < N_TOK; j0 += 64) {
        __syncthreads();
#pragma unroll
        for (int r = 0; r < 4; r++) {
            int f  = r * 256 + t;
            int j  = f / 16;
            int c4 = (f % 16) * 4;
            *(float4*)&Ssh[j * 68 + c4] =
                *(const float4*)(S + ((size_t)i * N_TOK + j0 + j) * 64 + c4);
        }
        if (t < 128) {
            int hh = t / 16;
            int j4 = (t % 16) * 4;
            *(float4*)&psh[hh * 64 + j4] =
                *(const float4*)(g_scores + (size_t)i * NH + hh * N_TOK + j0 + j4);
        }
        __syncthreads();
        int jb = jh * 32;
#pragma unroll 8
        for (int j = jb; j < jb + 32; j++) {
            float4 s = *(const float4*)&Ssh[j * 68 + e4];
            float  pp = psh[h * 64 + j];
            acc.x += pp * s.x; acc.y += pp * s.y; acc.z += pp * s.z; acc.w += pp * s.w;
        }
    }
    __syncthreads();
    if (jh == 1) *(float4*)&red[h * 64 + e4] = acc;
    __syncthreads();
    if (jh == 0) {
        float4 o = *(const float4*)&red[h * 64 + e4];
        o.x += acc.x; o.y += acc.y; o.z += acc.z; o.w += acc.w;
        *(float4*)(g_acct + (size_t)i * DM + h * DK + e4) = o;
    }
}

// ---------------- K6: out_pre = acc_v + acc_t @ Wsv + bsv ----------------
__global__ void combine_kernel(const float* __restrict__ Wsv, const float* __restrict__ bsv) {
    __shared__ float Wsh[64 * 64];
    __shared__ float tsh[8 * 64];
    int i = blockIdx.x;
    int t = threadIdx.x;
#pragma unroll
    for (int r = 0; r < 4; r++) {
        int f = r * 256 + t;
        *(float4*)&Wsh[f * 4] = *(const float4*)(Wsv + f * 4);
    }
    if (t < 128) *(float4*)&tsh[t * 4] = *(const float4*)(g_acct + (size_t)i * DM + t * 4);
    __syncthreads();
    int d  = t % 64;
    int h0 = t / 64;
    float bd = bsv[d];
#pragma unroll
    for (int r = 0; r < 2; r++) {
        int h = h0 + r * 4;
        float a = 0.f;
#pragma unroll 16
        for (int e = 0; e < 64; e++) a += tsh[h * 64 + e] * Wsh[e * 64 + d];
        g_outpre[(size_t)i * DM + h * DK + d] =
            g_accv[(size_t)i * DM + h * DK + d] + a + bd;
    }
}

// ---------------- fp32 GEMM (output path: v projection + final Wo) -------
__global__ void gemm_bias_f32_kernel(const float* __restrict__ A,
                                     const float* __restrict__ B,
                                     const float* __restrict__ bias,
                                     float* __restrict__ C,
                                     int M, int N, int K) {
    __shared__ float As[16][68];
    __shared__ float Bs[16][68];
    int t  = threadIdx.x;
    int tx = t % 16;
    int ty = t / 16;
    int m0 = blockIdx.y * 64;
    int n0 = blockIdx.x * 64;

    float acc[4][4] = {};
    for (int k0 = 0; k0 < K; k0 += 16) {
        {
            int m  = t / 4;
            int k4 = (t % 4) * 4;
            float4 av = *(const float4*)(A + (size_t)(m0 + m) * K + k0 + k4);
            As[k4 + 0][m] = av.x; As[k4 + 1][m] = av.y;
            As[k4 + 2][m] = av.z; As[k4 + 3][m] = av.w;
        }
        {
            int k  = t / 16;
            int n4 = (t % 16) * 4;
            *(float4*)&Bs[k][n4] = *(const float4*)(B + (size_t)(k0 + k) * N + n0 + n4);
        }
        __syncthreads();
#pragma unroll
        for (int k = 0; k < 16; k++) {
            float4 av = *(const float4*)&As[k][ty * 4];
            float4 bv = *(const float4*)&Bs[k][tx * 4];
            acc[0][0] += av.x * bv.x; acc[0][1] += av.x * bv.y; acc[0][2] += av.x * bv.z; acc[0][3] += av.x * bv.w;
            acc[1][0] += av.y * bv.x; acc[1][1] += av.y * bv.y; acc[1][2] += av.y * bv.z; acc[1][3] += av.y * bv.w;
            acc[2][0] += av.z * bv.x; acc[2][1] += av.z * bv.y; acc[2][2] += av.z * bv.z; acc[2][3] += av.z * bv.w;
            acc[3][0] += av.w * bv.x; acc[3][1] += av.w * bv.y; acc[3][2] += av.w * bv.z; acc[3][3] += av.w * bv.w;
        }
        __syncthreads();
    }
    float4 bb = *(const float4*)(bias + n0 + tx * 4);
#pragma unroll
    for (int mi = 0; mi < 4; mi++) {
        float4 o;
        o.x = acc[mi][0] + bb.x; o.y = acc[mi][1] + bb.y;
        o.z = acc[mi][2] + bb.z; o.w = acc[mi][3] + bb.w;
        *(float4*)(C + (size_t)(m0 + ty * 4 + mi) * N + n0 + tx * 4) = o;
    }
}

// ---------------- launch ----------------
extern "C" void kernel_launch(void* const* d_in, const int* in_sizes, int n_in,
                              void* d_out, int out_size) {
    const float* x   = (const float*)d_in[0];
    const float* S   = (const float*)d_in[1];
    const float* Wq  = (const float*)d_in[2];  const float* bq  = (const float*)d_in[3];
    const float* Wk  = (const float*)d_in[4];  const float* bk  = (const float*)d_in[5];
    const float* Wv  = (const float*)d_in[6];  const float* bv  = (const float*)d_in[7];
    const float* Wo  = (const float*)d_in[8];  const float* bo  = (const float*)d_in[9];
    const float* Wsk = (const float*)d_in[10]; const float* bsk = (const float*)d_in[11];
    const float* Wsv = (const float*)d_in[12]; const float* bsv = (const float*)d_in[13];
    float* out = (float*)d_out;

    void *pxb, *pwt, *pqb, *pkb, *pv, *pop;
    cudaGetSymbolAddress(&pxb, g_xb);
    cudaGetSymbolAddress(&pwt, g_wt);
    cudaGetSymbolAddress(&pqb, g_qb);
    cudaGetSymbolAddress(&pkb, g_kb);
    cudaGetSymbolAddress(&pv,  g_v);
    cudaGetSymbolAddress(&pop, g_outpre);
    __nv_bfloat16* xb = (__nv_bfloat16*)pxb;
    __nv_bfloat16* wt = (__nv_bfloat16*)pwt;

    cudaFuncSetAttribute(sscore_kernel, cudaFuncAttributeMaxDynamicSharedMemorySize, SS_SMEM);

    // x -> bf16 (logit path only)
    xconv_kernel<<<N_TOK * DM / 1024, 256>>>(x, xb);

    dim3 tg(16, 16);
    dim3 pg(DM / 64, N_TOK / 64);
    // q/k projections: bf16 mma (feed softmax only — bf16-safe)
    wtrans_kernel<<<tg, 256>>>(Wq, wt);
    proj_gemm_bf16<<<pg, 256>>>(xb, wt, bq, (__nv_bfloat16*)pqb);
    wtrans_kernel<<<tg, 256>>>(Wk, wt);
    proj_gemm_bf16<<<pg, 256>>>(xb, wt, bk, (__nv_bfloat16*)pkb);
    // v projection: exact fp32 (multiplied by p — output path)
    gemm_bias_f32_kernel<<<pg, 256>>>(x, Wv, bv, (float*)pv, N_TOK, DM, DM);

    // qk scores (bf16 mma, fp32 out)
    qk_mma_kernel<<<dim3(16, 16, 8), 256>>>((const __nv_bfloat16*)pqb, (const __nv_bfloat16*)pkb);

    // structure scores + softmax -> p fp32 (in place in g_scores)
    sscore_kernel<<<N_TOK, 256, SS_SMEM>>>(S, (const __nv_bfloat16*)pqb, Wsk, bsk);

    // value aggregation (fp32 output path)
    accv_kernel<<<dim3(16, 8), 256>>>((const float*)pv);
    acct_kernel<<<N_TOK, 256>>>(S);

    combine_kernel<<<N_TOK, 256>>>(Wsv, bsv);

    // final output projection in fp32
    gemm_bias_f32_kernel<<<dim3(DM / 64, N_TOK / 64), 256>>>((const float*)pop, Wo, bo, out, N_TOK, DM, DM);
}

// round 12
// speedup vs baseline: 2.4485x; 1.1237x over previous
#include <cuda_runtime.h>
#include <cuda_bf16.h>
#include <math.h>
#include <stdint.h>

#define N_TOK 1024
#define DM    512
#define H     8
#define DK    64
#define NH    8192          // N_TOK * H
#define SCALE 0.125f        // 1/sqrt(64)

// ---------------- scratch (device globals; no allocation) ----------------
__device__ __nv_bfloat16 g_xb[N_TOK * DM];            // x in bf16
__device__ __nv_bfloat16 g_wt[DM * DM];               // transposed weight scratch [n][k]
__device__ __nv_bfloat16 g_qb[N_TOK * DM];            // relu(q) bf16 (logit path only)
__device__ __nv_bfloat16 g_kb[N_TOK * DM];            // relu(k) bf16 (logit path only)
__device__ float g_v[N_TOK * DM];                     // v fp32 (output path, near-exact)
__device__ float g_scores[(size_t)N_TOK * H * N_TOK]; // qk scores -> then p (fp32, in place)
__device__ float g_accv[N_TOK * DM];
__device__ float g_acct[N_TOK * DM];
__device__ float g_outpre[N_TOK * DM];

// ---------------- asm helpers ----------------
__device__ __forceinline__ uint32_t sptr(const void* p) {
    uint32_t r;
    asm("{ .reg .u64 t; cvta.to.shared.u64 t, %1; cvt.u32.u64 %0, t; }" : "=r"(r) : "l"(p));
    return r;
}
__device__ __forceinline__ void ldsm_x4(uint32_t& a0, uint32_t& a1, uint32_t& a2, uint32_t& a3, uint32_t addr) {
    asm volatile("ldmatrix.sync.aligned.m8n8.x4.shared.b16 {%0,%1,%2,%3}, [%4];"
                 : "=r"(a0), "=r"(a1), "=r"(a2), "=r"(a3) : "r"(addr));
}
__device__ __forceinline__ void ldsm_x4_t(uint32_t& a0, uint32_t& a1, uint32_t& a2, uint32_t& a3, uint32_t addr) {
    asm volatile("ldmatrix.sync.aligned.m8n8.x4.trans.shared.b16 {%0,%1,%2,%3}, [%4];"
                 : "=r"(a0), "=r"(a1), "=r"(a2), "=r"(a3) : "r"(addr));
}
__device__ __forceinline__ void ldsm_x2(uint32_t& b0, uint32_t& b1, uint32_t addr) {
    asm volatile("ldmatrix.sync.aligned.m8n8.x2.shared.b16 {%0,%1}, [%2];"
                 : "=r"(b0), "=r"(b1) : "r"(addr));
}
__device__ __forceinline__ void mma_bf16(float& c0, float& c1, float& c2, float& c3,
                                         uint32_t a0, uint32_t a1, uint32_t a2, uint32_t a3,
                                         uint32_t b0, uint32_t b1) {
    asm volatile("mma.sync.aligned.m16n8k16.row.col.f32.bf16.bf16.f32 "
                 "{%0,%1,%2,%3}, {%4,%5,%6,%7}, {%8,%9}, {%0,%1,%2,%3};"
                 : "+f"(c0), "+f"(c1), "+f"(c2), "+f"(c3)
                 : "r"(a0), "r"(a1), "r"(a2), "r"(a3), "r"(b0), "r"(b1));
}
__device__ __forceinline__ uint32_t pack_bf16x2(float lo, float hi) {
    uint32_t p;
    asm("cvt.rn.bf16x2.f32 %0, %1, %2;" : "=r"(p) : "f"(hi), "f"(lo));
    return p;
}
// split fp32 pair -> (hi bf16x2, lo bf16x2)
__device__ __forceinline__ void split2(float a, float b, uint32_t& hi, uint32_t& lo) {
    __nv_bfloat16 ha = __float2bfloat16(a), hb = __float2bfloat16(b);
    float ra = a - __bfloat162float(ha);
    float rb = b - __bfloat162float(hb);
    hi = pack_bf16x2(__bfloat162float(ha), __bfloat162float(hb));
    lo = pack_bf16x2(ra, rb);
}

// ---------------- K0a: x -> bf16 ----------------
__global__ void xconv_kernel(const float* __restrict__ x, __nv_bfloat16* __restrict__ xb) {
    int idx = (blockIdx.x * 256 + threadIdx.x) * 4;
    float4 v = *(const float4*)(x + idx);
    uint32_t lo = pack_bf16x2(v.x, v.y);
    uint32_t hi = pack_bf16x2(v.z, v.w);
    *(uint2*)(xb + idx) = make_uint2(lo, hi);
}

// ---------------- K0b: W [K][N] fp32 -> Wt [N][K] bf16 ----------------
__global__ void wtrans_kernel(const float* __restrict__ W, __nv_bfloat16* __restrict__ Wt) {
    __shared__ float tile[32][33];
    int k0 = blockIdx.y * 32, n0 = blockIdx.x * 32;
    int x = threadIdx.x & 31, y = threadIdx.x >> 5;   // y 0..7
#pragma unroll
    for (int r = 0; r < 4; r++)
        tile[y * 4 + r][x] = W[(size_t)(k0 + y * 4 + r) * DM + n0 + x];
    __syncthreads();
#pragma unroll
    for (int r = 0; r < 4; r++)
        Wt[(size_t)(n0 + y * 4 + r) * DM + k0 + x] = __float2bfloat16(tile[x][y * 4 + r]);
}

// ---------------- K1: projection GEMM bf16 mma (logit path: q, k) --------
__global__ __launch_bounds__(256) void proj_gemm_bf16(
        const __nv_bfloat16* __restrict__ X,
        const __nv_bfloat16* __restrict__ Wt,
        const float* __restrict__ bias,
        __nv_bfloat16* __restrict__ C) {
    __shared__ __align__(16) uint16_t Xs[64 * 72];
    __shared__ __align__(16) uint16_t Ws[64 * 72];
    int t = threadIdx.x, lane = t & 31, w = t >> 5;
    int m0 = blockIdx.y * 64, n0 = blockIdx.x * 64;
    int mblk = (w & 3) * 16, nhalf = (w >> 2) * 32;
    uint32_t Xb = sptr(Xs), Wb = sptr(Ws);
    float c[4][4] = {};

    for (int k0 = 0; k0 < DM; k0 += 64) {
        __syncthreads();
#pragma unroll
        for (int r = 0; r < 2; r++) {
            int f = r * 256 + t;
            int row = f >> 3, c8 = (f & 7) * 8;
            *(uint4*)&Xs[row * 72 + c8] = *(const uint4*)(X  + (size_t)(m0 + row) * DM + k0 + c8);
            *(uint4*)&Ws[row * 72 + c8] = *(const uint4*)(Wt + (size_t)(n0 + row) * DM + k0 + c8);
        }
        __syncthreads();
#pragma unroll
        for (int ks = 0; ks < 4; ks++) {
            uint32_t a0, a1, a2, a3;
            ldsm_x4(a0, a1, a2, a3, Xb + ((mblk + (lane & 15)) * 72 + ks * 16 + ((lane >> 4) << 3)) * 2);
#pragma unroll
            for (int nb = 0; nb < 2; nb++) {
                uint32_t b0, b1, b2, b3;
                int row = nhalf + nb * 16 + ((lane & 7) | ((lane >> 1) & 8));
                int col = ks * 16 + ((lane & 8) ? 8 : 0);
                ldsm_x4(b0, b1, b2, b3, Wb + (row * 72 + col) * 2);
                mma_bf16(c[nb*2][0], c[nb*2][1], c[nb*2][2], c[nb*2][3], a0, a1, a2, a3, b0, b1);
                mma_bf16(c[nb*2+1][0], c[nb*2+1][1], c[nb*2+1][2], c[nb*2+1][3], a0, a1, a2, a3, b2, b3);
            }
        }
    }
    int r = lane >> 2, cc = 2 * (lane & 3);
#pragma unroll
    for (int nb = 0; nb < 4; nb++) {
        int n = n0 + nhalf + nb * 8 + cc;
        float b0 = bias[n], b1 = bias[n + 1];
        float v0 = fmaxf(c[nb][0] + b0, 0.f), v1 = fmaxf(c[nb][1] + b1, 0.f);
        float v2 = fmaxf(c[nb][2] + b0, 0.f), v3 = fmaxf(c[nb][3] + b1, 0.f);
        *(uint32_t*)(C + (size_t)(m0 + mblk + r) * DM + n)     = pack_bf16x2(v0, v1);
        *(uint32_t*)(C + (size_t)(m0 + mblk + r + 8) * DM + n) = pack_bf16x2(v2, v3);
    }
}

// ---------------- split-bf16 fp32 GEMM (near-fp32 accuracy on tensor cores)
// C[M,N] = A[M,K] @ B[K,N] (+ bias). A row-major lda; B row-major ldb ([k][n]).
// z-offsets allow per-head slab addressing (accv).
__global__ __launch_bounds__(256) void fgemm_split_kernel(
        const float* __restrict__ A, int lda, int aoffz,
        const float* __restrict__ B, int ldb, int boffz,
        float* __restrict__ C, int ldc, int coffz,
        int K, const float* __restrict__ bias) {
    __shared__ __align__(16) uint16_t Ahi[64 * 72], Alo[64 * 72];
    __shared__ __align__(16) uint16_t Bhi[64 * 72], Blo[64 * 72];
    int t = threadIdx.x, lane = t & 31, w = t >> 5;
    int m0 = blockIdx.y * 64, n0 = blockIdx.x * 64, z = blockIdx.z;
    A += (size_t)z * aoffz; B += (size_t)z * boffz; C += (size_t)z * coffz;
    int mblk = (w & 3) * 16, nhalf = (w >> 2) * 32;
    uint32_t Ahb = sptr(Ahi), Alb = sptr(Alo), Bhb = sptr(Bhi), Blb = sptr(Blo);
    float c[4][4] = {};

    for (int k0 = 0; k0 < K; k0 += 64) {
        __syncthreads();
#pragma unroll
        for (int r = 0; r < 4; r++) {
            int f = r * 256 + t;
            int row = f >> 4, c4 = (f & 15) * 4;
            float4 av = *(const float4*)(A + (size_t)(m0 + row) * lda + k0 + c4);
            uint32_t h0, l0, h1, l1;
            split2(av.x, av.y, h0, l0);
            split2(av.z, av.w, h1, l1);
            *(uint2*)&Ahi[row * 72 + c4] = make_uint2(h0, h1);
            *(uint2*)&Alo[row * 72 + c4] = make_uint2(l0, l1);
            float4 bv = *(const float4*)(B + (size_t)(k0 + row) * ldb + n0 + c4);
            split2(bv.x, bv.y, h0, l0);
            split2(bv.z, bv.w, h1, l1);
            *(uint2*)&Bhi[row * 72 + c4] = make_uint2(h0, h1);
            *(uint2*)&Blo[row * 72 + c4] = make_uint2(l0, l1);
        }
        __syncthreads();
#pragma unroll
        for (int ks = 0; ks < 4; ks++) {
            uint32_t aoff = ((mblk + (lane & 15)) * 72 + ks * 16 + ((lane >> 4) << 3)) * 2;
            uint32_t ah0, ah1, ah2, ah3, al0, al1, al2, al3;
            ldsm_x4(ah0, ah1, ah2, ah3, Ahb + aoff);
            ldsm_x4(al0, al1, al2, al3, Alb + aoff);
#pragma unroll
            for (int nb = 0; nb < 2; nb++) {
                uint32_t boff = ((ks * 16 + (lane & 15)) * 72 + nhalf + nb * 16 + ((lane >> 4) << 3)) * 2;
                uint32_t bh0, bh1, bh2, bh3, bl0, bl1, bl2, bl3;
                ldsm_x4_t(bh0, bh1, bh2, bh3, Bhb + boff);
                ldsm_x4_t(bl0, bl1, bl2, bl3, Blb + boff);
                float* cl = c[nb * 2];
                float* ch = c[nb * 2 + 1];
                mma_bf16(cl[0], cl[1], cl[2], cl[3], ah0, ah1, ah2, ah3, bh0, bh1);
                mma_bf16(cl[0], cl[1], cl[2], cl[3], ah0, ah1, ah2, ah3, bl0, bl1);
                mma_bf16(cl[0], cl[1], cl[2], cl[3], al0, al1, al2, al3, bh0, bh1);
                mma_bf16(ch[0], ch[1], ch[2], ch[3], ah0, ah1, ah2, ah3, bh2, bh3);
                mma_bf16(ch[0], ch[1], ch[2], ch[3], ah0, ah1, ah2, ah3, bl2, bl3);
                mma_bf16(ch[0], ch[1], ch[2], ch[3], al0, al1, al2, al3, bh2, bh3);
            }
        }
    }
    int r = lane >> 2, cc = 2 * (lane & 3);
#pragma unroll
    for (int nb = 0; nb < 4; nb++) {
        int n = n0 + nhalf + nb * 8 + cc;
        float b0 = bias ? bias[n] : 0.f;
        float b1 = bias ? bias[n + 1] : 0.f;
        *(float2*)(C + (size_t)(m0 + mblk + r) * ldc + n)     = make_float2(c[nb][0] + b0, c[nb][1] + b1);
        *(float2*)(C + (size_t)(m0 + mblk + r + 8) * ldc + n) = make_float2(c[nb][2] + b0, c[nb][3] + b1);
    }
}

// ---------------- K2: qk scores via bf16 mma ----------------
__global__ __launch_bounds__(256) void qk_mma_kernel(
        const __nv_bfloat16* __restrict__ Q, const __nv_bfloat16* __restrict__ K) {
    __shared__ __align__(16) uint16_t Qs[64 * 72];   // [i][e]
    __shared__ __align__(16) uint16_t Ks[64 * 72];   // [j][e]
    int h = blockIdx.z, i0 = blockIdx.y * 64, j0 = blockIdx.x * 64;
    int t = threadIdx.x, lane = t & 31, w = t >> 5;
    int iblk = (w & 3) * 16, jhalf = (w >> 2) * 32;
    uint32_t Qb = sptr(Qs), Kb = sptr(Ks);

#pragma unroll
    for (int r = 0; r < 2; r++) {
        int f = r * 256 + t;
        int row = f >> 3, c8 = (f & 7) * 8;
        *(uint4*)&Qs[row * 72 + c8] = *(const uint4*)(Q + (size_t)(i0 + row) * DM + h * DK + c8);
        *(uint4*)&Ks[row * 72 + c8] = *(const uint4*)(K + (size_t)(j0 + row) * DM + h * DK + c8);
    }
    __syncthreads();

    float c[4][4] = {};
#pragma unroll
    for (int ks = 0; ks < 4; ks++) {
        uint32_t a0, a1, a2, a3;
        ldsm_x4(a0, a1, a2, a3, Qb + ((iblk + (lane & 15)) * 72 + ks * 16 + ((lane >> 4) << 3)) * 2);
#pragma unroll
        for (int nb = 0; nb < 2; nb++) {
            uint32_t b0, b1, b2, b3;
            int row = jhalf + nb * 16 + ((lane & 7) | ((lane >> 1) & 8));
            int col = ks * 16 + ((lane & 8) ? 8 : 0);
            ldsm_x4(b0, b1, b2, b3, Kb + (row * 72 + col) * 2);
            mma_bf16(c[nb*2][0], c[nb*2][1], c[nb*2][2], c[nb*2][3], a0, a1, a2, a3, b0, b1);
            mma_bf16(c[nb*2+1][0], c[nb*2+1][1], c[nb*2+1][2], c[nb*2+1][3], a0, a1, a2, a3, b2, b3);
        }
    }
    int r = lane >> 2, cc = 2 * (lane & 3);
#pragma unroll
    for (int nb = 0; nb < 4; nb++) {
        int j = j0 + jhalf + nb * 8 + cc;
        *(float2*)(g_scores + (size_t)(i0 + iblk + r) * NH + h * N_TOK + j)     = make_float2(c[nb][0], c[nb][1]);
        *(float2*)(g_scores + (size_t)(i0 + iblk + r + 8) * NH + h * N_TOK + j) = make_float2(c[nb][2], c[nb][3]);
    }
}

// ---------------- K3: fused structure-scores + softmax -> p fp32 ---------
#define SS_SMEM 61824
__global__ __launch_bounds__(256, 2) void sscore_kernel(
        const float* __restrict__ S,
        const __nv_bfloat16* __restrict__ qb,
        const float* __restrict__ Wsk,
        const float* __restrict__ bsk) {
    extern __shared__ __align__(16) char dyn[];
    uint16_t* S_sh  = (uint16_t*)dyn;              // [128 j][72 c]
    uint16_t* W_sh  = (uint16_t*)(dyn + 18432);    // [64 e][72 c]
    uint16_t* q_sh  = (uint16_t*)(dyn + 27648);    // [8 h][72 e]
    float*    bsk_sh = (float*)(dyn + 28800);      // 64
    float*    p_sh  = (float*)(dyn + 29056);       // [8 h][1024 j]

    const int i    = blockIdx.x;
    const int t    = threadIdx.x;
    const int lane = t & 31;
    const int w    = t >> 5;

#pragma unroll
    for (int r = 0; r < 16; r++) {
        int f = r * 256 + t;
        int c = f >> 6, e = f & 63;
        __nv_bfloat16 b = __float2bfloat16(Wsk[f]);
        W_sh[e * 72 + c] = *(uint16_t*)&b;
    }
    if (t < 64) {
        int h = t >> 3, e8 = (t & 7) * 8;
        *(uint4*)&q_sh[h * 72 + e8] = *(const uint4*)(qb + (size_t)i * DM + h * DK + e8);
        bsk_sh[t] = bsk[t];
    }
    __syncthreads();

    const uint32_t Sbase = sptr(S_sh);
    const uint32_t Wbase = sptr(W_sh);
    const uint32_t qbase = sptr(q_sh);
    const uint32_t offA = ((w * 16 + (lane & 15)) * 72 + ((lane >> 4) << 3)) * 2;
    const uint32_t offB = ((lane & 7) * 72 + (((lane >> 3) & 1) << 3)) * 2;

    uint32_t qf[4][2];
#pragma unroll
    for (int ek = 0; ek < 4; ek++)
        ldsm_x2(qf[ek][0], qf[ek][1], qbase + offB + ek * 32);

    const int ecol = 2 * (lane & 3);
    const float* Srow = S + (size_t)i * N_TOK * 64;

    for (int j0 = 0; j0 < N_TOK; j0 += 128) {
        __syncthreads();
#pragma unroll
        for (int r = 0; r < 8; r++) {
            int f  = r * 256 + t;
            int jj = f >> 4;
            int c4 = (f & 15) * 4;
            float4 v = *(const float4*)(Srow + (size_t)(j0 + jj) * 64 + c4);
            uint32_t lo = pack_bf16x2(v.x, v.y);
            uint32_t hi = pack_bf16x2(v.z, v.w);
            *(uint2*)&S_sh[jj * 72 + c4] = make_uint2(lo, hi);
        }
        __syncthreads();

        uint32_t sa[4][4];
#pragma unroll
        for (int ck = 0; ck < 4; ck++)
            ldsm_x4(sa[ck][0], sa[ck][1], sa[ck][2], sa[ck][3], Sbase + offA + ck * 32);

        uint32_t skl[8], skh[8];
#pragma unroll
        for (int et = 0; et < 8; et++) {
            float c0 = 0.f, c1 = 0.f, c2 = 0.f, c3 = 0.f;
#pragma unroll
            for (int ck = 0; ck < 4; ck++) {
                uint32_t b0, b1;
                ldsm_x2(b0, b1, Wbase + offB + et * (8 * 72 * 2) + ck * 32);
                mma_bf16(c0, c1, c2, c3, sa[ck][0], sa[ck][1], sa[ck][2], sa[ck][3], b0, b1);
            }
            float blo = bsk_sh[et * 8 + ecol];
            float bhi = bsk_sh[et * 8 + ecol + 1];
            c0 = fmaxf(c0 + blo, 0.f); c1 = fmaxf(c1 + bhi, 0.f);
            c2 = fmaxf(c2 + blo, 0.f); c3 = fmaxf(c3 + bhi, 0.f);
            skl[et] = pack_bf16x2(c0, c1);
            skh[et] = pack_bf16x2(c2, c3);
        }

        float s0 = 0.f, s1 = 0.f, s2 = 0.f, s3 = 0.f;
#pragma unroll
        for (int ek = 0; ek < 4; ek++)
            mma_bf16(s0, s1, s2, s3,
                     skl[2*ek], skh[2*ek], skl[2*ek+1], skh[2*ek+1],
                     qf[ek][0], qf[ek][1]);

        int jw = j0 + w * 16 + (lane >> 2);
        int h0 = 2 * (lane & 3);
        p_sh[h0 * N_TOK + jw]           = s0;
        p_sh[(h0 + 1) * N_TOK + jw]     = s1;
        p_sh[h0 * N_TOK + jw + 8]       = s2;
        p_sh[(h0 + 1) * N_TOK + jw + 8] = s3;
    }
    __syncthreads();

    // softmax: warp w owns row h=w; p written back to g_scores (fp32)
    {
        float* row = p_sh + w * N_TOK;
        float* gsc = g_scores + (size_t)i * NH + w * N_TOK;
        float mx = -1e30f;
#pragma unroll
        for (int rr = 0; rr < 8; rr++) {
            int idx = rr * 128 + lane * 4;
            float4 g = *(const float4*)(gsc + idx);
            float4 p = *(float4*)(row + idx);
            p.x = (p.x + g.x) * SCALE; p.y = (p.y + g.y) * SCALE;
            p.z = (p.z + g.z) * SCALE; p.w = (p.w + g.w) * SCALE;
            *(float4*)(row + idx) = p;
            mx = fmaxf(mx, fmaxf(fmaxf(p.x, p.y), fmaxf(p.z, p.w)));
        }
#pragma unroll
        for (int o = 16; o; o >>= 1) mx = fmaxf(mx, __shfl_xor_sync(0xffffffffu, mx, o));
        float sum = 0.f;
#pragma unroll
        for (int rr = 0; rr < 8; rr++) {
            int idx = rr * 128 + lane * 4;
            float4 p = *(float4*)(row + idx);
            p.x = __expf(p.x - mx); p.y = __expf(p.y - mx);
            p.z = __expf(p.z - mx); p.w = __expf(p.w - mx);
            *(float4*)(row + idx) = p;
            sum += p.x + p.y + p.z + p.w;
        }
#pragma unroll
        for (int o = 16; o; o >>= 1) sum += __shfl_xor_sync(0xffffffffu, sum, o);
        float inv = 1.0f / sum;
#pragma unroll
        for (int rr = 0; rr < 8; rr++) {
            int idx = rr * 128 + lane * 4;
            float4 p = *(float4*)(row + idx);
            p.x *= inv; p.y *= inv; p.z *= inv; p.w *= inv;
            *(float4*)(gsc + idx) = p;
        }
    }
}

// ---------------- K5b: acc_t[i,h,e] = sum_j p[i,h,j] * S[i,j,e] ----------
__global__ void acct_kernel(const float* __restrict__ S) {
    __shared__ float Ssh[64 * 68];
    __shared__ float psh[8 * 64];
    __shared__ float red[8 * 64];
    int i = blockIdx.x;
    int t = threadIdx.x;
    const int e4 = (t % 16) * 4;
    const int h  = (t / 16) % 8;
    const int jh = t / 128;

    float4 acc = make_float4(0.f, 0.f, 0.f, 0.f);
    for (int j0 = 0; j0 < N_TOK; j0 += 64) {
        __syncthreads();
#pragma unroll
        for (int r = 0; r < 4; r++) {
            int f  = r * 256 + t;
            int j  = f / 16;
            int c4 = (f % 16) * 4;
            *(float4*)&Ssh[j * 68 + c4] =
                *(const float4*)(S + ((size_t)i * N_TOK + j0 + j) * 64 + c4);
        }
        if (t < 128) {
            int hh = t / 16;
            int j4 = (t % 16) * 4;
            *(float4*)&psh[hh * 64 + j4] =
                *(const float4*)(g_scores + (size_t)i * NH + hh * N_TOK + j0 + j4);
        }
        __syncthreads();
        int jb = jh * 32;
#pragma unroll 8
        for (int j = jb; j < jb + 32; j++) {
            float4 s = *(const float4*)&Ssh[j * 68 + e4];
            float  pp = psh[h * 64 + j];
            acc.x += pp * s.x; acc.y += pp * s.y; acc.z += pp * s.z; acc.w += pp * s.w;
        }
    }
    __syncthreads();
    if (jh == 1) *(float4*)&red[h * 64 + e4] = acc;
    __syncthreads();
    if (jh == 0) {
        float4 o = *(const float4*)&red[h * 64 + e4];
        o.x += acc.x; o.y += acc.y; o.z += acc.z; o.w += acc.w;
        *(float4*)(g_acct + (size_t)i * DM + h * DK + e4) = o;
    }
}

// ---------------- K6: out_pre = acc_v + acc_t @ Wsv + bsv ----------------
__global__ void combine_kernel(const float* __restrict__ Wsv, const float* __restrict__ bsv) {
    __shared__ float Wsh[64 * 64];
    __shared__ float tsh[8 * 64];
    int i = blockIdx.x;
    int t = threadIdx.x;
#pragma unroll
    for (int r = 0; r < 4; r++) {
        int f = r * 256 + t;
        *(float4*)&Wsh[f * 4] = *(const float4*)(Wsv + f * 4);
    }
    if (t < 128) *(float4*)&tsh[t * 4] = *(const float4*)(g_acct + (size_t)i * DM + t * 4);
    __syncthreads();
    int d  = t % 64;
    int h0 = t / 64;
    float bd = bsv[d];
#pragma unroll
    for (int r = 0; r < 2; r++) {
        int h = h0 + r * 4;
        float a = 0.f;
#pragma unroll 16
        for (int e = 0; e < 64; e++) a += tsh[h * 64 + e] * Wsh[e * 64 + d];
        g_outpre[(size_t)i * DM + h * DK + d] =
            g_accv[(size_t)i * DM + h * DK + d] + a + bd;
    }
}

// ---------------- launch ----------------
extern "C" void kernel_launch(void* const* d_in, const int* in_sizes, int n_in,
                              void* d_out, int out_size) {
    const float* x   = (const float*)d_in[0];
    const float* S   = (const float*)d_in[1];
    const float* Wq  = (const float*)d_in[2];  const float* bq  = (const float*)d_in[3];
    const float* Wk  = (const float*)d_in[4];  const float* bk  = (const float*)d_in[5];
    const float* Wv  = (const float*)d_in[6];  const float* bv  = (const float*)d_in[7];
    const float* Wo  = (const float*)d_in[8];  const float* bo  = (const float*)d_in[9];
    const float* Wsk = (const float*)d_in[10]; const float* bsk = (const float*)d_in[11];
    const float* Wsv = (const float*)d_in[12]; const float* bsv = (const float*)d_in[13];
    float* out = (float*)d_out;

    void *pxb, *pwt, *pqb, *pkb, *pv, *pop, *psc, *pav;
    cudaGetSymbolAddress(&pxb, g_xb);
    cudaGetSymbolAddress(&pwt, g_wt);
    cudaGetSymbolAddress(&pqb, g_qb);
    cudaGetSymbolAddress(&pkb, g_kb);
    cudaGetSymbolAddress(&pv,  g_v);
    cudaGetSymbolAddress(&pop, g_outpre);
    cudaGetSymbolAddress(&psc, g_scores);
    cudaGetSymbolAddress(&pav, g_accv);
    __nv_bfloat16* xb = (__nv_bfloat16*)pxb;
    __nv_bfloat16* wt = (__nv_bfloat16*)pwt;

    cudaFuncSetAttribute(sscore_kernel, cudaFuncAttributeMaxDynamicSharedMemorySize, SS_SMEM);

    // x -> bf16 (logit path only)
    xconv_kernel<<<N_TOK * DM / 1024, 256>>>(x, xb);

    dim3 tg(16, 16);
    dim3 pg(DM / 64, N_TOK / 64);
    // q/k projections: bf16 mma (feed softmax only — bf16-safe)
    wtrans_kernel<<<tg, 256>>>(Wq, wt);
    proj_gemm_bf16<<<pg, 256>>>(xb, wt, bq, (__nv_bfloat16*)pqb);
    wtrans_kernel<<<tg, 256>>>(Wk, wt);
    proj_gemm_bf16<<<pg, 256>>>(xb, wt, bk, (__nv_bfloat16*)pkb);
    // v projection: split-bf16 tensor-core GEMM (near-fp32 exact)
    fgemm_split_kernel<<<pg, 256>>>(x, DM, 0, Wv, DM, 0, (float*)pv, DM, 0, DM, bv);

    // qk scores (bf16 mma, fp32 out)
    qk_mma_kernel<<<dim3(16, 16, 8), 256>>>((const __nv_bfloat16*)pqb, (const __nv_bfloat16*)pkb);

    // structure scores + softmax -> p fp32 (in place in g_scores)
    sscore_kernel<<<N_TOK, 256, SS_SMEM>>>(S, (const __nv_bfloat16*)pqb, Wsk, bsk);

    // acc_v = p @ v : split-bf16 GEMM, one z-slab per head
    fgemm_split_kernel<<<dim3(1, 16, 8), 256>>>(
        (const float*)psc, NH, N_TOK,
        (const float*)pv,  DM, DK,
        (float*)pav,       DM, DK,
        N_TOK, nullptr);

    acct_kernel<<<N_TOK, 256>>>(S);

    combine_kernel<<<N_TOK, 256>>>(Wsv, bsv);

    // final output projection: split-bf16 GEMM
    fgemm_split_kernel<<<pg, 256>>>((const float*)pop, DM, 0, Wo, DM, 0, out, DM, 0, DM, bo);
}

// round 13
// speedup vs baseline: 2.7923x; 1.1404x over previous
#include <cuda_runtime.h>
#include <cuda_bf16.h>
#include <math.h>
#include <stdint.h>

#define N_TOK 1024
#define DM    512
#define H     8
#define DK    64
#define NH    8192          // N_TOK * H
#define SCALE 0.125f        // 1/sqrt(64)

// ---------------- scratch (device globals; no allocation) ----------------
__device__ __nv_bfloat16 g_xb[N_TOK * DM];            // x in bf16
__device__ __nv_bfloat16 g_wt[DM * DM];               // transposed Wq bf16 [n][k]
__device__ __nv_bfloat16 g_wt2[DM * DM];              // transposed Wk bf16 [n][k]
__device__ __nv_bfloat16 g_qb[N_TOK * DM];            // relu(q) bf16 (logit path only)
__device__ __nv_bfloat16 g_kb[N_TOK * DM];            // relu(k) bf16 (logit path only)
__device__ float g_v[N_TOK * DM];                     // v fp32 (output path, near-exact)
__device__ float g_scores[(size_t)N_TOK * H * N_TOK]; // qk scores -> then p (fp32, in place)
__device__ float g_accv[N_TOK * DM];
__device__ float g_acct[N_TOK * DM];
__device__ float g_outpre[N_TOK * DM];

// ---------------- asm helpers ----------------
__device__ __forceinline__ uint32_t sptr(const void* p) {
    uint32_t r;
    asm("{ .reg .u64 t; cvta.to.shared.u64 t, %1; cvt.u32.u64 %0, t; }" : "=r"(r) : "l"(p));
    return r;
}
__device__ __forceinline__ void ldsm_x4(uint32_t& a0, uint32_t& a1, uint32_t& a2, uint32_t& a3, uint32_t addr) {
    asm volatile("ldmatrix.sync.aligned.m8n8.x4.shared.b16 {%0,%1,%2,%3}, [%4];"
                 : "=r"(a0), "=r"(a1), "=r"(a2), "=r"(a3) : "r"(addr));
}
__device__ __forceinline__ void ldsm_x4_t(uint32_t& a0, uint32_t& a1, uint32_t& a2, uint32_t& a3, uint32_t addr) {
    asm volatile("ldmatrix.sync.aligned.m8n8.x4.trans.shared.b16 {%0,%1,%2,%3}, [%4];"
                 : "=r"(a0), "=r"(a1), "=r"(a2), "=r"(a3) : "r"(addr));
}
__device__ __forceinline__ void ldsm_x2(uint32_t& b0, uint32_t& b1, uint32_t addr) {
    asm volatile("ldmatrix.sync.aligned.m8n8.x2.shared.b16 {%0,%1}, [%2];"
                 : "=r"(b0), "=r"(b1) : "r"(addr));
}
__device__ __forceinline__ void mma_bf16(float& c0, float& c1, float& c2, float& c3,
                                         uint32_t a0, uint32_t a1, uint32_t a2, uint32_t a3,
                                         uint32_t b0, uint32_t b1) {
    asm volatile("mma.sync.aligned.m16n8k16.row.col.f32.bf16.bf16.f32 "
                 "{%0,%1,%2,%3}, {%4,%5,%6,%7}, {%8,%9}, {%0,%1,%2,%3};"
                 : "+f"(c0), "+f"(c1), "+f"(c2), "+f"(c3)
                 : "r"(a0), "r"(a1), "r"(a2), "r"(a3), "r"(b0), "r"(b1));
}
__device__ __forceinline__ uint32_t pack_bf16x2(float lo, float hi) {
    uint32_t p;
    asm("cvt.rn.bf16x2.f32 %0, %1, %2;" : "=r"(p) : "f"(hi), "f"(lo));
    return p;
}
// split fp32 pair -> (hi bf16x2, lo bf16x2)
__device__ __forceinline__ void split2(float a, float b, uint32_t& hi, uint32_t& lo) {
    __nv_bfloat16 ha = __float2bfloat16(a), hb = __float2bfloat16(b);
    float ra = a - __bfloat162float(ha);
    float rb = b - __bfloat162float(hb);
    hi = pack_bf16x2(__bfloat162float(ha), __bfloat162float(hb));
    lo = pack_bf16x2(ra, rb);
}

// ---------------- K0a: x -> bf16 ----------------
__global__ void xconv_kernel(const float* __restrict__ x, __nv_bfloat16* __restrict__ xb) {
    int idx = (blockIdx.x * 256 + threadIdx.x) * 4;
    float4 v = *(const float4*)(x + idx);
    uint32_t lo = pack_bf16x2(v.x, v.y);
    uint32_t hi = pack_bf16x2(v.z, v.w);
    *(uint2*)(xb + idx) = make_uint2(lo, hi);
}

// ---------------- K0b: dual W [K][N] fp32 -> Wt [N][K] bf16 (z=2) --------
__global__ void wtrans2_kernel(const float* __restrict__ Wq, const float* __restrict__ Wk,
                               __nv_bfloat16* __restrict__ Wtq, __nv_bfloat16* __restrict__ Wtk) {
    const float* W = blockIdx.z ? Wk : Wq;
    __nv_bfloat16* Wt = blockIdx.z ? Wtk : Wtq;
    __shared__ float tile[32][33];
    int k0 = blockIdx.y * 32, n0 = blockIdx.x * 32;
    int x = threadIdx.x & 31, y = threadIdx.x >> 5;
#pragma unroll
    for (int r = 0; r < 4; r++)
        tile[y * 4 + r][x] = W[(size_t)(k0 + y * 4 + r) * DM + n0 + x];
    __syncthreads();
#pragma unroll
    for (int r = 0; r < 4; r++)
        Wt[(size_t)(n0 + y * 4 + r) * DM + k0 + x] = __float2bfloat16(tile[x][y * 4 + r]);
}

// ---------------- K1: dual projection GEMM bf16 mma (q and k, z=2) -------
__global__ __launch_bounds__(256) void proj2_gemm_bf16(
        const __nv_bfloat16* __restrict__ X,
        const __nv_bfloat16* __restrict__ Wtq,
        const __nv_bfloat16* __restrict__ Wtk,
        const float* __restrict__ bq,
        const float* __restrict__ bk,
        __nv_bfloat16* __restrict__ Cq,
        __nv_bfloat16* __restrict__ Ck) {
    const __nv_bfloat16* Wt = blockIdx.z ? Wtk : Wtq;
    const float* bias = blockIdx.z ? bk : bq;
    __nv_bfloat16* C = blockIdx.z ? Ck : Cq;
    __shared__ __align__(16) uint16_t Xs[64 * 72];
    __shared__ __align__(16) uint16_t Ws[64 * 72];
    int t = threadIdx.x, lane = t & 31, w = t >> 5;
    int m0 = blockIdx.y * 64, n0 = blockIdx.x * 64;
    int mblk = (w & 3) * 16, nhalf = (w >> 2) * 32;
    uint32_t Xb = sptr(Xs), Wb = sptr(Ws);
    float c[4][4] = {};

    for (int k0 = 0; k0 < DM; k0 += 64) {
        __syncthreads();
#pragma unroll
        for (int r = 0; r < 2; r++) {
            int f = r * 256 + t;
            int row = f >> 3, c8 = (f & 7) * 8;
            *(uint4*)&Xs[row * 72 + c8] = *(const uint4*)(X  + (size_t)(m0 + row) * DM + k0 + c8);
            *(uint4*)&Ws[row * 72 + c8] = *(const uint4*)(Wt + (size_t)(n0 + row) * DM + k0 + c8);
        }
        __syncthreads();
#pragma unroll
        for (int ks = 0; ks < 4; ks++) {
            uint32_t a0, a1, a2, a3;
            ldsm_x4(a0, a1, a2, a3, Xb + ((mblk + (lane & 15)) * 72 + ks * 16 + ((lane >> 4) << 3)) * 2);
#pragma unroll
            for (int nb = 0; nb < 2; nb++) {
                uint32_t b0, b1, b2, b3;
                int row = nhalf + nb * 16 + ((lane & 7) | ((lane >> 1) & 8));
                int col = ks * 16 + ((lane & 8) ? 8 : 0);
                ldsm_x4(b0, b1, b2, b3, Wb + (row * 72 + col) * 2);
                mma_bf16(c[nb*2][0], c[nb*2][1], c[nb*2][2], c[nb*2][3], a0, a1, a2, a3, b0, b1);
                mma_bf16(c[nb*2+1][0], c[nb*2+1][1], c[nb*2+1][2], c[nb*2+1][3], a0, a1, a2, a3, b2, b3);
            }
        }
    }
    int r = lane >> 2, cc = 2 * (lane & 3);
#pragma unroll
    for (int nb = 0; nb < 4; nb++) {
        int n = n0 + nhalf + nb * 8 + cc;
        float b0 = bias[n], b1 = bias[n + 1];
        float v0 = fmaxf(c[nb][0] + b0, 0.f), v1 = fmaxf(c[nb][1] + b1, 0.f);
        float v2 = fmaxf(c[nb][2] + b0, 0.f), v3 = fmaxf(c[nb][3] + b1, 0.f);
        *(uint32_t*)(C + (size_t)(m0 + mblk + r) * DM + n)     = pack_bf16x2(v0, v1);
        *(uint32_t*)(C + (size_t)(m0 + mblk + r + 8) * DM + n) = pack_bf16x2(v2, v3);
    }
}

// ---------------- split-bf16 fp32 GEMM (near-fp32 accuracy on tensor cores)
__global__ __launch_bounds__(256) void fgemm_split_kernel(
        const float* __restrict__ A, int lda, int aoffz,
        const float* __restrict__ B, int ldb, int boffz,
        float* __restrict__ C, int ldc, int coffz,
        int K, const float* __restrict__ bias) {
    __shared__ __align__(16) uint16_t Ahi[64 * 72], Alo[64 * 72];
    __shared__ __align__(16) uint16_t Bhi[64 * 72], Blo[64 * 72];
    int t = threadIdx.x, lane = t & 31, w = t >> 5;
    int m0 = blockIdx.y * 64, n0 = blockIdx.x * 64, z = blockIdx.z;
    A += (size_t)z * aoffz; B += (size_t)z * boffz; C += (size_t)z * coffz;
    int mblk = (w & 3) * 16, nhalf = (w >> 2) * 32;
    uint32_t Ahb = sptr(Ahi), Alb = sptr(Alo), Bhb = sptr(Bhi), Blb = sptr(Blo);
    float c[4][4] = {};

    for (int k0 = 0; k0 < K; k0 += 64) {
        __syncthreads();
#pragma unroll
        for (int r = 0; r < 4; r++) {
            int f = r * 256 + t;
            int row = f >> 4, c4 = (f & 15) * 4;
            float4 av = *(const float4*)(A + (size_t)(m0 + row) * lda + k0 + c4);
            uint32_t h0, l0, h1, l1;
            split2(av.x, av.y, h0, l0);
            split2(av.z, av.w, h1, l1);
            *(uint2*)&Ahi[row * 72 + c4] = make_uint2(h0, h1);
            *(uint2*)&Alo[row * 72 + c4] = make_uint2(l0, l1);
            float4 bv = *(const float4*)(B + (size_t)(k0 + row) * ldb + n0 + c4);
            split2(bv.x, bv.y, h0, l0);
            split2(bv.z, bv.w, h1, l1);
            *(uint2*)&Bhi[row * 72 + c4] = make_uint2(h0, h1);
            *(uint2*)&Blo[row * 72 + c4] = make_uint2(l0, l1);
        }
        __syncthreads();
#pragma unroll
        for (int ks = 0; ks < 4; ks++) {
            uint32_t aoff = ((mblk + (lane & 15)) * 72 + ks * 16 + ((lane >> 4) << 3)) * 2;
            uint32_t ah0, ah1, ah2, ah3, al0, al1, al2, al3;
            ldsm_x4(ah0, ah1, ah2, ah3, Ahb + aoff);
            ldsm_x4(al0, al1, al2, al3, Alb + aoff);
#pragma unroll
            for (int nb = 0; nb < 2; nb++) {
                uint32_t boff = ((ks * 16 + (lane & 15)) * 72 + nhalf + nb * 16 + ((lane >> 4) << 3)) * 2;
                uint32_t bh0, bh1, bh2, bh3, bl0, bl1, bl2, bl3;
                ldsm_x4_t(bh0, bh1, bh2, bh3, Bhb + boff);
                ldsm_x4_t(bl0, bl1, bl2, bl3, Blb + boff);
                float* cl = c[nb * 2];
                float* ch = c[nb * 2 + 1];
                mma_bf16(cl[0], cl[1], cl[2], cl[3], ah0, ah1, ah2, ah3, bh0, bh1);
                mma_bf16(cl[0], cl[1], cl[2], cl[3], ah0, ah1, ah2, ah3, bl0, bl1);
                mma_bf16(cl[0], cl[1], cl[2], cl[3], al0, al1, al2, al3, bh0, bh1);
                mma_bf16(ch[0], ch[1], ch[2], ch[3], ah0, ah1, ah2, ah3, bh2, bh3);
                mma_bf16(ch[0], ch[1], ch[2], ch[3], ah0, ah1, ah2, ah3, bl2, bl3);
                mma_bf16(ch[0], ch[1], ch[2], ch[3], al0, al1, al2, al3, bh2, bh3);
            }
        }
    }
    int r = lane >> 2, cc = 2 * (lane & 3);
#pragma unroll
    for (int nb = 0; nb < 4; nb++) {
        int n = n0 + nhalf + nb * 8 + cc;
        float b0 = bias ? bias[n] : 0.f;
        float b1 = bias ? bias[n + 1] : 0.f;
        *(float2*)(C + (size_t)(m0 + mblk + r) * ldc + n)     = make_float2(c[nb][0] + b0, c[nb][1] + b1);
        *(float2*)(C + (size_t)(m0 + mblk + r + 8) * ldc + n) = make_float2(c[nb][2] + b0, c[nb][3] + b1);
    }
}

// ---------------- K2: qk scores via bf16 mma ----------------
__global__ __launch_bounds__(256) void qk_mma_kernel(
        const __nv_bfloat16* __restrict__ Q, const __nv_bfloat16* __restrict__ K) {
    __shared__ __align__(16) uint16_t Qs[64 * 72];   // [i][e]
    __shared__ __align__(16) uint16_t Ks[64 * 72];   // [j][e]
    int h = blockIdx.z, i0 = blockIdx.y * 64, j0 = blockIdx.x * 64;
    int t = threadIdx.x, lane = t & 31, w = t >> 5;
    int iblk = (w & 3) * 16, jhalf = (w >> 2) * 32;
    uint32_t Qb = sptr(Qs), Kb = sptr(Ks);

#pragma unroll
    for (int r = 0; r < 2; r++) {
        int f = r * 256 + t;
        int row = f >> 3, c8 = (f & 7) * 8;
        *(uint4*)&Qs[row * 72 + c8] = *(const uint4*)(Q + (size_t)(i0 + row) * DM + h * DK + c8);
        *(uint4*)&Ks[row * 72 + c8] = *(const uint4*)(K + (size_t)(j0 + row) * DM + h * DK + c8);
    }
    __syncthreads();

    float c[4][4] = {};
#pragma unroll
    for (int ks = 0; ks < 4; ks++) {
        uint32_t a0, a1, a2, a3;
        ldsm_x4(a0, a1, a2, a3, Qb + ((iblk + (lane & 15)) * 72 + ks * 16 + ((lane >> 4) << 3)) * 2);
#pragma unroll
        for (int nb = 0; nb < 2; nb++) {
            uint32_t b0, b1, b2, b3;
            int row = jhalf + nb * 16 + ((lane & 7) | ((lane >> 1) & 8));
            int col = ks * 16 + ((lane & 8) ? 8 : 0);
            ldsm_x4(b0, b1, b2, b3, Kb + (row * 72 + col) * 2);
            mma_bf16(c[nb*2][0], c[nb*2][1], c[nb*2][2], c[nb*2][3], a0, a1, a2, a3, b0, b1);
            mma_bf16(c[nb*2+1][0], c[nb*2+1][1], c[nb*2+1][2], c[nb*2+1][3], a0, a1, a2, a3, b2, b3);
        }
    }
    int r = lane >> 2, cc = 2 * (lane & 3);
#pragma unroll
    for (int nb = 0; nb < 4; nb++) {
        int j = j0 + jhalf + nb * 8 + cc;
        *(float2*)(g_scores + (size_t)(i0 + iblk + r) * NH + h * N_TOK + j)     = make_float2(c[nb][0], c[nb][1]);
        *(float2*)(g_scores + (size_t)(i0 + iblk + r + 8) * NH + h * N_TOK + j) = make_float2(c[nb][2], c[nb][3]);
    }
}

// ---------------- K3: fused structure-scores + softmax -> p fp32 ---------
#define SS_SMEM 61824
__global__ __launch_bounds__(256, 3) void sscore_kernel(
        const float* __restrict__ S,
        const __nv_bfloat16* __restrict__ qb,
        const float* __restrict__ Wsk,
        const float* __restrict__ bsk) {
    extern __shared__ __align__(16) char dyn[];
    uint16_t* S_sh  = (uint16_t*)dyn;              // [128 j][72 c]
    uint16_t* W_sh  = (uint16_t*)(dyn + 18432);    // [64 e][72 c]
    uint16_t* q_sh  = (uint16_t*)(dyn + 27648);    // [8 h][72 e]
    float*    bsk_sh = (float*)(dyn + 28800);      // 64
    float*    p_sh  = (float*)(dyn + 29056);       // [8 h][1024 j]

    const int i    = blockIdx.x;
    const int t    = threadIdx.x;
    const int lane = t & 31;
    const int w    = t >> 5;

#pragma unroll
    for (int r = 0; r < 16; r++) {
        int f = r * 256 + t;
        int c = f >> 6, e = f & 63;
        __nv_bfloat16 b = __float2bfloat16(Wsk[f]);
        W_sh[e * 72 + c] = *(uint16_t*)&b;
    }
    if (t < 64) {
        int h = t >> 3, e8 = (t & 7) * 8;
        *(uint4*)&q_sh[h * 72 + e8] = *(const uint4*)(qb + (size_t)i * DM + h * DK + e8);
        bsk_sh[t] = bsk[t];
    }
    __syncthreads();

    const uint32_t Sbase = sptr(S_sh);
    const uint32_t Wbase = sptr(W_sh);
    const uint32_t qbase = sptr(q_sh);
    const uint32_t offA = ((w * 16 + (lane & 15)) * 72 + ((lane >> 4) << 3)) * 2;
    const uint32_t offB = ((lane & 7) * 72 + (((lane >> 3) & 1) << 3)) * 2;

    uint32_t qf[4][2];
#pragma unroll
    for (int ek = 0; ek < 4; ek++)
        ldsm_x2(qf[ek][0], qf[ek][1], qbase + offB + ek * 32);

    const int ecol = 2 * (lane & 3);
    const float* Srow = S + (size_t)i * N_TOK * 64;

    for (int j0 = 0; j0 < N_TOK; j0 += 128) {
        __syncthreads();
#pragma unroll
        for (int r = 0; r < 8; r++) {
            int f  = r * 256 + t;
            int jj = f >> 4;
            int c4 = (f & 15) * 4;
            float4 v = *(const float4*)(Srow + (size_t)(j0 + jj) * 64 + c4);
            uint32_t lo = pack_bf16x2(v.x, v.y);
            uint32_t hi = pack_bf16x2(v.z, v.w);
            *(uint2*)&S_sh[jj * 72 + c4] = make_uint2(lo, hi);
        }
        __syncthreads();

        uint32_t sa[4][4];
#pragma unroll
        for (int ck = 0; ck < 4; ck++)
            ldsm_x4(sa[ck][0], sa[ck][1], sa[ck][2], sa[ck][3], Sbase + offA + ck * 32);

        uint32_t skl[8], skh[8];
#pragma unroll
        for (int et = 0; et < 8; et++) {
            float c0 = 0.f, c1 = 0.f, c2 = 0.f, c3 = 0.f;
#pragma unroll
            for (int ck = 0; ck < 4; ck++) {
                uint32_t b0, b1;
                ldsm_x2(b0, b1, Wbase + offB + et * (8 * 72 * 2) + ck * 32);
                mma_bf16(c0, c1, c2, c3, sa[ck][0], sa[ck][1], sa[ck][2], sa[ck][3], b0, b1);
            }
            float blo = bsk_sh[et * 8 + ecol];
            float bhi = bsk_sh[et * 8 + ecol + 1];
            c0 = fmaxf(c0 + blo, 0.f); c1 = fmaxf(c1 + bhi, 0.f);
            c2 = fmaxf(c2 + blo, 0.f); c3 = fmaxf(c3 + bhi, 0.f);
            skl[et] = pack_bf16x2(c0, c1);
            skh[et] = pack_bf16x2(c2, c3);
        }

        float s0 = 0.f, s1 = 0.f, s2 = 0.f, s3 = 0.f;
#pragma unroll
        for (int ek = 0; ek < 4; ek++)
            mma_bf16(s0, s1, s2, s3,
                     skl[2*ek], skh[2*ek], skl[2*ek+1], skh[2*ek+1],
                     qf[ek][0], qf[ek][1]);

        int jw = j0 + w * 16 + (lane >> 2);
        int h0 = 2 * (lane & 3);
        p_sh[h0 * N_TOK + jw]           = s0;
        p_sh[(h0 + 1) * N_TOK + jw]     = s1;
        p_sh[h0 * N_TOK + jw + 8]       = s2;
        p_sh[(h0 + 1) * N_TOK + jw + 8] = s3;
    }
    __syncthreads();

    // softmax: warp w owns row h=w; p written back to g_scores (fp32)
    {
        float* row = p_sh + w * N_TOK;
        float* gsc = g_scores + (size_t)i * NH + w * N_TOK;
        float mx = -1e30f;
#pragma unroll
        for (int rr = 0; rr < 8; rr++) {
            int idx = rr * 128 + lane * 4;
            float4 g = *(const float4*)(gsc + idx);
            float4 p = *(float4*)(row + idx);
            p.x = (p.x + g.x) * SCALE; p.y = (p.y + g.y) * SCALE;
            p.z = (p.z + g.z) * SCALE; p.w = (p.w + g.w) * SCALE;
            *(float4*)(row + idx) = p;
            mx = fmaxf(mx, fmaxf(fmaxf(p.x, p.y), fmaxf(p.z, p.w)));
        }
#pragma unroll
        for (int o = 16; o; o >>= 1) mx = fmaxf(mx, __shfl_xor_sync(0xffffffffu, mx, o));
        float sum = 0.f;
#pragma unroll
        for (int rr = 0; rr < 8; rr++) {
            int idx = rr * 128 + lane * 4;
            float4 p = *(float4*)(row + idx);
            p.x = __expf(p.x - mx); p.y = __expf(p.y - mx);
            p.z = __expf(p.z - mx); p.w = __expf(p.w - mx);
            *(float4*)(row + idx) = p;
            sum += p.x + p.y + p.z + p.w;
        }
#pragma unroll
        for (int o = 16; o; o >>= 1) sum += __shfl_xor_sync(0xffffffffu, sum, o);
        float inv = 1.0f / sum;
#pragma unroll
        for (int rr = 0; rr < 8; rr++) {
            int idx = rr * 128 + lane * 4;
            float4 p = *(float4*)(row + idx);
            p.x *= inv; p.y *= inv; p.z *= inv; p.w *= inv;
            *(float4*)(gsc + idx) = p;
        }
    }
}

// ---------------- K5b: acc_t[i,h,e] = sum_j p[i,h,j] * S[i,j,e] ----------
// Register-accumulating streamer: S via coalesced LDG.128, p broadcast from
// smem, 8-head accumulators in registers, one smem tree-reduce at the end.
__global__ __launch_bounds__(256) void acct_kernel(const float* __restrict__ S) {
    __shared__ float psh[8 * 1024];     // 32KB: all p for this i, then reused for reduce
    int i = blockIdx.x, t = threadIdx.x;
#pragma unroll
    for (int r = 0; r < 8; r++) {
        int f = (r * 256 + t) * 4;
        *(float4*)&psh[f] = *(const float4*)(g_scores + (size_t)i * NH + f);
    }
    __syncthreads();

    const int e4   = (t & 15) * 4;   // 4 consecutive e
    const int joff = t >> 4;         // 0..15
    float4 acc[8];
#pragma unroll
    for (int h = 0; h < 8; h++) acc[h] = make_float4(0.f, 0.f, 0.f, 0.f);

    const float* Sr = S + (size_t)i * N_TOK * 64;
#pragma unroll 4
    for (int j = joff; j < N_TOK; j += 16) {
        float4 s = *(const float4*)(Sr + (size_t)j * 64 + e4);
#pragma unroll
        for (int h = 0; h < 8; h++) {
            float p = psh[h * N_TOK + j];
            acc[h].x += p * s.x; acc[h].y += p * s.y;
            acc[h].z += p * s.z; acc[h].w += p * s.w;
        }
    }
    __syncthreads();   // done reading psh

    // stage partials: psh reused as red[joff][512]
#pragma unroll
    for (int h = 0; h < 8; h++)
        *(float4*)&psh[joff * 512 + h * 64 + e4] = acc[h];
    __syncthreads();

#pragma unroll
    for (int r = 0; r < 2; r++) {
        int o = r * 256 + t;   // h*64 + e
        float s = 0.f;
#pragma unroll
        for (int jo = 0; jo < 16; jo++) s += psh[jo * 512 + o];
        g_acct[(size_t)i * DM + o] = s;
    }
}

// ---------------- K6: out_pre = acc_v + acc_t @ Wsv + bsv ----------------
__global__ void combine_kernel(const float* __restrict__ Wsv, const float* __restrict__ bsv) {
    __shared__ float Wsh[64 * 64];
    __shared__ float tsh[8 * 64];
    int i = blockIdx.x;
    int t = threadIdx.x;
#pragma unroll
    for (int r = 0; r < 4; r++) {
        int f = r * 256 + t;
        *(float4*)&Wsh[f * 4] = *(const float4*)(Wsv + f * 4);
    }
    if (t < 128) *(float4*)&tsh[t * 4] = *(const float4*)(g_acct + (size_t)i * DM + t * 4);
    __syncthreads();
    int d  = t % 64;
    int h0 = t / 64;
    float bd = bsv[d];
#pragma unroll
    for (int r = 0; r < 2; r++) {
        int h = h0 + r * 4;
        float a = 0.f;
#pragma unroll 16
        for (int e = 0; e < 64; e++) a += tsh[h * 64 + e] * Wsh[e * 64 + d];
        g_outpre[(size_t)i * DM + h * DK + d] =
            g_accv[(size_t)i * DM + h * DK + d] + a + bd;
    }
}

// ---------------- launch ----------------
extern "C" void kernel_launch(void* const* d_in, const int* in_sizes, int n_in,
                              void* d_out, int out_size) {
    const float* x   = (const float*)d_in[0];
    const float* S   = (const float*)d_in[1];
    const float* Wq  = (const float*)d_in[2];  const float* bq  = (const float*)d_in[3];
    const float* Wk  = (const float*)d_in[4];  const float* bk  = (const float*)d_in[5];
    const float* Wv  = (const float*)d_in[6];  const float* bv  = (const float*)d_in[7];
    const float* Wo  = (const float*)d_in[8];  const float* bo  = (const float*)d_in[9];
    const float* Wsk = (const float*)d_in[10]; const float* bsk = (const float*)d_in[11];
    const float* Wsv = (const float*)d_in[12]; const float* bsv = (const float*)d_in[13];
    float* out = (float*)d_out;

    void *pxb, *pwt, *pwt2, *pqb, *pkb, *pv, *pop, *psc, *pav;
    cudaGetSymbolAddress(&pxb, g_xb);
    cudaGetSymbolAddress(&pwt, g_wt);
    cudaGetSymbolAddress(&pwt2, g_wt2);
    cudaGetSymbolAddress(&pqb, g_qb);
    cudaGetSymbolAddress(&pkb, g_kb);
    cudaGetSymbolAddress(&pv,  g_v);
    cudaGetSymbolAddress(&pop, g_outpre);
    cudaGetSymbolAddress(&psc, g_scores);
    cudaGetSymbolAddress(&pav, g_accv);
    __nv_bfloat16* xb  = (__nv_bfloat16*)pxb;
    __nv_bfloat16* wt  = (__nv_bfloat16*)pwt;
    __nv_bfloat16* wt2 = (__nv_bfloat16*)pwt2;

    cudaFuncSetAttribute(sscore_kernel, cudaFuncAttributeMaxDynamicSharedMemorySize, SS_SMEM);

    // x -> bf16 (logit path only)
    xconv_kernel<<<N_TOK * DM / 1024, 256>>>(x, xb);

    // q/k weight transposes and projections, merged into z=2 launches
    wtrans2_kernel<<<dim3(16, 16, 2), 256>>>(Wq, Wk, wt, wt2);
    proj2_gemm_bf16<<<dim3(DM / 64, N_TOK / 64, 2), 256>>>(
        xb, wt, wt2, bq, bk, (__nv_bfloat16*)pqb, (__nv_bfloat16*)pkb);

    // v projection: split-bf16 tensor-core GEMM (near-fp32 exact)
    fgemm_split_kernel<<<dim3(DM / 64, N_TOK / 64), 256>>>(
        x, DM, 0, Wv, DM, 0, (float*)pv, DM, 0, DM, bv);

    // qk scores (bf16 mma, fp32 out)
    qk_mma_kernel<<<dim3(16, 16, 8), 256>>>((const __nv_bfloat16*)pqb, (const __nv_bfloat16*)pkb);

    // structure scores + softmax -> p fp32 (in place in g_scores)
    sscore_kernel<<<N_TOK, 256, SS_SMEM>>>(S, (const __nv_bfloat16*)pqb, Wsk, bsk);

    // acc_v = p @ v : split-bf16 GEMM, one z-slab per head
    fgemm_split_kernel<<<dim3(1, 16, 8), 256>>>(
        (const float*)psc, NH, N_TOK,
        (const float*)pv,  DM, DK,
        (float*)pav,       DM, DK,
        N_TOK, nullptr);

    // acc_t = p @ S (register streamer, fp32 exact)
    acct_kernel<<<N_TOK, 256>>>(S);

    combine_kernel<<<N_TOK, 256>>>(Wsv, bsv);

    // final output projection: split-bf16 GEMM
    fgemm_split_kernel<<<dim3(DM / 64, N_TOK / 64), 256>>>(
        (const float*)pop, DM, 0, Wo, DM, 0, out, DM, 0, DM, bo);
}

// round 14
// speedup vs baseline: 3.4281x; 1.2277x over previous
#include <cuda_runtime.h>
#include <cuda_bf16.h>
#include <math.h>
#include <stdint.h>

#define N_TOK 1024
#define DM    512
#define H     8
#define DK    64
#define NH    8192          // N_TOK * H
#define SCALE 0.125f        // 1/sqrt(64)

// ---------------- scratch (device globals; no allocation) ----------------
__device__ __nv_bfloat16 g_xb[N_TOK * DM];            // x in bf16
__device__ __nv_bfloat16 g_wt[DM * DM];               // transposed Wq bf16 [n][k]
__device__ __nv_bfloat16 g_wt2[DM * DM];              // transposed Wk bf16 [n][k]
__device__ __nv_bfloat16 g_qb[N_TOK * DM];            // relu(q) bf16 (logit path only)
__device__ __nv_bfloat16 g_kb[N_TOK * DM];            // relu(k) bf16 (logit path only)
__device__ float g_v[N_TOK * DM];                     // v fp32 (output path, near-exact)
__device__ float g_scores[(size_t)N_TOK * H * N_TOK]; // qk scores -> then p (fp32, in place)
__device__ float g_accv[N_TOK * DM];
__device__ float g_acct[N_TOK * DM];
__device__ float g_outpre[N_TOK * DM];

// ---------------- asm helpers ----------------
__device__ __forceinline__ uint32_t sptr(const void* p) {
    uint32_t r;
    asm("{ .reg .u64 t; cvta.to.shared.u64 t, %1; cvt.u32.u64 %0, t; }" : "=r"(r) : "l"(p));
    return r;
}
__device__ __forceinline__ void ldsm_x4(uint32_t& a0, uint32_t& a1, uint32_t& a2, uint32_t& a3, uint32_t addr) {
    asm volatile("ldmatrix.sync.aligned.m8n8.x4.shared.b16 {%0,%1,%2,%3}, [%4];"
                 : "=r"(a0), "=r"(a1), "=r"(a2), "=r"(a3) : "r"(addr));
}
__device__ __forceinline__ void ldsm_x4_t(uint32_t& a0, uint32_t& a1, uint32_t& a2, uint32_t& a3, uint32_t addr) {
    asm volatile("ldmatrix.sync.aligned.m8n8.x4.trans.shared.b16 {%0,%1,%2,%3}, [%4];"
                 : "=r"(a0), "=r"(a1), "=r"(a2), "=r"(a3) : "r"(addr));
}
__device__ __forceinline__ void ldsm_x2(uint32_t& b0, uint32_t& b1, uint32_t addr) {
    asm volatile("ldmatrix.sync.aligned.m8n8.x2.shared.b16 {%0,%1}, [%2];"
                 : "=r"(b0), "=r"(b1) : "r"(addr));
}
__device__ __forceinline__ void mma_bf16(float& c0, float& c1, float& c2, float& c3,
                                         uint32_t a0, uint32_t a1, uint32_t a2, uint32_t a3,
                                         uint32_t b0, uint32_t b1) {
    asm volatile("mma.sync.aligned.m16n8k16.row.col.f32.bf16.bf16.f32 "
                 "{%0,%1,%2,%3}, {%4,%5,%6,%7}, {%8,%9}, {%0,%1,%2,%3};"
                 : "+f"(c0), "+f"(c1), "+f"(c2), "+f"(c3)
                 : "r"(a0), "r"(a1), "r"(a2), "r"(a3), "r"(b0), "r"(b1));
}
__device__ __forceinline__ uint32_t pack_bf16x2(float lo, float hi) {
    uint32_t p;
    asm("cvt.rn.bf16x2.f32 %0, %1, %2;" : "=r"(p) : "f"(hi), "f"(lo));
    return p;
}
// split fp32 pair -> (hi bf16x2, lo bf16x2)
__device__ __forceinline__ void split2(float a, float b, uint32_t& hi, uint32_t& lo) {
    __nv_bfloat16 ha = __float2bfloat16(a), hb = __float2bfloat16(b);
    float ra = a - __bfloat162float(ha);
    float rb = b - __bfloat162float(hb);
    hi = pack_bf16x2(__bfloat162float(ha), __bfloat162float(hb));
    lo = pack_bf16x2(ra, rb);
}

// ---------------- K0a: x -> bf16 ----------------
__global__ void xconv_kernel(const float* __restrict__ x, __nv_bfloat16* __restrict__ xb) {
    int idx = (blockIdx.x * 256 + threadIdx.x) * 4;
    float4 v = *(const float4*)(x + idx);
    uint32_t lo = pack_bf16x2(v.x, v.y);
    uint32_t hi = pack_bf16x2(v.z, v.w);
    *(uint2*)(xb + idx) = make_uint2(lo, hi);
}

// ---------------- K0b: dual W [K][N] fp32 -> Wt [N][K] bf16 (z=2) --------
__global__ void wtrans2_kernel(const float* __restrict__ Wq, const float* __restrict__ Wk,
                               __nv_bfloat16* __restrict__ Wtq, __nv_bfloat16* __restrict__ Wtk) {
    const float* W = blockIdx.z ? Wk : Wq;
    __nv_bfloat16* Wt = blockIdx.z ? Wtk : Wtq;
    __shared__ float tile[32][33];
    int k0 = blockIdx.y * 32, n0 = blockIdx.x * 32;
    int x = threadIdx.x & 31, y = threadIdx.x >> 5;
#pragma unroll
    for (int r = 0; r < 4; r++)
        tile[y * 4 + r][x] = W[(size_t)(k0 + y * 4 + r) * DM + n0 + x];
    __syncthreads();
#pragma unroll
    for (int r = 0; r < 4; r++)
        Wt[(size_t)(n0 + y * 4 + r) * DM + k0 + x] = __float2bfloat16(tile[x][y * 4 + r]);
}

// ---------------- K1: dual projection GEMM bf16 mma (q and k, z=2) -------
__global__ __launch_bounds__(256) void proj2_gemm_bf16(
        const __nv_bfloat16* __restrict__ X,
        const __nv_bfloat16* __restrict__ Wtq,
        const __nv_bfloat16* __restrict__ Wtk,
        const float* __restrict__ bq,
        const float* __restrict__ bk,
        __nv_bfloat16* __restrict__ Cq,
        __nv_bfloat16* __restrict__ Ck) {
    const __nv_bfloat16* Wt = blockIdx.z ? Wtk : Wtq;
    const float* bias = blockIdx.z ? bk : bq;
    __nv_bfloat16* C = blockIdx.z ? Ck : Cq;
    __shared__ __align__(16) uint16_t Xs[64 * 72];
    __shared__ __align__(16) uint16_t Ws[64 * 72];
    int t = threadIdx.x, lane = t & 31, w = t >> 5;
    int m0 = blockIdx.y * 64, n0 = blockIdx.x * 64;
    int mblk = (w & 3) * 16, nhalf = (w >> 2) * 32;
    uint32_t Xb = sptr(Xs), Wb = sptr(Ws);
    float c[4][4] = {};

    for (int k0 = 0; k0 < DM; k0 += 64) {
        __syncthreads();
#pragma unroll
        for (int r = 0; r < 2; r++) {
            int f = r * 256 + t;
            int row = f >> 3, c8 = (f & 7) * 8;
            *(uint4*)&Xs[row * 72 + c8] = *(const uint4*)(X  + (size_t)(m0 + row) * DM + k0 + c8);
            *(uint4*)&Ws[row * 72 + c8] = *(const uint4*)(Wt + (size_t)(n0 + row) * DM + k0 + c8);
        }
        __syncthreads();
#pragma unroll
        for (int ks = 0; ks < 4; ks++) {
            uint32_t a0, a1, a2, a3;
            ldsm_x4(a0, a1, a2, a3, Xb + ((mblk + (lane & 15)) * 72 + ks * 16 + ((lane >> 4) << 3)) * 2);
#pragma unroll
            for (int nb = 0; nb < 2; nb++) {
                uint32_t b0, b1, b2, b3;
                int row = nhalf + nb * 16 + ((lane & 7) | ((lane >> 1) & 8));
                int col = ks * 16 + ((lane & 8) ? 8 : 0);
                ldsm_x4(b0, b1, b2, b3, Wb + (row * 72 + col) * 2);
                mma_bf16(c[nb*2][0], c[nb*2][1], c[nb*2][2], c[nb*2][3], a0, a1, a2, a3, b0, b1);
                mma_bf16(c[nb*2+1][0], c[nb*2+1][1], c[nb*2+1][2], c[nb*2+1][3], a0, a1, a2, a3, b2, b3);
            }
        }
    }
    int r = lane >> 2, cc = 2 * (lane & 3);
#pragma unroll
    for (int nb = 0; nb < 4; nb++) {
        int n = n0 + nhalf + nb * 8 + cc;
        float b0 = bias[n], b1 = bias[n + 1];
        float v0 = fmaxf(c[nb][0] + b0, 0.f), v1 = fmaxf(c[nb][1] + b1, 0.f);
        float v2 = fmaxf(c[nb][2] + b0, 0.f), v3 = fmaxf(c[nb][3] + b1, 0.f);
        *(uint32_t*)(C + (size_t)(m0 + mblk + r) * DM + n)     = pack_bf16x2(v0, v1);
        *(uint32_t*)(C + (size_t)(m0 + mblk + r + 8) * DM + n) = pack_bf16x2(v2, v3);
    }
}

// ---------------- split-bf16 fp32 GEMM, double-buffered + reg prefetch ---
// C[M,N] = A[M,K] @ B[K,N] (+ bias). Same math/order as before -> bit-stable.
#define FG_ARR  4608                     // 64*72 uint16 per array
#define FG_BUF  (4 * FG_ARR)             // Ahi,Alo,Bhi,Blo per buffer
#define FG_SMEM (2 * FG_BUF * 2)         // 73728 bytes
__global__ __launch_bounds__(256) void fgemm_split_kernel(
        const float* __restrict__ A, int lda, int aoffz,
        const float* __restrict__ B, int ldb, int boffz,
        float* __restrict__ C, int ldc, int coffz,
        int K, const float* __restrict__ bias) {
    extern __shared__ __align__(16) uint16_t fg[];
    int t = threadIdx.x, lane = t & 31, w = t >> 5;
    int m0 = blockIdx.y * 64, n0 = blockIdx.x * 64, z = blockIdx.z;
    A += (size_t)z * aoffz; B += (size_t)z * boffz; C += (size_t)z * coffz;
    int mblk = (w & 3) * 16, nhalf = (w >> 2) * 32;

    // prefetch tile 0 into registers
    float4 av[4], bv[4];
#pragma unroll
    for (int r = 0; r < 4; r++) {
        int f = r * 256 + t;
        int row = f >> 4, c4 = (f & 15) * 4;
        av[r] = *(const float4*)(A + (size_t)(m0 + row) * lda + c4);
        bv[r] = *(const float4*)(B + (size_t)row * ldb + n0 + c4);
    }

    float c[4][4] = {};
    const int nk = K >> 6;
    for (int ki = 0; ki < nk; ki++) {
        uint16_t* buf = fg + (ki & 1) * FG_BUF;
        uint32_t Ahb = sptr(buf);
        uint32_t Alb = Ahb + FG_ARR * 2;
        uint32_t Bhb = Alb + FG_ARR * 2;
        uint32_t Blb = Bhb + FG_ARR * 2;

        // store prefetched regs -> smem (split into hi/lo)
#pragma unroll
        for (int r = 0; r < 4; r++) {
            int f = r * 256 + t;
            int row = f >> 4, c4 = (f & 15) * 4;
            uint32_t h0, l0, h1, l1;
            split2(av[r].x, av[r].y, h0, l0);
            split2(av[r].z, av[r].w, h1, l1);
            *(uint2*)(buf + row * 72 + c4)              = make_uint2(h0, h1);
            *(uint2*)(buf + FG_ARR + row * 72 + c4)     = make_uint2(l0, l1);
            split2(bv[r].x, bv[r].y, h0, l0);
            split2(bv[r].z, bv[r].w, h1, l1);
            *(uint2*)(buf + 2 * FG_ARR + row * 72 + c4) = make_uint2(h0, h1);
            *(uint2*)(buf + 3 * FG_ARR + row * 72 + c4) = make_uint2(l0, l1);
        }
        __syncthreads();

        // prefetch next tile (overlaps the mma chain below)
        if (ki + 1 < nk) {
            int k0 = (ki + 1) << 6;
#pragma unroll
            for (int r = 0; r < 4; r++) {
                int f = r * 256 + t;
                int row = f >> 4, c4 = (f & 15) * 4;
                av[r] = *(const float4*)(A + (size_t)(m0 + row) * lda + k0 + c4);
                bv[r] = *(const float4*)(B + (size_t)(k0 + row) * ldb + n0 + c4);
            }
        }

#pragma unroll
        for (int ks = 0; ks < 4; ks++) {
            uint32_t aoff = ((mblk + (lane & 15)) * 72 + ks * 16 + ((lane >> 4) << 3)) * 2;
            uint32_t ah0, ah1, ah2, ah3, al0, al1, al2, al3;
            ldsm_x4(ah0, ah1, ah2, ah3, Ahb + aoff);
            ldsm_x4(al0, al1, al2, al3, Alb + aoff);
#pragma unroll
            for (int nb = 0; nb < 2; nb++) {
                uint32_t boff = ((ks * 16 + (lane & 15)) * 72 + nhalf + nb * 16 + ((lane >> 4) << 3)) * 2;
                uint32_t bh0, bh1, bh2, bh3, bl0, bl1, bl2, bl3;
                ldsm_x4_t(bh0, bh1, bh2, bh3, Bhb + boff);
                ldsm_x4_t(bl0, bl1, bl2, bl3, Blb + boff);
                float* cl = c[nb * 2];
                float* ch = c[nb * 2 + 1];
                mma_bf16(cl[0], cl[1], cl[2], cl[3], ah0, ah1, ah2, ah3, bh0, bh1);
                mma_bf16(cl[0], cl[1], cl[2], cl[3], ah0, ah1, ah2, ah3, bl0, bl1);
                mma_bf16(cl[0], cl[1], cl[2], cl[3], al0, al1, al2, al3, bh0, bh1);
                mma_bf16(ch[0], ch[1], ch[2], ch[3], ah0, ah1, ah2, ah3, bh2, bh3);
                mma_bf16(ch[0], ch[1], ch[2], ch[3], ah0, ah1, ah2, ah3, bl2, bl3);
                mma_bf16(ch[0], ch[1], ch[2], ch[3], al0, al1, al2, al3, bh2, bh3);
            }
        }
        // no trailing sync: next iteration writes the other buffer; the
        // next sync (after its store phase) orders buffer reuse at ki+2.
    }
    int r = lane >> 2, cc = 2 * (lane & 3);
#pragma unroll
    for (int nb = 0; nb < 4; nb++) {
        int n = n0 + nhalf + nb * 8 + cc;
        float b0 = bias ? bias[n] : 0.f;
        float b1 = bias ? bias[n + 1] : 0.f;
        *(float2*)(C + (size_t)(m0 + mblk + r) * ldc + n)     = make_float2(c[nb][0] + b0, c[nb][1] + b1);
        *(float2*)(C + (size_t)(m0 + mblk + r + 8) * ldc + n) = make_float2(c[nb][2] + b0, c[nb][3] + b1);
    }
}

// ---------------- K2: qk scores via bf16 mma ----------------
__global__ __launch_bounds__(256) void qk_mma_kernel(
        const __nv_bfloat16* __restrict__ Q, const __nv_bfloat16* __restrict__ K) {
    __shared__ __align__(16) uint16_t Qs[64 * 72];   // [i][e]
    __shared__ __align__(16) uint16_t Ks[64 * 72];   // [j][e]
    int h = blockIdx.z, i0 = blockIdx.y * 64, j0 = blockIdx.x * 64;
    int t = threadIdx.x, lane = t & 31, w = t >> 5;
    int iblk = (w & 3) * 16, jhalf = (w >> 2) * 32;
    uint32_t Qb = sptr(Qs), Kb = sptr(Ks);

#pragma unroll
    for (int r = 0; r < 2; r++) {
        int f = r * 256 + t;
        int row = f >> 3, c8 = (f & 7) * 8;
        *(uint4*)&Qs[row * 72 + c8] = *(const uint4*)(Q + (size_t)(i0 + row) * DM + h * DK + c8);
        *(uint4*)&Ks[row * 72 + c8] = *(const uint4*)(K + (size_t)(j0 + row) * DM + h * DK + c8);
    }
    __syncthreads();

    float c[4][4] = {};
#pragma unroll
    for (int ks = 0; ks < 4; ks++) {
        uint32_t a0, a1, a2, a3;
        ldsm_x4(a0, a1, a2, a3, Qb + ((iblk + (lane & 15)) * 72 + ks * 16 + ((lane >> 4) << 3)) * 2);
#pragma unroll
        for (int nb = 0; nb < 2; nb++) {
            uint32_t b0, b1, b2, b3;
            int row = jhalf + nb * 16 + ((lane & 7) | ((lane >> 1) & 8));
            int col = ks * 16 + ((lane & 8) ? 8 : 0);
            ldsm_x4(b0, b1, b2, b3, Kb + (row * 72 + col) * 2);
            mma_bf16(c[nb*2][0], c[nb*2][1], c[nb*2][2], c[nb*2][3], a0, a1, a2, a3, b0, b1);
            mma_bf16(c[nb*2+1][0], c[nb*2+1][1], c[nb*2+1][2], c[nb*2+1][3], a0, a1, a2, a3, b2, b3);
        }
    }
    int r = lane >> 2, cc = 2 * (lane & 3);
#pragma unroll
    for (int nb = 0; nb < 4; nb++) {
        int j = j0 + jhalf + nb * 8 + cc;
        *(float2*)(g_scores + (size_t)(i0 + iblk + r) * NH + h * N_TOK + j)     = make_float2(c[nb][0], c[nb][1]);
        *(float2*)(g_scores + (size_t)(i0 + iblk + r + 8) * NH + h * N_TOK + j) = make_float2(c[nb][2], c[nb][3]);
    }
}

// ---------------- K3: fused structure-scores + softmax -> p fp32 ---------
#define SS_SMEM 61824
__global__ __launch_bounds__(256, 3) void sscore_kernel(
        const float* __restrict__ S,
        const __nv_bfloat16* __restrict__ qb,
        const float* __restrict__ Wsk,
        const float* __restrict__ bsk) {
    extern __shared__ __align__(16) char dyn[];
    uint16_t* S_sh  = (uint16_t*)dyn;              // [128 j][72 c]
    uint16_t* W_sh  = (uint16_t*)(dyn + 18432);    // [64 e][72 c]
    uint16_t* q_sh  = (uint16_t*)(dyn + 27648);    // [8 h][72 e]
    float*    bsk_sh = (float*)(dyn + 28800);      // 64
    float*    p_sh  = (float*)(dyn + 29056);       // [8 h][1024 j]

    const int i    = blockIdx.x;
    const int t    = threadIdx.x;
    const int lane = t & 31;
    const int w    = t >> 5;

#pragma unroll
    for (int r = 0; r < 16; r++) {
        int f = r * 256 + t;
        int c = f >> 6, e = f & 63;
        __nv_bfloat16 b = __float2bfloat16(Wsk[f]);
        W_sh[e * 72 + c] = *(uint16_t*)&b;
    }
    if (t < 64) {
        int h = t >> 3, e8 = (t & 7) * 8;
        *(uint4*)&q_sh[h * 72 + e8] = *(const uint4*)(qb + (size_t)i * DM + h * DK + e8);
        bsk_sh[t] = bsk[t];
    }
    __syncthreads();

    const uint32_t Sbase = sptr(S_sh);
    const uint32_t Wbase = sptr(W_sh);
    const uint32_t qbase = sptr(q_sh);
    const uint32_t offA = ((w * 16 + (lane & 15)) * 72 + ((lane >> 4) << 3)) * 2;
    const uint32_t offB = ((lane & 7) * 72 + (((lane >> 3) & 1) << 3)) * 2;

    uint32_t qf[4][2];
#pragma unroll
    for (int ek = 0; ek < 4; ek++)
        ldsm_x2(qf[ek][0], qf[ek][1], qbase + offB + ek * 32);

    const int ecol = 2 * (lane & 3);
    const float* Srow = S + (size_t)i * N_TOK * 64;

    for (int j0 = 0; j0 < N_TOK; j0 += 128) {
        __syncthreads();
#pragma unroll
        for (int r = 0; r < 8; r++) {
            int f  = r * 256 + t;
            int jj = f >> 4;
            int c4 = (f & 15) * 4;
            float4 v = *(const float4*)(Srow + (size_t)(j0 + jj) * 64 + c4);
            uint32_t lo = pack_bf16x2(v.x, v.y);
            uint32_t hi = pack_bf16x2(v.z, v.w);
            *(uint2*)&S_sh[jj * 72 + c4] = make_uint2(lo, hi);
        }
        __syncthreads();

        uint32_t sa[4][4];
#pragma unroll
        for (int ck = 0; ck < 4; ck++)
            ldsm_x4(sa[ck][0], sa[ck][1], sa[ck][2], sa[ck][3], Sbase + offA + ck * 32);

        uint32_t skl[8], skh[8];
#pragma unroll
        for (int et = 0; et < 8; et++) {
            float c0 = 0.f, c1 = 0.f, c2 = 0.f, c3 = 0.f;
#pragma unroll
            for (int ck = 0; ck < 4; ck++) {
                uint32_t b0, b1;
                ldsm_x2(b0, b1, Wbase + offB + et * (8 * 72 * 2) + ck * 32);
                mma_bf16(c0, c1, c2, c3, sa[ck][0], sa[ck][1], sa[ck][2], sa[ck][3], b0, b1);
            }
            float blo = bsk_sh[et * 8 + ecol];
            float bhi = bsk_sh[et * 8 + ecol + 1];
            c0 = fmaxf(c0 + blo, 0.f); c1 = fmaxf(c1 + bhi, 0.f);
            c2 = fmaxf(c2 + blo, 0.f); c3 = fmaxf(c3 + bhi, 0.f);
            skl[et] = pack_bf16x2(c0, c1);
            skh[et] = pack_bf16x2(c2, c3);
        }

        float s0 = 0.f, s1 = 0.f, s2 = 0.f, s3 = 0.f;
#pragma unroll
        for (int ek = 0; ek < 4; ek++)
            mma_bf16(s0, s1, s2, s3,
                     skl[2*ek], skh[2*ek], skl[2*ek+1], skh[2*ek+1],
                     qf[ek][0], qf[ek][1]);

        int jw = j0 + w * 16 + (lane >> 2);
        int h0 = 2 * (lane & 3);
        p_sh[h0 * N_TOK + jw]           = s0;
        p_sh[(h0 + 1) * N_TOK + jw]     = s1;
        p_sh[h0 * N_TOK + jw + 8]       = s2;
        p_sh[(h0 + 1) * N_TOK + jw + 8] = s3;
    }
    __syncthreads();

    // softmax: warp w owns row h=w; p written back to g_scores (fp32)
    {
        float* row = p_sh + w * N_TOK;
        float* gsc = g_scores + (size_t)i * NH + w * N_TOK;
        float mx = -1e30f;
#pragma unroll
        for (int rr = 0; rr < 8; rr++) {
            int idx = rr * 128 + lane * 4;
            float4 g = *(const float4*)(gsc + idx);
            float4 p = *(float4*)(row + idx);
            p.x = (p.x + g.x) * SCALE; p.y = (p.y + g.y) * SCALE;
            p.z = (p.z + g.z) * SCALE; p.w = (p.w + g.w) * SCALE;
            *(float4*)(row + idx) = p;
            mx = fmaxf(mx, fmaxf(fmaxf(p.x, p.y), fmaxf(p.z, p.w)));
        }
#pragma unroll
        for (int o = 16; o; o >>= 1) mx = fmaxf(mx, __shfl_xor_sync(0xffffffffu, mx, o));
        float sum = 0.f;
#pragma unroll
        for (int rr = 0; rr < 8; rr++) {
            int idx = rr * 128 + lane * 4;
            float4 p = *(float4*)(row + idx);
            p.x = __expf(p.x - mx); p.y = __expf(p.y - mx);
            p.z = __expf(p.z - mx); p.w = __expf(p.w - mx);
            *(float4*)(row + idx) = p;
            sum += p.x + p.y + p.z + p.w;
        }
#pragma unroll
        for (int o = 16; o; o >>= 1) sum += __shfl_xor_sync(0xffffffffu, sum, o);
        float inv = 1.0f / sum;
#pragma unroll
        for (int rr = 0; rr < 8; rr++) {
            int idx = rr * 128 + lane * 4;
            float4 p = *(float4*)(row + idx);
            p.x *= inv; p.y *= inv; p.z *= inv; p.w *= inv;
            *(float4*)(gsc + idx) = p;
        }
    }
}

// ---------------- K5b: acc_t[i,h,e] = sum_j p[i,h,j] * S[i,j,e] ----------
__global__ __launch_bounds__(256) void acct_kernel(const float* __restrict__ S) {
    __shared__ float psh[8 * 1024];     // 32KB: all p for this i, then reused for reduce
    int i = blockIdx.x, t = threadIdx.x;
#pragma unroll
    for (int r = 0; r < 8; r++) {
        int f = (r * 256 + t) * 4;
        *(float4*)&psh[f] = *(const float4*)(g_scores + (size_t)i * NH + f);
    }
    __syncthreads();

    const int e4   = (t & 15) * 4;   // 4 consecutive e
    const int joff = t >> 4;         // 0..15
    float4 acc[8];
#pragma unroll
    for (int h = 0; h < 8; h++) acc[h] = make_float4(0.f, 0.f, 0.f, 0.f);

    const float* Sr = S + (size_t)i * N_TOK * 64;
#pragma unroll 4
    for (int j = joff; j < N_TOK; j += 16) {
        float4 s = *(const float4*)(Sr + (size_t)j * 64 + e4);
#pragma unroll
        for (int h = 0; h < 8; h++) {
            float p = psh[h * N_TOK + j];
            acc[h].x += p * s.x; acc[h].y += p * s.y;
            acc[h].z += p * s.z; acc[h].w += p * s.w;
        }
    }
    __syncthreads();   // done reading psh

#pragma unroll
    for (int h = 0; h < 8; h++)
        *(float4*)&psh[joff * 512 + h * 64 + e4] = acc[h];
    __syncthreads();

#pragma unroll
    for (int r = 0; r < 2; r++) {
        int o = r * 256 + t;   // h*64 + e
        float s = 0.f;
#pragma unroll
        for (int jo = 0; jo < 16; jo++) s += psh[jo * 512 + o];
        g_acct[(size_t)i * DM + o] = s;
    }
}

// ---------------- K6: out_pre = acc_v + acc_t @ Wsv + bsv ----------------
__global__ void combine_kernel(const float* __restrict__ Wsv, const float* __restrict__ bsv) {
    __shared__ float Wsh[64 * 64];
    __shared__ float tsh[8 * 64];
    int i = blockIdx.x;
    int t = threadIdx.x;
#pragma unroll
    for (int r = 0; r < 4; r++) {
        int f = r * 256 + t;
        *(float4*)&Wsh[f * 4] = *(const float4*)(Wsv + f * 4);
    }
    if (t < 128) *(float4*)&tsh[t * 4] = *(const float4*)(g_acct + (size_t)i * DM + t * 4);
    __syncthreads();
    int d  = t % 64;
    int h0 = t / 64;
    float bd = bsv[d];
#pragma unroll
    for (int r = 0; r < 2; r++) {
        int h = h0 + r * 4;
        float a = 0.f;
#pragma unroll 16
        for (int e = 0; e < 64; e++) a += tsh[h * 64 + e] * Wsh[e * 64 + d];
        g_outpre[(size_t)i * DM + h * DK + d] =
            g_accv[(size_t)i * DM + h * DK + d] + a + bd;
    }
}

// ---------------- launch ----------------
extern "C" void kernel_launch(void* const* d_in, const int* in_sizes, int n_in,
                              void* d_out, int out_size) {
    const float* x   = (const float*)d_in[0];
    const float* S   = (const float*)d_in[1];
    const float* Wq  = (const float*)d_in[2];  const float* bq  = (const float*)d_in[3];
    const float* Wk  = (const float*)d_in[4];  const float* bk  = (const float*)d_in[5];
    const float* Wv  = (const float*)d_in[6];  const float* bv  = (const float*)d_in[7];
    const float* Wo  = (const float*)d_in[8];  const float* bo  = (const float*)d_in[9];
    const float* Wsk = (const float*)d_in[10]; const float* bsk = (const float*)d_in[11];
    const float* Wsv = (const float*)d_in[12]; const float* bsv = (const float*)d_in[13];
    float* out = (float*)d_out;

    void *pxb, *pwt, *pwt2, *pqb, *pkb, *pv, *pop, *psc, *pav;
    cudaGetSymbolAddress(&pxb, g_xb);
    cudaGetSymbolAddress(&pwt, g_wt);
    cudaGetSymbolAddress(&pwt2, g_wt2);
    cudaGetSymbolAddress(&pqb, g_qb);
    cudaGetSymbolAddress(&pkb, g_kb);
    cudaGetSymbolAddress(&pv,  g_v);
    cudaGetSymbolAddress(&pop, g_outpre);
    cudaGetSymbolAddress(&psc, g_scores);
    cudaGetSymbolAddress(&pav, g_accv);
    __nv_bfloat16* xb  = (__nv_bfloat16*)pxb;
    __nv_bfloat16* wt  = (__nv_bfloat16*)pwt;
    __nv_bfloat16* wt2 = (__nv_bfloat16*)pwt2;

    cudaFuncSetAttribute(sscore_kernel, cudaFuncAttributeMaxDynamicSharedMemorySize, SS_SMEM);
    cudaFuncSetAttribute(fgemm_split_kernel, cudaFuncAttributeMaxDynamicSharedMemorySize, FG_SMEM);

    // x -> bf16 (logit path only)
    xconv_kernel<<<N_TOK * DM / 1024, 256>>>(x, xb);

    // q/k weight transposes and projections, merged into z=2 launches
    wtrans2_kernel<<<dim3(16, 16, 2), 256>>>(Wq, Wk, wt, wt2);
    proj2_gemm_bf16<<<dim3(DM / 64, N_TOK / 64, 2), 256>>>(
        xb, wt, wt2, bq, bk, (__nv_bfloat16*)pqb, (__nv_bfloat16*)pkb);

    // v projection: split-bf16 tensor-core GEMM (near-fp32 exact, pipelined)
    fgemm_split_kernel<<<dim3(DM / 64, N_TOK / 64), 256, FG_SMEM>>>(
        x, DM, 0, Wv, DM, 0, (float*)pv, DM, 0, DM, bv);

    // qk scores (bf16 mma, fp32 out)
    qk_mma_kernel<<<dim3(16, 16, 8), 256>>>((const __nv_bfloat16*)pqb, (const __nv_bfloat16*)pkb);

    // structure scores + softmax -> p fp32 (in place in g_scores)
    sscore_kernel<<<N_TOK, 256, SS_SMEM>>>(S, (const __nv_bfloat16*)pqb, Wsk, bsk);

    // acc_v = p @ v : split-bf16 GEMM, one z-slab per head
    fgemm_split_kernel<<<dim3(1, 16, 8), 256, FG_SMEM>>>(
        (const float*)psc, NH, N_TOK,
        (const float*)pv,  DM, DK,
        (float*)pav,       DM, DK,
        N_TOK, nullptr);

    // acc_t = p @ S (register streamer, fp32 exact)
    acct_kernel<<<N_TOK, 256>>>(S);

    combine_kernel<<<N_TOK, 256>>>(Wsv, bsv);

    // final output projection: split-bf16 GEMM (pipelined)
    fgemm_split_kernel<<<dim3(DM / 64, N_TOK / 64), 256, FG_SMEM>>>(
        (const float*)pop, DM, 0, Wo, DM, 0, out, DM, 0, DM, bo);
}

// round 15
// speedup vs baseline: 3.6182x; 1.0555x over previous
#include <cuda_runtime.h>
#include <cuda_bf16.h>
#include <math.h>
#include <stdint.h>

#define N_TOK 1024
#define DM    512
#define H     8
#define DK    64
#define NH    8192          // N_TOK * H
#define SCALE 0.125f        // 1/sqrt(64)

// ---------------- scratch (device globals; no allocation) ----------------
__device__ __nv_bfloat16 g_xb[N_TOK * DM];            // x in bf16
__device__ __nv_bfloat16 g_wt[DM * DM];               // transposed Wq bf16 [n][k]
__device__ __nv_bfloat16 g_wt2[DM * DM];              // transposed Wk bf16 [n][k]
__device__ __nv_bfloat16 g_qb[N_TOK * DM];            // relu(q) bf16 (logit path only)
__device__ __nv_bfloat16 g_kb[N_TOK * DM];            // relu(k) bf16 (logit path only)
__device__ float g_v[N_TOK * DM];                     // v fp32 (output path, near-exact)
__device__ float g_scores[(size_t)N_TOK * H * N_TOK]; // qk scores -> then p (fp32, in place)
__device__ float g_accv[N_TOK * DM];
__device__ float g_outpre[N_TOK * DM];

// ---------------- asm helpers ----------------
__device__ __forceinline__ uint32_t sptr(const void* p) {
    uint32_t r;
    asm("{ .reg .u64 t; cvta.to.shared.u64 t, %1; cvt.u32.u64 %0, t; }" : "=r"(r) : "l"(p));
    return r;
}
__device__ __forceinline__ void ldsm_x4(uint32_t& a0, uint32_t& a1, uint32_t& a2, uint32_t& a3, uint32_t addr) {
    asm volatile("ldmatrix.sync.aligned.m8n8.x4.shared.b16 {%0,%1,%2,%3}, [%4];"
                 : "=r"(a0), "=r"(a1), "=r"(a2), "=r"(a3) : "r"(addr));
}
__device__ __forceinline__ void ldsm_x4_t(uint32_t& a0, uint32_t& a1, uint32_t& a2, uint32_t& a3, uint32_t addr) {
    asm volatile("ldmatrix.sync.aligned.m8n8.x4.trans.shared.b16 {%0,%1,%2,%3}, [%4];"
                 : "=r"(a0), "=r"(a1), "=r"(a2), "=r"(a3) : "r"(addr));
}
__device__ __forceinline__ void ldsm_x2(uint32_t& b0, uint32_t& b1, uint32_t addr) {
    asm volatile("ldmatrix.sync.aligned.m8n8.x2.shared.b16 {%0,%1}, [%2];"
                 : "=r"(b0), "=r"(b1) : "r"(addr));
}
__device__ __forceinline__ void mma_bf16(float& c0, float& c1, float& c2, float& c3,
                                         uint32_t a0, uint32_t a1, uint32_t a2, uint32_t a3,
                                         uint32_t b0, uint32_t b1) {
    asm volatile("mma.sync.aligned.m16n8k16.row.col.f32.bf16.bf16.f32 "
                 "{%0,%1,%2,%3}, {%4,%5,%6,%7}, {%8,%9}, {%0,%1,%2,%3};"
                 : "+f"(c0), "+f"(c1), "+f"(c2), "+f"(c3)
                 : "r"(a0), "r"(a1), "r"(a2), "r"(a3), "r"(b0), "r"(b1));
}
__device__ __forceinline__ uint32_t pack_bf16x2(float lo, float hi) {
    uint32_t p;
    asm("cvt.rn.bf16x2.f32 %0, %1, %2;" : "=r"(p) : "f"(hi), "f"(lo));
    return p;
}
// split fp32 pair -> (hi bf16x2, lo bf16x2)
__device__ __forceinline__ void split2(float a, float b, uint32_t& hi, uint32_t& lo) {
    __nv_bfloat16 ha = __float2bfloat16(a), hb = __float2bfloat16(b);
    float ra = a - __bfloat162float(ha);
    float rb = b - __bfloat162float(hb);
    hi = pack_bf16x2(__bfloat162float(ha), __bfloat162float(hb));
    lo = pack_bf16x2(ra, rb);
}

// ---------------- K0a: x -> bf16 ----------------
__global__ void xconv_kernel(const float* __restrict__ x, __nv_bfloat16* __restrict__ xb) {
    int idx = (blockIdx.x * 256 + threadIdx.x) * 4;
    float4 v = *(const float4*)(x + idx);
    uint32_t lo = pack_bf16x2(v.x, v.y);
    uint32_t hi = pack_bf16x2(v.z, v.w);
    *(uint2*)(xb + idx) = make_uint2(lo, hi);
}

// ---------------- K0b: dual W [K][N] fp32 -> Wt [N][K] bf16 (z=2) --------
__global__ void wtrans2_kernel(const float* __restrict__ Wq, const float* __restrict__ Wk,
                               __nv_bfloat16* __restrict__ Wtq, __nv_bfloat16* __restrict__ Wtk) {
    const float* W = blockIdx.z ? Wk : Wq;
    __nv_bfloat16* Wt = blockIdx.z ? Wtk : Wtq;
    __shared__ float tile[32][33];
    int k0 = blockIdx.y * 32, n0 = blockIdx.x * 32;
    int x = threadIdx.x & 31, y = threadIdx.x >> 5;
#pragma unroll
    for (int r = 0; r < 4; r++)
        tile[y * 4 + r][x] = W[(size_t)(k0 + y * 4 + r) * DM + n0 + x];
    __syncthreads();
#pragma unroll
    for (int r = 0; r < 4; r++)
        Wt[(size_t)(n0 + y * 4 + r) * DM + k0 + x] = __float2bfloat16(tile[x][y * 4 + r]);
}

// ---------------- K1: dual projection GEMM bf16 mma (q and k, z=2) -------
__global__ __launch_bounds__(256) void proj2_gemm_bf16(
        const __nv_bfloat16* __restrict__ X,
        const __nv_bfloat16* __restrict__ Wtq,
        const __nv_bfloat16* __restrict__ Wtk,
        const float* __restrict__ bq,
        const float* __restrict__ bk,
        __nv_bfloat16* __restrict__ Cq,
        __nv_bfloat16* __restrict__ Ck) {
    const __nv_bfloat16* Wt = blockIdx.z ? Wtk : Wtq;
    const float* bias = blockIdx.z ? bk : bq;
    __nv_bfloat16* C = blockIdx.z ? Ck : Cq;
    __shared__ __align__(16) uint16_t Xs[64 * 72];
    __shared__ __align__(16) uint16_t Ws[64 * 72];
    int t = threadIdx.x, lane = t & 31, w = t >> 5;
    int m0 = blockIdx.y * 64, n0 = blockIdx.x * 64;
    int mblk = (w & 3) * 16, nhalf = (w >> 2) * 32;
    uint32_t Xb = sptr(Xs), Wb = sptr(Ws);
    float c[4][4] = {};

    for (int k0 = 0; k0 < DM; k0 += 64) {
        __syncthreads();
#pragma unroll
        for (int r = 0; r < 2; r++) {
            int f = r * 256 + t;
            int row = f >> 3, c8 = (f & 7) * 8;
            *(uint4*)&Xs[row * 72 + c8] = *(const uint4*)(X  + (size_t)(m0 + row) * DM + k0 + c8);
            *(uint4*)&Ws[row * 72 + c8] = *(const uint4*)(Wt + (size_t)(n0 + row) * DM + k0 + c8);
        }
        __syncthreads();
#pragma unroll
        for (int ks = 0; ks < 4; ks++) {
            uint32_t a0, a1, a2, a3;
            ldsm_x4(a0, a1, a2, a3, Xb + ((mblk + (lane & 15)) * 72 + ks * 16 + ((lane >> 4) << 3)) * 2);
#pragma unroll
            for (int nb = 0; nb < 2; nb++) {
                uint32_t b0, b1, b2, b3;
                int row = nhalf + nb * 16 + ((lane & 7) | ((lane >> 1) & 8));
                int col = ks * 16 + ((lane & 8) ? 8 : 0);
                ldsm_x4(b0, b1, b2, b3, Wb + (row * 72 + col) * 2);
                mma_bf16(c[nb*2][0], c[nb*2][1], c[nb*2][2], c[nb*2][3], a0, a1, a2, a3, b0, b1);
                mma_bf16(c[nb*2+1][0], c[nb*2+1][1], c[nb*2+1][2], c[nb*2+1][3], a0, a1, a2, a3, b2, b3);
            }
        }
    }
    int r = lane >> 2, cc = 2 * (lane & 3);
#pragma unroll
    for (int nb = 0; nb < 4; nb++) {
        int n = n0 + nhalf + nb * 8 + cc;
        float b0 = bias[n], b1 = bias[n + 1];
        float v0 = fmaxf(c[nb][0] + b0, 0.f), v1 = fmaxf(c[nb][1] + b1, 0.f);
        float v2 = fmaxf(c[nb][2] + b0, 0.f), v3 = fmaxf(c[nb][3] + b1, 0.f);
        *(uint32_t*)(C + (size_t)(m0 + mblk + r) * DM + n)     = pack_bf16x2(v0, v1);
        *(uint32_t*)(C + (size_t)(m0 + mblk + r + 8) * DM + n) = pack_bf16x2(v2, v3);
    }
}

// ---------------- split-bf16 fp32 GEMM, double-buffered + reg prefetch ---
#define FG_ARR  4608                     // 64*72 uint16 per array
#define FG_BUF  (4 * FG_ARR)             // Ahi,Alo,Bhi,Blo per buffer
#define FG_SMEM (2 * FG_BUF * 2)         // 73728 bytes
__global__ __launch_bounds__(256) void fgemm_split_kernel(
        const float* __restrict__ A, int lda, int aoffz,
        const float* __restrict__ B, int ldb, int boffz,
        float* __restrict__ C, int ldc, int coffz,
        int K, const float* __restrict__ bias) {
    extern __shared__ __align__(16) uint16_t fg[];
    int t = threadIdx.x, lane = t & 31, w = t >> 5;
    int m0 = blockIdx.y * 64, n0 = blockIdx.x * 64, z = blockIdx.z;
    A += (size_t)z * aoffz; B += (size_t)z * boffz; C += (size_t)z * coffz;
    int mblk = (w & 3) * 16, nhalf = (w >> 2) * 32;

    float4 av[4], bv[4];
#pragma unroll
    for (int r = 0; r < 4; r++) {
        int f = r * 256 + t;
        int row = f >> 4, c4 = (f & 15) * 4;
        av[r] = *(const float4*)(A + (size_t)(m0 + row) * lda + c4);
        bv[r] = *(const float4*)(B + (size_t)row * ldb + n0 + c4);
    }

    float c[4][4] = {};
    const int nk = K >> 6;
    for (int ki = 0; ki < nk; ki++) {
        uint16_t* buf = fg + (ki & 1) * FG_BUF;
        uint32_t Ahb = sptr(buf);
        uint32_t Alb = Ahb + FG_ARR * 2;
        uint32_t Bhb = Alb + FG_ARR * 2;
        uint32_t Blb = Bhb + FG_ARR * 2;

#pragma unroll
        for (int r = 0; r < 4; r++) {
            int f = r * 256 + t;
            int row = f >> 4, c4 = (f & 15) * 4;
            uint32_t h0, l0, h1, l1;
            split2(av[r].x, av[r].y, h0, l0);
            split2(av[r].z, av[r].w, h1, l1);
            *(uint2*)(buf + row * 72 + c4)              = make_uint2(h0, h1);
            *(uint2*)(buf + FG_ARR + row * 72 + c4)     = make_uint2(l0, l1);
            split2(bv[r].x, bv[r].y, h0, l0);
            split2(bv[r].z, bv[r].w, h1, l1);
            *(uint2*)(buf + 2 * FG_ARR + row * 72 + c4) = make_uint2(h0, h1);
            *(uint2*)(buf + 3 * FG_ARR + row * 72 + c4) = make_uint2(l0, l1);
        }
        __syncthreads();

        if (ki + 1 < nk) {
            int k0 = (ki + 1) << 6;
#pragma unroll
            for (int r = 0; r < 4; r++) {
                int f = r * 256 + t;
                int row = f >> 4, c4 = (f & 15) * 4;
                av[r] = *(const float4*)(A + (size_t)(m0 + row) * lda + k0 + c4);
                bv[r] = *(const float4*)(B + (size_t)(k0 + row) * ldb + n0 + c4);
            }
        }

#pragma unroll
        for (int ks = 0; ks < 4; ks++) {
            uint32_t aoff = ((mblk + (lane & 15)) * 72 + ks * 16 + ((lane >> 4) << 3)) * 2;
            uint32_t ah0, ah1, ah2, ah3, al0, al1, al2, al3;
            ldsm_x4(ah0, ah1, ah2, ah3, Ahb + aoff);
            ldsm_x4(al0, al1, al2, al3, Alb + aoff);
#pragma unroll
            for (int nb = 0; nb < 2; nb++) {
                uint32_t boff = ((ks * 16 + (lane & 15)) * 72 + nhalf + nb * 16 + ((lane >> 4) << 3)) * 2;
                uint32_t bh0, bh1, bh2, bh3, bl0, bl1, bl2, bl3;
                ldsm_x4_t(bh0, bh1, bh2, bh3, Bhb + boff);
                ldsm_x4_t(bl0, bl1, bl2, bl3, Blb + boff);
                float* cl = c[nb * 2];
                float* ch = c[nb * 2 + 1];
                mma_bf16(cl[0], cl[1], cl[2], cl[3], ah0, ah1, ah2, ah3, bh0, bh1);
                mma_bf16(cl[0], cl[1], cl[2], cl[3], ah0, ah1, ah2, ah3, bl0, bl1);
                mma_bf16(cl[0], cl[1], cl[2], cl[3], al0, al1, al2, al3, bh0, bh1);
                mma_bf16(ch[0], ch[1], ch[2], ch[3], ah0, ah1, ah2, ah3, bh2, bh3);
                mma_bf16(ch[0], ch[1], ch[2], ch[3], ah0, ah1, ah2, ah3, bl2, bl3);
                mma_bf16(ch[0], ch[1], ch[2], ch[3], al0, al1, al2, al3, bh2, bh3);
            }
        }
    }
    int r = lane >> 2, cc = 2 * (lane & 3);
#pragma unroll
    for (int nb = 0; nb < 4; nb++) {
        int n = n0 + nhalf + nb * 8 + cc;
        float b0 = bias ? bias[n] : 0.f;
        float b1 = bias ? bias[n + 1] : 0.f;
        *(float2*)(C + (size_t)(m0 + mblk + r) * ldc + n)     = make_float2(c[nb][0] + b0, c[nb][1] + b1);
        *(float2*)(C + (size_t)(m0 + mblk + r + 8) * ldc + n) = make_float2(c[nb][2] + b0, c[nb][3] + b1);
    }
}

// ---------------- K2: qk scores via bf16 mma ----------------
__global__ __launch_bounds__(256) void qk_mma_kernel(
        const __nv_bfloat16* __restrict__ Q, const __nv_bfloat16* __restrict__ K) {
    __shared__ __align__(16) uint16_t Qs[64 * 72];   // [i][e]
    __shared__ __align__(16) uint16_t Ks[64 * 72];   // [j][e]
    int h = blockIdx.z, i0 = blockIdx.y * 64, j0 = blockIdx.x * 64;
    int t = threadIdx.x, lane = t & 31, w = t >> 5;
    int iblk = (w & 3) * 16, jhalf = (w >> 2) * 32;
    uint32_t Qb = sptr(Qs), Kb = sptr(Ks);

#pragma unroll
    for (int r = 0; r < 2; r++) {
        int f = r * 256 + t;
        int row = f >> 3, c8 = (f & 7) * 8;
        *(uint4*)&Qs[row * 72 + c8] = *(const uint4*)(Q + (size_t)(i0 + row) * DM + h * DK + c8);
        *(uint4*)&Ks[row * 72 + c8] = *(const uint4*)(K + (size_t)(j0 + row) * DM + h * DK + c8);
    }
    __syncthreads();

    float c[4][4] = {};
#pragma unroll
    for (int ks = 0; ks < 4; ks++) {
        uint32_t a0, a1, a2, a3;
        ldsm_x4(a0, a1, a2, a3, Qb + ((iblk + (lane & 15)) * 72 + ks * 16 + ((lane >> 4) << 3)) * 2);
#pragma unroll
        for (int nb = 0; nb < 2; nb++) {
            uint32_t b0, b1, b2, b3;
            int row = jhalf + nb * 16 + ((lane & 7) | ((lane >> 1) & 8));
            int col = ks * 16 + ((lane & 8) ? 8 : 0);
            ldsm_x4(b0, b1, b2, b3, Kb + (row * 72 + col) * 2);
            mma_bf16(c[nb*2][0], c[nb*2][1], c[nb*2][2], c[nb*2][3], a0, a1, a2, a3, b0, b1);
            mma_bf16(c[nb*2+1][0], c[nb*2+1][1], c[nb*2+1][2], c[nb*2+1][3], a0, a1, a2, a3, b2, b3);
        }
    }
    int r = lane >> 2, cc = 2 * (lane & 3);
#pragma unroll
    for (int nb = 0; nb < 4; nb++) {
        int j = j0 + jhalf + nb * 8 + cc;
        *(float2*)(g_scores + (size_t)(i0 + iblk + r) * NH + h * N_TOK + j)     = make_float2(c[nb][0], c[nb][1]);
        *(float2*)(g_scores + (size_t)(i0 + iblk + r + 8) * NH + h * N_TOK + j) = make_float2(c[nb][2], c[nb][3]);
    }
}

// ---------------- K3: fused structure-scores + softmax -> p fp32 ---------
// Register-prefetched S tiles (pipelined like fgemm); p in place in g_scores.
#define SS_SMEM 61824
__global__ __launch_bounds__(256, 2) void sscore_kernel(
        const float* __restrict__ S,
        const __nv_bfloat16* __restrict__ qb,
        const float* __restrict__ Wsk,
        const float* __restrict__ bsk) {
    extern __shared__ __align__(16) char dyn[];
    uint16_t* S_sh  = (uint16_t*)dyn;              // [128 j][72 c]
    uint16_t* W_sh  = (uint16_t*)(dyn + 18432);    // [64 e][72 c]
    uint16_t* q_sh  = (uint16_t*)(dyn + 27648);    // [8 h][72 e]
    float*    bsk_sh = (float*)(dyn + 28800);      // 64
    float*    p_sh  = (float*)(dyn + 29056);       // [8 h][1024 j]

    const int i    = blockIdx.x;
    const int t    = threadIdx.x;
    const int lane = t & 31;
    const int w    = t >> 5;

#pragma unroll
    for (int r = 0; r < 16; r++) {
        int f = r * 256 + t;
        int c = f >> 6, e = f & 63;
        __nv_bfloat16 b = __float2bfloat16(Wsk[f]);
        W_sh[e * 72 + c] = *(uint16_t*)&b;
    }
    if (t < 64) {
        int h = t >> 3, e8 = (t & 7) * 8;
        *(uint4*)&q_sh[h * 72 + e8] = *(const uint4*)(qb + (size_t)i * DM + h * DK + e8);
        bsk_sh[t] = bsk[t];
    }
    __syncthreads();

    const uint32_t Sbase = sptr(S_sh);
    const uint32_t Wbase = sptr(W_sh);
    const uint32_t qbase = sptr(q_sh);
    const uint32_t offA = ((w * 16 + (lane & 15)) * 72 + ((lane >> 4) << 3)) * 2;
    const uint32_t offB = ((lane & 7) * 72 + (((lane >> 3) & 1) << 3)) * 2;

    uint32_t qf[4][2];
#pragma unroll
    for (int ek = 0; ek < 4; ek++)
        ldsm_x2(qf[ek][0], qf[ek][1], qbase + offB + ek * 32);

    const int ecol = 2 * (lane & 3);
    const float* Srow = S + (size_t)i * N_TOK * 64;
    const int prow = t >> 4;            // S-tile load: row within group of 16
    const int pc4  = (t & 15) * 4;      // 4 consecutive c

    // prefetch S tile 0 into registers
    float4 pf[8];
#pragma unroll
    for (int r = 0; r < 8; r++)
        pf[r] = *(const float4*)(Srow + (size_t)(r * 16 + prow) * 64 + pc4);

    for (int j0 = 0; j0 < N_TOK; j0 += 128) {
        __syncthreads();   // previous tile's mma readers done with S_sh
        // store prefetched tile -> bf16 smem
#pragma unroll
        for (int r = 0; r < 8; r++) {
            int jj = r * 16 + prow;
            uint32_t lo = pack_bf16x2(pf[r].x, pf[r].y);
            uint32_t hi = pack_bf16x2(pf[r].z, pf[r].w);
            *(uint2*)&S_sh[jj * 72 + pc4] = make_uint2(lo, hi);
        }
        __syncthreads();

        // prefetch next tile (overlaps mma chain below)
        if (j0 + 128 < N_TOK) {
            const float* Snext = Srow + (size_t)(j0 + 128) * 64;
#pragma unroll
            for (int r = 0; r < 8; r++)
                pf[r] = *(const float4*)(Snext + (size_t)(r * 16 + prow) * 64 + pc4);
        }

        uint32_t sa[4][4];
#pragma unroll
        for (int ck = 0; ck < 4; ck++)
            ldsm_x4(sa[ck][0], sa[ck][1], sa[ck][2], sa[ck][3], Sbase + offA + ck * 32);

        uint32_t skl[8], skh[8];
#pragma unroll
        for (int et = 0; et < 8; et++) {
            float c0 = 0.f, c1 = 0.f, c2 = 0.f, c3 = 0.f;
#pragma unroll
            for (int ck = 0; ck < 4; ck++) {
                uint32_t b0, b1;
                ldsm_x2(b0, b1, Wbase + offB + et * (8 * 72 * 2) + ck * 32);
                mma_bf16(c0, c1, c2, c3, sa[ck][0], sa[ck][1], sa[ck][2], sa[ck][3], b0, b1);
            }
            float blo = bsk_sh[et * 8 + ecol];
            float bhi = bsk_sh[et * 8 + ecol + 1];
            c0 = fmaxf(c0 + blo, 0.f); c1 = fmaxf(c1 + bhi, 0.f);
            c2 = fmaxf(c2 + blo, 0.f); c3 = fmaxf(c3 + bhi, 0.f);
            skl[et] = pack_bf16x2(c0, c1);
            skh[et] = pack_bf16x2(c2, c3);
        }

        float s0 = 0.f, s1 = 0.f, s2 = 0.f, s3 = 0.f;
#pragma unroll
        for (int ek = 0; ek < 4; ek++)
            mma_bf16(s0, s1, s2, s3,
                     skl[2*ek], skh[2*ek], skl[2*ek+1], skh[2*ek+1],
                     qf[ek][0], qf[ek][1]);

        int jw = j0 + w * 16 + (lane >> 2);
        int h0 = 2 * (lane & 3);
        p_sh[h0 * N_TOK + jw]           = s0;
        p_sh[(h0 + 1) * N_TOK + jw]     = s1;
        p_sh[h0 * N_TOK + jw + 8]       = s2;
        p_sh[(h0 + 1) * N_TOK + jw + 8] = s3;
    }
    __syncthreads();

    // softmax: warp w owns row h=w; p written back to g_scores (fp32)
    {
        float* row = p_sh + w * N_TOK;
        float* gsc = g_scores + (size_t)i * NH + w * N_TOK;
        float mx = -1e30f;
#pragma unroll
        for (int rr = 0; rr < 8; rr++) {
            int idx = rr * 128 + lane * 4;
            float4 g = *(const float4*)(gsc + idx);
            float4 p = *(float4*)(row + idx);
            p.x = (p.x + g.x) * SCALE; p.y = (p.y + g.y) * SCALE;
            p.z = (p.z + g.z) * SCALE; p.w = (p.w + g.w) * SCALE;
            *(float4*)(row + idx) = p;
            mx = fmaxf(mx, fmaxf(fmaxf(p.x, p.y), fmaxf(p.z, p.w)));
        }
#pragma unroll
        for (int o = 16; o; o >>= 1) mx = fmaxf(mx, __shfl_xor_sync(0xffffffffu, mx, o));
        float sum = 0.f;
#pragma unroll
        for (int rr = 0; rr < 8; rr++) {
            int idx = rr * 128 + lane * 4;
            float4 p = *(float4*)(row + idx);
            p.x = __expf(p.x - mx); p.y = __expf(p.y - mx);
            p.z = __expf(p.z - mx); p.w = __expf(p.w - mx);
            *(float4*)(row + idx) = p;
            sum += p.x + p.y + p.z + p.w;
        }
#pragma unroll
        for (int o = 16; o; o >>= 1) sum += __shfl_xor_sync(0xffffffffu, sum, o);
        float inv = 1.0f / sum;
#pragma unroll
        for (int rr = 0; rr < 8; rr++) {
            int idx = rr * 128 + lane * 4;
            float4 p = *(float4*)(row + idx);
            p.x *= inv; p.y *= inv; p.z *= inv; p.w *= inv;
            *(float4*)(gsc + idx) = p;
        }
    }
}

// ---------------- K5b fused: out_pre = accv + (p@S) @ Wsv + bsv ----------
// acct streamer + combine epilogue in one kernel (same FP order as before).
__global__ __launch_bounds__(256) void acct_combine_kernel(
        const float* __restrict__ S,
        const float* __restrict__ Wsv,
        const float* __restrict__ bsv) {
    __shared__ float psh[8 * 1024];     // 32KB: p, then partials, then Wsv
    __shared__ float tsh[512];          // acc_t[h][e]
    int i = blockIdx.x, t = threadIdx.x;
#pragma unroll
    for (int r = 0; r < 8; r++) {
        int f = (r * 256 + t) * 4;
        *(float4*)&psh[f] = *(const float4*)(g_scores + (size_t)i * NH + f);
    }
    __syncthreads();

    const int e4   = (t & 15) * 4;
    const int joff = t >> 4;
    float4 acc[8];
#pragma unroll
    for (int h = 0; h < 8; h++) acc[h] = make_float4(0.f, 0.f, 0.f, 0.f);

    const float* Sr = S + (size_t)i * N_TOK * 64;
#pragma unroll 4
    for (int j = joff; j < N_TOK; j += 16) {
        float4 s = *(const float4*)(Sr + (size_t)j * 64 + e4);
#pragma unroll
        for (int h = 0; h < 8; h++) {
            float p = psh[h * N_TOK + j];
            acc[h].x += p * s.x; acc[h].y += p * s.y;
            acc[h].z += p * s.z; acc[h].w += p * s.w;
        }
    }
    __syncthreads();   // done reading psh (p)

#pragma unroll
    for (int h = 0; h < 8; h++)
        *(float4*)&psh[joff * 512 + h * 64 + e4] = acc[h];
    __syncthreads();

#pragma unroll
    for (int r = 0; r < 2; r++) {
        int o = r * 256 + t;   // h*64 + e
        float s = 0.f;
#pragma unroll
        for (int jo = 0; jo < 16; jo++) s += psh[jo * 512 + o];
        tsh[o] = s;
    }
    __syncthreads();   // tsh ready; partials no longer needed

    // load Wsv [e][d] 64x64 fp32 into psh (reuse)
#pragma unroll
    for (int r = 0; r < 4; r++) {
        int f = r * 256 + t;
        *(float4*)&psh[f * 4] = *(const float4*)(Wsv + f * 4);
    }
    __syncthreads();

    // combine epilogue (same loop order as the old combine_kernel)
    int d  = t & 63;
    int h0 = t >> 6;
    float bd = bsv[d];
#pragma unroll
    for (int r = 0; r < 2; r++) {
        int h = h0 + r * 4;
        float a = 0.f;
#pragma unroll 16
        for (int e = 0; e < 64; e++) a += tsh[h * 64 + e] * psh[e * 64 + d];
        g_outpre[(size_t)i * DM + h * DK + d] =
            g_accv[(size_t)i * DM + h * DK + d] + a + bd;
    }
}

// ---------------- launch ----------------
extern "C" void kernel_launch(void* const* d_in, const int* in_sizes, int n_in,
                              void* d_out, int out_size) {
    const float* x   = (const float*)d_in[0];
    const float* S   = (const float*)d_in[1];
    const float* Wq  = (const float*)d_in[2];  const float* bq  = (const float*)d_in[3];
    const float* Wk  = (const float*)d_in[4];  const float* bk  = (const float*)d_in[5];
    const float* Wv  = (const float*)d_in[6];  const float* bv  = (const float*)d_in[7];
    const float* Wo  = (const float*)d_in[8];  const float* bo  = (const float*)d_in[9];
    const float* Wsk = (const float*)d_in[10]; const float* bsk = (const float*)d_in[11];
    const float* Wsv = (const float*)d_in[12]; const float* bsv = (const float*)d_in[13];
    float* out = (float*)d_out;

    void *pxb, *pwt, *pwt2, *pqb, *pkb, *pv, *pop, *psc, *pav;
    cudaGetSymbolAddress(&pxb, g_xb);
    cudaGetSymbolAddress(&pwt, g_wt);
    cudaGetSymbolAddress(&pwt2, g_wt2);
    cudaGetSymbolAddress(&pqb, g_qb);
    cudaGetSymbolAddress(&pkb, g_kb);
    cudaGetSymbolAddress(&pv,  g_v);
    cudaGetSymbolAddress(&pop, g_outpre);
    cudaGetSymbolAddress(&psc, g_scores);
    cudaGetSymbolAddress(&pav, g_accv);
    __nv_bfloat16* xb  = (__nv_bfloat16*)pxb;
    __nv_bfloat16* wt  = (__nv_bfloat16*)pwt;
    __nv_bfloat16* wt2 = (__nv_bfloat16*)pwt2;

    cudaFuncSetAttribute(sscore_kernel, cudaFuncAttributeMaxDynamicSharedMemorySize, SS_SMEM);
    cudaFuncSetAttribute(fgemm_split_kernel, cudaFuncAttributeMaxDynamicSharedMemorySize, FG_SMEM);

    // x -> bf16 (logit path only)
    xconv_kernel<<<N_TOK * DM / 1024, 256>>>(x, xb);

    // q/k weight transposes and projections, merged into z=2 launches
    wtrans2_kernel<<<dim3(16, 16, 2), 256>>>(Wq, Wk, wt, wt2);
    proj2_gemm_bf16<<<dim3(DM / 64, N_TOK / 64, 2), 256>>>(
        xb, wt, wt2, bq, bk, (__nv_bfloat16*)pqb, (__nv_bfloat16*)pkb);

    // v projection: split-bf16 tensor-core GEMM (near-fp32 exact, pipelined)
    fgemm_split_kernel<<<dim3(DM / 64, N_TOK / 64), 256, FG_SMEM>>>(
        x, DM, 0, Wv, DM, 0, (float*)pv, DM, 0, DM, bv);

    // qk scores (bf16 mma, fp32 out)
    qk_mma_kernel<<<dim3(16, 16, 8), 256>>>((const __nv_bfloat16*)pqb, (const __nv_bfloat16*)pkb);

    // structure scores + softmax -> p fp32 (in place in g_scores), pipelined
    sscore_kernel<<<N_TOK, 256, SS_SMEM>>>(S, (const __nv_bfloat16*)pqb, Wsk, bsk);

    // acc_v = p @ v : split-bf16 GEMM, one z-slab per head
    fgemm_split_kernel<<<dim3(1, 16, 8), 256, FG_SMEM>>>(
        (const float*)psc, NH, N_TOK,
        (const float*)pv,  DM, DK,
        (float*)pav,       DM, DK,
        N_TOK, nullptr);

    // acc_t = p @ S, fused with combine epilogue -> g_outpre
    acct_combine_kernel<<<N_TOK, 256>>>(S, Wsv, bsv);

    // final output projection: split-bf16 GEMM (pipelined)
    fgemm_split_kernel<<<dim3(DM / 64, N_TOK / 64), 256, FG_SMEM>>>(
        (const float*)pop, DM, 0, Wo, DM, 0, out, DM, 0, DM, bo);
}

// round 16
// speedup vs baseline: 3.6538x; 1.0098x over previous
#include <cuda_runtime.h>
#include <cuda_bf16.h>
#include <math.h>
#include <stdint.h>

#define N_TOK 1024
#define DM    512
#define H     8
#define DK    64
#define NH    8192          // N_TOK * H
#define SCALE 0.125f        // 1/sqrt(64)

// ---------------- scratch (device globals; no allocation) ----------------
__device__ __nv_bfloat16 g_xb[N_TOK * DM];            // x in bf16
__device__ __nv_bfloat16 g_wt[DM * DM];               // transposed Wq bf16 [n][k]
__device__ __nv_bfloat16 g_wt2[DM * DM];              // transposed Wk bf16 [n][k]
__device__ __nv_bfloat16 g_qb[N_TOK * DM];            // relu(q) bf16 (logit path only)
__device__ __nv_bfloat16 g_kb[N_TOK * DM];            // relu(k) bf16 (logit path only)
__device__ float g_v[N_TOK * DM];                     // v fp32 (output path, near-exact)
__device__ float g_scores[(size_t)N_TOK * H * N_TOK]; // qk scores -> then p (fp32, in place)
__device__ float g_accv[N_TOK * DM];
__device__ float g_outpre[N_TOK * DM];

// ---------------- asm helpers ----------------
__device__ __forceinline__ uint32_t sptr(const void* p) {
    uint32_t r;
    asm("{ .reg .u64 t; cvta.to.shared.u64 t, %1; cvt.u32.u64 %0, t; }" : "=r"(r) : "l"(p));
    return r;
}
__device__ __forceinline__ void ldsm_x4(uint32_t& a0, uint32_t& a1, uint32_t& a2, uint32_t& a3, uint32_t addr) {
    asm volatile("ldmatrix.sync.aligned.m8n8.x4.shared.b16 {%0,%1,%2,%3}, [%4];"
                 : "=r"(a0), "=r"(a1), "=r"(a2), "=r"(a3) : "r"(addr));
}
__device__ __forceinline__ void ldsm_x4_t(uint32_t& a0, uint32_t& a1, uint32_t& a2, uint32_t& a3, uint32_t addr) {
    asm volatile("ldmatrix.sync.aligned.m8n8.x4.trans.shared.b16 {%0,%1,%2,%3}, [%4];"
                 : "=r"(a0), "=r"(a1), "=r"(a2), "=r"(a3) : "r"(addr));
}
__device__ __forceinline__ void ldsm_x2(uint32_t& b0, uint32_t& b1, uint32_t addr) {
    asm volatile("ldmatrix.sync.aligned.m8n8.x2.shared.b16 {%0,%1}, [%2];"
                 : "=r"(b0), "=r"(b1) : "r"(addr));
}
__device__ __forceinline__ void mma_bf16(float& c0, float& c1, float& c2, float& c3,
                                         uint32_t a0, uint32_t a1, uint32_t a2, uint32_t a3,
                                         uint32_t b0, uint32_t b1) {
    asm volatile("mma.sync.aligned.m16n8k16.row.col.f32.bf16.bf16.f32 "
                 "{%0,%1,%2,%3}, {%4,%5,%6,%7}, {%8,%9}, {%0,%1,%2,%3};"
                 : "+f"(c0), "+f"(c1), "+f"(c2), "+f"(c3)
                 : "r"(a0), "r"(a1), "r"(a2), "r"(a3), "r"(b0), "r"(b1));
}
__device__ __forceinline__ uint32_t pack_bf16x2(float lo, float hi) {
    uint32_t p;
    asm("cvt.rn.bf16x2.f32 %0, %1, %2;" : "=r"(p) : "f"(hi), "f"(lo));
    return p;
}
// split fp32 pair -> (hi bf16x2, lo bf16x2)
__device__ __forceinline__ void split2(float a, float b, uint32_t& hi, uint32_t& lo) {
    __nv_bfloat16 ha = __float2bfloat16(a), hb = __float2bfloat16(b);
    float ra = a - __bfloat162float(ha);
    float rb = b - __bfloat162float(hb);
    hi = pack_bf16x2(__bfloat162float(ha), __bfloat162float(hb));
    lo = pack_bf16x2(ra, rb);
}

// ---------------- K0a: x -> bf16 ----------------
__global__ void xconv_kernel(const float* __restrict__ x, __nv_bfloat16* __restrict__ xb) {
    int idx = (blockIdx.x * 256 + threadIdx.x) * 4;
    float4 v = *(const float4*)(x + idx);
    uint32_t lo = pack_bf16x2(v.x, v.y);
    uint32_t hi = pack_bf16x2(v.z, v.w);
    *(uint2*)(xb + idx) = make_uint2(lo, hi);
}

// ---------------- K0b: dual W [K][N] fp32 -> Wt [N][K] bf16 (z=2) --------
__global__ void wtrans2_kernel(const float* __restrict__ Wq, const float* __restrict__ Wk,
                               __nv_bfloat16* __restrict__ Wtq, __nv_bfloat16* __restrict__ Wtk) {
    const float* W = blockIdx.z ? Wk : Wq;
    __nv_bfloat16* Wt = blockIdx.z ? Wtk : Wtq;
    __shared__ float tile[32][33];
    int k0 = blockIdx.y * 32, n0 = blockIdx.x * 32;
    int x = threadIdx.x & 31, y = threadIdx.x >> 5;
#pragma unroll
    for (int r = 0; r < 4; r++)
        tile[y * 4 + r][x] = W[(size_t)(k0 + y * 4 + r) * DM + n0 + x];
    __syncthreads();
#pragma unroll
    for (int r = 0; r < 4; r++)
        Wt[(size_t)(n0 + y * 4 + r) * DM + k0 + x] = __float2bfloat16(tile[x][y * 4 + r]);
}

// ---------------- K1: dual projection GEMM bf16 mma (q and k, z=2) -------
__global__ __launch_bounds__(256) void proj2_gemm_bf16(
        const __nv_bfloat16* __restrict__ X,
        const __nv_bfloat16* __restrict__ Wtq,
        const __nv_bfloat16* __restrict__ Wtk,
        const float* __restrict__ bq,
        const float* __restrict__ bk,
        __nv_bfloat16* __restrict__ Cq,
        __nv_bfloat16* __restrict__ Ck) {
    const __nv_bfloat16* Wt = blockIdx.z ? Wtk : Wtq;
    const float* bias = blockIdx.z ? bk : bq;
    __nv_bfloat16* C = blockIdx.z ? Ck : Cq;
    __shared__ __align__(16) uint16_t Xs[64 * 72];
    __shared__ __align__(16) uint16_t Ws[64 * 72];
    int t = threadIdx.x, lane = t & 31, w = t >> 5;
    int m0 = blockIdx.y * 64, n0 = blockIdx.x * 64;
    int mblk = (w & 3) * 16, nhalf = (w >> 2) * 32;
    uint32_t Xb = sptr(Xs), Wb = sptr(Ws);
    float c[4][4] = {};

    for (int k0 = 0; k0 < DM; k0 += 64) {
        __syncthreads();
#pragma unroll
        for (int r = 0; r < 2; r++) {
            int f = r * 256 + t;
            int row = f >> 3, c8 = (f & 7) * 8;
            *(uint4*)&Xs[row * 72 + c8] = *(const uint4*)(X  + (size_t)(m0 + row) * DM + k0 + c8);
            *(uint4*)&Ws[row * 72 + c8] = *(const uint4*)(Wt + (size_t)(n0 + row) * DM + k0 + c8);
        }
        __syncthreads();
#pragma unroll
        for (int ks = 0; ks < 4; ks++) {
            uint32_t a0, a1, a2, a3;
            ldsm_x4(a0, a1, a2, a3, Xb + ((mblk + (lane & 15)) * 72 + ks * 16 + ((lane >> 4) << 3)) * 2);
#pragma unroll
            for (int nb = 0; nb < 2; nb++) {
                uint32_t b0, b1, b2, b3;
                int row = nhalf + nb * 16 + ((lane & 7) | ((lane >> 1) & 8));
                int col = ks * 16 + ((lane & 8) ? 8 : 0);
                ldsm_x4(b0, b1, b2, b3, Wb + (row * 72 + col) * 2);
                mma_bf16(c[nb*2][0], c[nb*2][1], c[nb*2][2], c[nb*2][3], a0, a1, a2, a3, b0, b1);
                mma_bf16(c[nb*2+1][0], c[nb*2+1][1], c[nb*2+1][2], c[nb*2+1][3], a0, a1, a2, a3, b2, b3);
            }
        }
    }
    int r = lane >> 2, cc = 2 * (lane & 3);
#pragma unroll
    for (int nb = 0; nb < 4; nb++) {
        int n = n0 + nhalf + nb * 8 + cc;
        float b0 = bias[n], b1 = bias[n + 1];
        float v0 = fmaxf(c[nb][0] + b0, 0.f), v1 = fmaxf(c[nb][1] + b1, 0.f);
        float v2 = fmaxf(c[nb][2] + b0, 0.f), v3 = fmaxf(c[nb][3] + b1, 0.f);
        *(uint32_t*)(C + (size_t)(m0 + mblk + r) * DM + n)     = pack_bf16x2(v0, v1);
        *(uint32_t*)(C + (size_t)(m0 + mblk + r + 8) * DM + n) = pack_bf16x2(v2, v3);
    }
}

// ---------------- split-bf16 fp32 GEMM, double-buffered + reg prefetch ---
#define FG_ARR  4608                     // 64*72 uint16 per array
#define FG_BUF  (4 * FG_ARR)             // Ahi,Alo,Bhi,Blo per buffer
#define FG_SMEM (2 * FG_BUF * 2)         // 73728 bytes
__global__ __launch_bounds__(256) void fgemm_split_kernel(
        const float* __restrict__ A, int lda, int aoffz,
        const float* __restrict__ B, int ldb, int boffz,
        float* __restrict__ C, int ldc, int coffz,
        int K, const float* __restrict__ bias) {
    extern __shared__ __align__(16) uint16_t fg[];
    int t = threadIdx.x, lane = t & 31, w = t >> 5;
    int m0 = blockIdx.y * 64, n0 = blockIdx.x * 64, z = blockIdx.z;
    A += (size_t)z * aoffz; B += (size_t)z * boffz; C += (size_t)z * coffz;
    int mblk = (w & 3) * 16, nhalf = (w >> 2) * 32;

    float4 av[4], bv[4];
#pragma unroll
    for (int r = 0; r < 4; r++) {
        int f = r * 256 + t;
        int row = f >> 4, c4 = (f & 15) * 4;
        av[r] = *(const float4*)(A + (size_t)(m0 + row) * lda + c4);
        bv[r] = *(const float4*)(B + (size_t)row * ldb + n0 + c4);
    }

    float c[4][4] = {};
    const int nk = K >> 6;
    for (int ki = 0; ki < nk; ki++) {
        uint16_t* buf = fg + (ki & 1) * FG_BUF;
        uint32_t Ahb = sptr(buf);
        uint32_t Alb = Ahb + FG_ARR * 2;
        uint32_t Bhb = Alb + FG_ARR * 2;
        uint32_t Blb = Bhb + FG_ARR * 2;

#pragma unroll
        for (int r = 0; r < 4; r++) {
            int f = r * 256 + t;
            int row = f >> 4, c4 = (f & 15) * 4;
            uint32_t h0, l0, h1, l1;
            split2(av[r].x, av[r].y, h0, l0);
            split2(av[r].z, av[r].w, h1, l1);
            *(uint2*)(buf + row * 72 + c4)              = make_uint2(h0, h1);
            *(uint2*)(buf + FG_ARR + row * 72 + c4)     = make_uint2(l0, l1);
            split2(bv[r].x, bv[r].y, h0, l0);
            split2(bv[r].z, bv[r].w, h1, l1);
            *(uint2*)(buf + 2 * FG_ARR + row * 72 + c4) = make_uint2(h0, h1);
            *(uint2*)(buf + 3 * FG_ARR + row * 72 + c4) = make_uint2(l0, l1);
        }
        __syncthreads();

        if (ki + 1 < nk) {
            int k0 = (ki + 1) << 6;
#pragma unroll
            for (int r = 0; r < 4; r++) {
                int f = r * 256 + t;
                int row = f >> 4, c4 = (f & 15) * 4;
                av[r] = *(const float4*)(A + (size_t)(m0 + row) * lda + k0 + c4);
                bv[r] = *(const float4*)(B + (size_t)(k0 + row) * ldb + n0 + c4);
            }
        }

#pragma unroll
        for (int ks = 0; ks < 4; ks++) {
            uint32_t aoff = ((mblk + (lane & 15)) * 72 + ks * 16 + ((lane >> 4) << 3)) * 2;
            uint32_t ah0, ah1, ah2, ah3, al0, al1, al2, al3;
            ldsm_x4(ah0, ah1, ah2, ah3, Ahb + aoff);
            ldsm_x4(al0, al1, al2, al3, Alb + aoff);
#pragma unroll
            for (int nb = 0; nb < 2; nb++) {
                uint32_t boff = ((ks * 16 + (lane & 15)) * 72 + nhalf + nb * 16 + ((lane >> 4) << 3)) * 2;
                uint32_t bh0, bh1, bh2, bh3, bl0, bl1, bl2, bl3;
                ldsm_x4_t(bh0, bh1, bh2, bh3, Bhb + boff);
                ldsm_x4_t(bl0, bl1, bl2, bl3, Blb + boff);
                float* cl = c[nb * 2];
                float* ch = c[nb * 2 + 1];
                mma_bf16(cl[0], cl[1], cl[2], cl[3], ah0, ah1, ah2, ah3, bh0, bh1);
                mma_bf16(cl[0], cl[1], cl[2], cl[3], ah0, ah1, ah2, ah3, bl0, bl1);
                mma_bf16(cl[0], cl[1], cl[2], cl[3], al0, al1, al2, al3, bh0, bh1);
                mma_bf16(ch[0], ch[1], ch[2], ch[3], ah0, ah1, ah2, ah3, bh2, bh3);
                mma_bf16(ch[0], ch[1], ch[2], ch[3], ah0, ah1, ah2, ah3, bl2, bl3);
                mma_bf16(ch[0], ch[1], ch[2], ch[3], al0, al1, al2, al3, bh2, bh3);
            }
        }
    }
    int r = lane >> 2, cc = 2 * (lane & 3);
#pragma unroll
    for (int nb = 0; nb < 4; nb++) {
        int n = n0 + nhalf + nb * 8 + cc;
        float b0 = bias ? bias[n] : 0.f;
        float b1 = bias ? bias[n + 1] : 0.f;
        *(float2*)(C + (size_t)(m0 + mblk + r) * ldc + n)     = make_float2(c[nb][0] + b0, c[nb][1] + b1);
        *(float2*)(C + (size_t)(m0 + mblk + r + 8) * ldc + n) = make_float2(c[nb][2] + b0, c[nb][3] + b1);
    }
}

// ---------------- K2: qk scores via bf16 mma ----------------
__global__ __launch_bounds__(256) void qk_mma_kernel(
        const __nv_bfloat16* __restrict__ Q, const __nv_bfloat16* __restrict__ K) {
    __shared__ __align__(16) uint16_t Qs[64 * 72];   // [i][e]
    __shared__ __align__(16) uint16_t Ks[64 * 72];   // [j][e]
    int h = blockIdx.z, i0 = blockIdx.y * 64, j0 = blockIdx.x * 64;
    int t = threadIdx.x, lane = t & 31, w = t >> 5;
    int iblk = (w & 3) * 16, jhalf = (w >> 2) * 32;
    uint32_t Qb = sptr(Qs), Kb = sptr(Ks);

#pragma unroll
    for (int r = 0; r < 2; r++) {
        int f = r * 256 + t;
        int row = f >> 3, c8 = (f & 7) * 8;
        *(uint4*)&Qs[row * 72 + c8] = *(const uint4*)(Q + (size_t)(i0 + row) * DM + h * DK + c8);
        *(uint4*)&Ks[row * 72 + c8] = *(const uint4*)(K + (size_t)(j0 + row) * DM + h * DK + c8);
    }
    __syncthreads();

    float c[4][4] = {};
#pragma unroll
    for (int ks = 0; ks < 4; ks++) {
        uint32_t a0, a1, a2, a3;
        ldsm_x4(a0, a1, a2, a3, Qb + ((iblk + (lane & 15)) * 72 + ks * 16 + ((lane >> 4) << 3)) * 2);
#pragma unroll
        for (int nb = 0; nb < 2; nb++) {
            uint32_t b0, b1, b2, b3;
            int row = jhalf + nb * 16 + ((lane & 7) | ((lane >> 1) & 8));
            int col = ks * 16 + ((lane & 8) ? 8 : 0);
            ldsm_x4(b0, b1, b2, b3, Kb + (row * 72 + col) * 2);
            mma_bf16(c[nb*2][0], c[nb*2][1], c[nb*2][2], c[nb*2][3], a0, a1, a2, a3, b0, b1);
            mma_bf16(c[nb*2+1][0], c[nb*2+1][1], c[nb*2+1][2], c[nb*2+1][3], a0, a1, a2, a3, b2, b3);
        }
    }
    int r = lane >> 2, cc = 2 * (lane & 3);
#pragma unroll
    for (int nb = 0; nb < 4; nb++) {
        int j = j0 + jhalf + nb * 8 + cc;
        *(float2*)(g_scores + (size_t)(i0 + iblk + r) * NH + h * N_TOK + j)     = make_float2(c[nb][0], c[nb][1]);
        *(float2*)(g_scores + (size_t)(i0 + iblk + r + 8) * NH + h * N_TOK + j) = make_float2(c[nb][2], c[nb][3]);
    }
}

// ---------------- K3: fused structure-scores + softmax -> p fp32 ---------
// W fragments loaded pairwise via ldsm_x4 (half the ldsm of the x2 version);
// mma issue order unchanged -> bit-identical.
#define SS_SMEM 61824
__global__ __launch_bounds__(256, 2) void sscore_kernel(
        const float* __restrict__ S,
        const __nv_bfloat16* __restrict__ qb,
        const float* __restrict__ Wsk,
        const float* __restrict__ bsk) {
    extern __shared__ __align__(16) char dyn[];
    uint16_t* S_sh  = (uint16_t*)dyn;              // [128 j][72 c]
    uint16_t* W_sh  = (uint16_t*)(dyn + 18432);    // [64 e][72 c]
    uint16_t* q_sh  = (uint16_t*)(dyn + 27648);    // [8 h][72 e]
    float*    bsk_sh = (float*)(dyn + 28800);      // 64
    float*    p_sh  = (float*)(dyn + 29056);       // [8 h][1024 j]

    const int i    = blockIdx.x;
    const int t    = threadIdx.x;
    const int lane = t & 31;
    const int w    = t >> 5;

#pragma unroll
    for (int r = 0; r < 16; r++) {
        int f = r * 256 + t;
        int c = f >> 6, e = f & 63;
        __nv_bfloat16 b = __float2bfloat16(Wsk[f]);
        W_sh[e * 72 + c] = *(uint16_t*)&b;
    }
    if (t < 64) {
        int h = t >> 3, e8 = (t & 7) * 8;
        *(uint4*)&q_sh[h * 72 + e8] = *(const uint4*)(qb + (size_t)i * DM + h * DK + e8);
        bsk_sh[t] = bsk[t];
    }
    __syncthreads();

    const uint32_t Sbase = sptr(S_sh);
    const uint32_t Wbase = sptr(W_sh);
    const uint32_t qbase = sptr(q_sh);
    const uint32_t offA = ((w * 16 + (lane & 15)) * 72 + ((lane >> 4) << 3)) * 2;
    const uint32_t offB = ((lane & 7) * 72 + (((lane >> 3) & 1) << 3)) * 2;
    // x4 W load: matrices = {ck cols 0-7, ck cols 8-15, ck+1 cols 0-7, ck+1 cols 8-15}
    const uint32_t offW = ((lane & 7) * 72 + (((lane >> 3) & 1) << 3)) * 2 + ((lane >> 4) << 5);

    uint32_t qf[4][2];
#pragma unroll
    for (int ek = 0; ek < 4; ek++)
        ldsm_x2(qf[ek][0], qf[ek][1], qbase + offB + ek * 32);

    const int ecol = 2 * (lane & 3);
    const float* Srow = S + (size_t)i * N_TOK * 64;
    const int prow = t >> 4;
    const int pc4  = (t & 15) * 4;

    // prefetch S tile 0 into registers
    float4 pf[8];
#pragma unroll
    for (int r = 0; r < 8; r++)
        pf[r] = *(const float4*)(Srow + (size_t)(r * 16 + prow) * 64 + pc4);

    for (int j0 = 0; j0 < N_TOK; j0 += 128) {
        __syncthreads();
#pragma unroll
        for (int r = 0; r < 8; r++) {
            int jj = r * 16 + prow;
            uint32_t lo = pack_bf16x2(pf[r].x, pf[r].y);
            uint32_t hi = pack_bf16x2(pf[r].z, pf[r].w);
            *(uint2*)&S_sh[jj * 72 + pc4] = make_uint2(lo, hi);
        }
        __syncthreads();

        if (j0 + 128 < N_TOK) {
            const float* Snext = Srow + (size_t)(j0 + 128) * 64;
#pragma unroll
            for (int r = 0; r < 8; r++)
                pf[r] = *(const float4*)(Snext + (size_t)(r * 16 + prow) * 64 + pc4);
        }

        uint32_t sa[4][4];
#pragma unroll
        for (int ck = 0; ck < 4; ck++)
            ldsm_x4(sa[ck][0], sa[ck][1], sa[ck][2], sa[ck][3], Sbase + offA + ck * 32);

        uint32_t skl[8], skh[8];
#pragma unroll
        for (int et = 0; et < 8; et++) {
            float c0 = 0.f, c1 = 0.f, c2 = 0.f, c3 = 0.f;
#pragma unroll
            for (int ck = 0; ck < 4; ck += 2) {
                uint32_t b0, b1, b2, b3;
                ldsm_x4(b0, b1, b2, b3, Wbase + offW + et * (8 * 72 * 2) + ck * 32);
                mma_bf16(c0, c1, c2, c3, sa[ck][0], sa[ck][1], sa[ck][2], sa[ck][3], b0, b1);
                mma_bf16(c0, c1, c2, c3, sa[ck+1][0], sa[ck+1][1], sa[ck+1][2], sa[ck+1][3], b2, b3);
            }
            float blo = bsk_sh[et * 8 + ecol];
            float bhi = bsk_sh[et * 8 + ecol + 1];
            c0 = fmaxf(c0 + blo, 0.f); c1 = fmaxf(c1 + bhi, 0.f);
            c2 = fmaxf(c2 + blo, 0.f); c3 = fmaxf(c3 + bhi, 0.f);
            skl[et] = pack_bf16x2(c0, c1);
            skh[et] = pack_bf16x2(c2, c3);
        }

        float s0 = 0.f, s1 = 0.f, s2 = 0.f, s3 = 0.f;
#pragma unroll
        for (int ek = 0; ek < 4; ek++)
            mma_bf16(s0, s1, s2, s3,
                     skl[2*ek], skh[2*ek], skl[2*ek+1], skh[2*ek+1],
                     qf[ek][0], qf[ek][1]);

        int jw = j0 + w * 16 + (lane >> 2);
        int h0 = 2 * (lane & 3);
        p_sh[h0 * N_TOK + jw]           = s0;
        p_sh[(h0 + 1) * N_TOK + jw]     = s1;
        p_sh[h0 * N_TOK + jw + 8]       = s2;
        p_sh[(h0 + 1) * N_TOK + jw + 8] = s3;
    }
    __syncthreads();

    // softmax: warp w owns row h=w; p written back to g_scores (fp32)
    {
        float* row = p_sh + w * N_TOK;
        float* gsc = g_scores + (size_t)i * NH + w * N_TOK;
        float mx = -1e30f;
#pragma unroll
        for (int rr = 0; rr < 8; rr++) {
            int idx = rr * 128 + lane * 4;
            float4 g = *(const float4*)(gsc + idx);
            float4 p = *(float4*)(row + idx);
            p.x = (p.x + g.x) * SCALE; p.y = (p.y + g.y) * SCALE;
            p.z = (p.z + g.z) * SCALE; p.w = (p.w + g.w) * SCALE;
            *(float4*)(row + idx) = p;
            mx = fmaxf(mx, fmaxf(fmaxf(p.x, p.y), fmaxf(p.z, p.w)));
        }
#pragma unroll
        for (int o = 16; o; o >>= 1) mx = fmaxf(mx, __shfl_xor_sync(0xffffffffu, mx, o));
        float sum = 0.f;
#pragma unroll
        for (int rr = 0; rr < 8; rr++) {
            int idx = rr * 128 + lane * 4;
            float4 p = *(float4*)(row + idx);
            p.x = __expf(p.x - mx); p.y = __expf(p.y - mx);
            p.z = __expf(p.z - mx); p.w = __expf(p.w - mx);
            *(float4*)(row + idx) = p;
            sum += p.x + p.y + p.z + p.w;
        }
#pragma unroll
        for (int o = 16; o; o >>= 1) sum += __shfl_xor_sync(0xffffffffu, sum, o);
        float inv = 1.0f / sum;
#pragma unroll
        for (int rr = 0; rr < 8; rr++) {
            int idx = rr * 128 + lane * 4;
            float4 p = *(float4*)(row + idx);
            p.x *= inv; p.y *= inv; p.z *= inv; p.w *= inv;
            *(float4*)(gsc + idx) = p;
        }
    }
}

// ---------------- K5b fused: out_pre = accv + (p@S) @ Wsv + bsv ----------
// Reverse-i order: sscore streamed S forward, so iterating i backward hits
// the L2-resident tail of S (stack reuse). Per-i math identical.
__global__ __launch_bounds__(256) void acct_combine_kernel(
        const float* __restrict__ S,
        const float* __restrict__ Wsv,
        const float* __restrict__ bsv) {
    __shared__ float psh[8 * 1024];     // 32KB: p, then partials, then Wsv
    __shared__ float tsh[512];          // acc_t[h][e]
    int i = N_TOK - 1 - blockIdx.x, t = threadIdx.x;
#pragma unroll
    for (int r = 0; r < 8; r++) {
        int f = (r * 256 + t) * 4;
        *(float4*)&psh[f] = *(const float4*)(g_scores + (size_t)i * NH + f);
    }
    __syncthreads();

    const int e4   = (t & 15) * 4;
    const int joff = t >> 4;
    float4 acc[8];
#pragma unroll
    for (int h = 0; h < 8; h++) acc[h] = make_float4(0.f, 0.f, 0.f, 0.f);

    const float* Sr = S + (size_t)i * N_TOK * 64;
#pragma unroll 4
    for (int j = joff; j < N_TOK; j += 16) {
        float4 s = *(const float4*)(Sr + (size_t)j * 64 + e4);
#pragma unroll
        for (int h = 0; h < 8; h++) {
            float p = psh[h * N_TOK + j];
            acc[h].x += p * s.x; acc[h].y += p * s.y;
            acc[h].z += p * s.z; acc[h].w += p * s.w;
        }
    }
    __syncthreads();

#pragma unroll
    for (int h = 0; h < 8; h++)
        *(float4*)&psh[joff * 512 + h * 64 + e4] = acc[h];
    __syncthreads();

#pragma unroll
    for (int r = 0; r < 2; r++) {
        int o = r * 256 + t;   // h*64 + e
        float s = 0.f;
#pragma unroll
        for (int jo = 0; jo < 16; jo++) s += psh[jo * 512 + o];
        tsh[o] = s;
    }
    __syncthreads();

    // load Wsv [e][d] 64x64 fp32 into psh (reuse)
#pragma unroll
    for (int r = 0; r < 4; r++) {
        int f = r * 256 + t;
        *(float4*)&psh[f * 4] = *(const float4*)(Wsv + f * 4);
    }
    __syncthreads();

    int d  = t & 63;
    int h0 = t >> 6;
    float bd = bsv[d];
#pragma unroll
    for (int r = 0; r < 2; r++) {
        int h = h0 + r * 4;
        float a = 0.f;
#pragma unroll 16
        for (int e = 0; e < 64; e++) a += tsh[h * 64 + e] * psh[e * 64 + d];
        g_outpre[(size_t)i * DM + h * DK + d] =
            g_accv[(size_t)i * DM + h * DK + d] + a + bd;
    }
}

// ---------------- launch ----------------
extern "C" void kernel_launch(void* const* d_in, const int* in_sizes, int n_in,
                              void* d_out, int out_size) {
    const float* x   = (const float*)d_in[0];
    const float* S   = (const float*)d_in[1];
    const float* Wq  = (const float*)d_in[2];  const float* bq  = (const float*)d_in[3];
    const float* Wk  = (const float*)d_in[4];  const float* bk  = (const float*)d_in[5];
    const float* Wv  = (const float*)d_in[6];  const float* bv  = (const float*)d_in[7];
    const float* Wo  = (const float*)d_in[8];  const float* bo  = (const float*)d_in[9];
    const float* Wsk = (const float*)d_in[10]; const float* bsk = (const float*)d_in[11];
    const float* Wsv = (const float*)d_in[12]; const float* bsv = (const float*)d_in[13];
    float* out = (float*)d_out;

    void *pxb, *pwt, *pwt2, *pqb, *pkb, *pv, *pop, *psc, *pav;
    cudaGetSymbolAddress(&pxb, g_xb);
    cudaGetSymbolAddress(&pwt, g_wt);
    cudaGetSymbolAddress(&pwt2, g_wt2);
    cudaGetSymbolAddress(&pqb, g_qb);
    cudaGetSymbolAddress(&pkb, g_kb);
    cudaGetSymbolAddress(&pv,  g_v);
    cudaGetSymbolAddress(&pop, g_outpre);
    cudaGetSymbolAddress(&psc, g_scores);
    cudaGetSymbolAddress(&pav, g_accv);
    __nv_bfloat16* xb  = (__nv_bfloat16*)pxb;
    __nv_bfloat16* wt  = (__nv_bfloat16*)pwt;
    __nv_bfloat16* wt2 = (__nv_bfloat16*)pwt2;

    cudaFuncSetAttribute(sscore_kernel, cudaFuncAttributeMaxDynamicSharedMemorySize, SS_SMEM);
    cudaFuncSetAttribute(fgemm_split_kernel, cudaFuncAttributeMaxDynamicSharedMemorySize, FG_SMEM);

    // x -> bf16 (logit path only)
    xconv_kernel<<<N_TOK * DM / 1024, 256>>>(x, xb);

    // q/k weight transposes and projections, merged into z=2 launches
    wtrans2_kernel<<<dim3(16, 16, 2), 256>>>(Wq, Wk, wt, wt2);
    proj2_gemm_bf16<<<dim3(DM / 64, N_TOK / 64, 2), 256>>>(
        xb, wt, wt2, bq, bk, (__nv_bfloat16*)pqb, (__nv_bfloat16*)pkb);

    // v projection: split-bf16 tensor-core GEMM (near-fp32 exact, pipelined)
    fgemm_split_kernel<<<dim3(DM / 64, N_TOK / 64), 256, FG_SMEM>>>(
        x, DM, 0, Wv, DM, 0, (float*)pv, DM, 0, DM, bv);

    // qk scores (bf16 mma, fp32 out)
    qk_mma_kernel<<<dim3(16, 16, 8), 256>>>((const __nv_bfloat16*)pqb, (const __nv_bfloat16*)pkb);

    // structure scores + softmax -> p fp32 (in place in g_scores), pipelined
    sscore_kernel<<<N_TOK, 256, SS_SMEM>>>(S, (const __nv_bfloat16*)pqb, Wsk, bsk);

    // acc_v = p @ v : split-bf16 GEMM, one z-slab per head
    fgemm_split_kernel<<<dim3(1, 16, 8), 256, FG_SMEM>>>(
        (const float*)psc, NH, N_TOK,
        (const float*)pv,  DM, DK,
        (float*)pav,       DM, DK,
        N_TOK, nullptr);

    // acc_t = p @ S (reverse-i for L2 reuse), fused combine -> g_outpre
    acct_combine_kernel<<<N_TOK, 256>>>(S, Wsv, bsv);

    // final output projection: split-bf16 GEMM (pipelined)
    fgemm_split_kernel<<<dim3(DM / 64, N_TOK / 64), 256, FG_SMEM>>>(
        (const float*)pop, DM, 0, Wo, DM, 0, out, DM, 0, DM, bo);
}

// round 17
// speedup vs baseline: 4.3798x; 1.1987x over previous
#include <cuda_runtime.h>
#include <cuda_bf16.h>
#include <math.h>
#include <stdint.h>

#define N_TOK 1024
#define DM    512
#define H     8
#define DK    64
#define NH    8192          // N_TOK * H
#define SCALE 0.125f        // 1/sqrt(64)

// ---------------- scratch (device globals; no allocation) ----------------
__device__ __nv_bfloat16 g_xb[N_TOK * DM];            // x in bf16
__device__ __nv_bfloat16 g_wt[DM * DM];               // transposed Wq bf16 [n][k]
__device__ __nv_bfloat16 g_wt2[DM * DM];              // transposed Wk bf16 [n][k]
__device__ __nv_bfloat16 g_qb[N_TOK * DM];            // relu(q) bf16 (logit path only)
__device__ __nv_bfloat16 g_kb[N_TOK * DM];            // relu(k) bf16 (logit path only)
__device__ float g_v[N_TOK * DM];                     // v fp32 (output path, near-exact)
__device__ float g_scores[(size_t)N_TOK * H * N_TOK]; // qk scores -> then p (fp32, in place)
__device__ float g_outpre[N_TOK * DM];                // acct@Wsv + bsv, then += p@v

// ---------------- asm helpers ----------------
__device__ __forceinline__ uint32_t sptr(const void* p) {
    uint32_t r;
    asm("{ .reg .u64 t; cvta.to.shared.u64 t, %1; cvt.u32.u64 %0, t; }" : "=r"(r) : "l"(p));
    return r;
}
__device__ __forceinline__ void ldsm_x4(uint32_t& a0, uint32_t& a1, uint32_t& a2, uint32_t& a3, uint32_t addr) {
    asm volatile("ldmatrix.sync.aligned.m8n8.x4.shared.b16 {%0,%1,%2,%3}, [%4];"
                 : "=r"(a0), "=r"(a1), "=r"(a2), "=r"(a3) : "r"(addr));
}
__device__ __forceinline__ void ldsm_x4_t(uint32_t& a0, uint32_t& a1, uint32_t& a2, uint32_t& a3, uint32_t addr) {
    asm volatile("ldmatrix.sync.aligned.m8n8.x4.trans.shared.b16 {%0,%1,%2,%3}, [%4];"
                 : "=r"(a0), "=r"(a1), "=r"(a2), "=r"(a3) : "r"(addr));
}
__device__ __forceinline__ void ldsm_x2(uint32_t& b0, uint32_t& b1, uint32_t addr) {
    asm volatile("ldmatrix.sync.aligned.m8n8.x2.shared.b16 {%0,%1}, [%2];"
                 : "=r"(b0), "=r"(b1) : "r"(addr));
}
__device__ __forceinline__ void mma_bf16(float& c0, float& c1, float& c2, float& c3,
                                         uint32_t a0, uint32_t a1, uint32_t a2, uint32_t a3,
                                         uint32_t b0, uint32_t b1) {
    asm volatile("mma.sync.aligned.m16n8k16.row.col.f32.bf16.bf16.f32 "
                 "{%0,%1,%2,%3}, {%4,%5,%6,%7}, {%8,%9}, {%0,%1,%2,%3};"
                 : "+f"(c0), "+f"(c1), "+f"(c2), "+f"(c3)
                 : "r"(a0), "r"(a1), "r"(a2), "r"(a3), "r"(b0), "r"(b1));
}
__device__ __forceinline__ uint32_t pack_bf16x2(float lo, float hi) {
    uint32_t p;
    asm("cvt.rn.bf16x2.f32 %0, %1, %2;" : "=r"(p) : "f"(hi), "f"(lo));
    return p;
}
// split fp32 pair -> (hi bf16x2, lo bf16x2)
__device__ __forceinline__ void split2(float a, float b, uint32_t& hi, uint32_t& lo) {
    __nv_bfloat16 ha = __float2bfloat16(a), hb = __float2bfloat16(b);
    float ra = a - __bfloat162float(ha);
    float rb = b - __bfloat162float(hb);
    hi = pack_bf16x2(__bfloat162float(ha), __bfloat162float(hb));
    lo = pack_bf16x2(ra, rb);
}

// ---------------- K0a: x -> bf16 ----------------
__global__ void xconv_kernel(const float* __restrict__ x, __nv_bfloat16* __restrict__ xb) {
    int idx = (blockIdx.x * 256 + threadIdx.x) * 4;
    float4 v = *(const float4*)(x + idx);
    uint32_t lo = pack_bf16x2(v.x, v.y);
    uint32_t hi = pack_bf16x2(v.z, v.w);
    *(uint2*)(xb + idx) = make_uint2(lo, hi);
}

// ---------------- K0b: dual W [K][N] fp32 -> Wt [N][K] bf16 (z=2) --------
__global__ void wtrans2_kernel(const float* __restrict__ Wq, const float* __restrict__ Wk,
                               __nv_bfloat16* __restrict__ Wtq, __nv_bfloat16* __restrict__ Wtk) {
    const float* W = blockIdx.z ? Wk : Wq;
    __nv_bfloat16* Wt = blockIdx.z ? Wtk : Wtq;
    __shared__ float tile[32][33];
    int k0 = blockIdx.y * 32, n0 = blockIdx.x * 32;
    int x = threadIdx.x & 31, y = threadIdx.x >> 5;
#pragma unroll
    for (int r = 0; r < 4; r++)
        tile[y * 4 + r][x] = W[(size_t)(k0 + y * 4 + r) * DM + n0 + x];
    __syncthreads();
#pragma unroll
    for (int r = 0; r < 4; r++)
        Wt[(size_t)(n0 + y * 4 + r) * DM + k0 + x] = __float2bfloat16(tile[x][y * 4 + r]);
}

// ---------------- K1: dual projection GEMM bf16 mma (q and k, z=2) -------
__global__ __launch_bounds__(256) void proj2_gemm_bf16(
        const __nv_bfloat16* __restrict__ X,
        const __nv_bfloat16* __restrict__ Wtq,
        const __nv_bfloat16* __restrict__ Wtk,
        const float* __restrict__ bq,
        const float* __restrict__ bk,
        __nv_bfloat16* __restrict__ Cq,
        __nv_bfloat16* __restrict__ Ck) {
    const __nv_bfloat16* Wt = blockIdx.z ? Wtk : Wtq;
    const float* bias = blockIdx.z ? bk : bq;
    __nv_bfloat16* C = blockIdx.z ? Ck : Cq;
    __shared__ __align__(16) uint16_t Xs[64 * 72];
    __shared__ __align__(16) uint16_t Ws[64 * 72];
    int t = threadIdx.x, lane = t & 31, w = t >> 5;
    int m0 = blockIdx.y * 64, n0 = blockIdx.x * 64;
    int mblk = (w & 3) * 16, nhalf = (w >> 2) * 32;
    uint32_t Xb = sptr(Xs), Wb = sptr(Ws);
    float c[4][4] = {};

    for (int k0 = 0; k0 < DM; k0 += 64) {
        __syncthreads();
#pragma unroll
        for (int r = 0; r < 2; r++) {
            int f = r * 256 + t;
            int row = f >> 3, c8 = (f & 7) * 8;
            *(uint4*)&Xs[row * 72 + c8] = *(const uint4*)(X  + (size_t)(m0 + row) * DM + k0 + c8);
            *(uint4*)&Ws[row * 72 + c8] = *(const uint4*)(Wt + (size_t)(n0 + row) * DM + k0 + c8);
        }
        __syncthreads();
#pragma unroll
        for (int ks = 0; ks < 4; ks++) {
            uint32_t a0, a1, a2, a3;
            ldsm_x4(a0, a1, a2, a3, Xb + ((mblk + (lane & 15)) * 72 + ks * 16 + ((lane >> 4) << 3)) * 2);
#pragma unroll
            for (int nb = 0; nb < 2; nb++) {
                uint32_t b0, b1, b2, b3;
                int row = nhalf + nb * 16 + ((lane & 7) | ((lane >> 1) & 8));
                int col = ks * 16 + ((lane & 8) ? 8 : 0);
                ldsm_x4(b0, b1, b2, b3, Wb + (row * 72 + col) * 2);
                mma_bf16(c[nb*2][0], c[nb*2][1], c[nb*2][2], c[nb*2][3], a0, a1, a2, a3, b0, b1);
                mma_bf16(c[nb*2+1][0], c[nb*2+1][1], c[nb*2+1][2], c[nb*2+1][3], a0, a1, a2, a3, b2, b3);
            }
        }
    }
    int r = lane >> 2, cc = 2 * (lane & 3);
#pragma unroll
    for (int nb = 0; nb < 4; nb++) {
        int n = n0 + nhalf + nb * 8 + cc;
        float b0 = bias[n], b1 = bias[n + 1];
        float v0 = fmaxf(c[nb][0] + b0, 0.f), v1 = fmaxf(c[nb][1] + b1, 0.f);
        float v2 = fmaxf(c[nb][2] + b0, 0.f), v3 = fmaxf(c[nb][3] + b1, 0.f);
        *(uint32_t*)(C + (size_t)(m0 + mblk + r) * DM + n)     = pack_bf16x2(v0, v1);
        *(uint32_t*)(C + (size_t)(m0 + mblk + r + 8) * DM + n) = pack_bf16x2(v2, v3);
    }
}

// ---------------- split-bf16 fp32 GEMM, double-buffered + reg prefetch ---
// accum!=0: C = A@B + C_prev (bias ignored-as-zero add order preserved).
#define FG_ARR  4608                     // 64*72 uint16 per array
#define FG_BUF  (4 * FG_ARR)             // Ahi,Alo,Bhi,Blo per buffer
#define FG_SMEM (2 * FG_BUF * 2)         // 73728 bytes
__global__ __launch_bounds__(256) void fgemm_split_kernel(
        const float* __restrict__ A, int lda, int aoffz,
        const float* __restrict__ B, int ldb, int boffz,
        float* __restrict__ C, int ldc, int coffz,
        int K, const float* __restrict__ bias, int accum) {
    extern __shared__ __align__(16) uint16_t fg[];
    int t = threadIdx.x, lane = t & 31, w = t >> 5;
    int m0 = blockIdx.y * 64, n0 = blockIdx.x * 64, z = blockIdx.z;
    A += (size_t)z * aoffz; B += (size_t)z * boffz; C += (size_t)z * coffz;
    int mblk = (w & 3) * 16, nhalf = (w >> 2) * 32;

    float4 av[4], bv[4];
#pragma unroll
    for (int r = 0; r < 4; r++) {
        int f = r * 256 + t;
        int row = f >> 4, c4 = (f & 15) * 4;
        av[r] = *(const float4*)(A + (size_t)(m0 + row) * lda + c4);
        bv[r] = *(const float4*)(B + (size_t)row * ldb + n0 + c4);
    }

    float c[4][4] = {};
    const int nk = K >> 6;
    for (int ki = 0; ki < nk; ki++) {
        uint16_t* buf = fg + (ki & 1) * FG_BUF;
        uint32_t Ahb = sptr(buf);
        uint32_t Alb = Ahb + FG_ARR * 2;
        uint32_t Bhb = Alb + FG_ARR * 2;
        uint32_t Blb = Bhb + FG_ARR * 2;

#pragma unroll
        for (int r = 0; r < 4; r++) {
            int f = r * 256 + t;
            int row = f >> 4, c4 = (f & 15) * 4;
            uint32_t h0, l0, h1, l1;
            split2(av[r].x, av[r].y, h0, l0);
            split2(av[r].z, av[r].w, h1, l1);
            *(uint2*)(buf + row * 72 + c4)              = make_uint2(h0, h1);
            *(uint2*)(buf + FG_ARR + row * 72 + c4)     = make_uint2(l0, l1);
            split2(bv[r].x, bv[r].y, h0, l0);
            split2(bv[r].z, bv[r].w, h1, l1);
            *(uint2*)(buf + 2 * FG_ARR + row * 72 + c4) = make_uint2(h0, h1);
            *(uint2*)(buf + 3 * FG_ARR + row * 72 + c4) = make_uint2(l0, l1);
        }
        __syncthreads();

        if (ki + 1 < nk) {
            int k0 = (ki + 1) << 6;
#pragma unroll
            for (int r = 0; r < 4; r++) {
                int f = r * 256 + t;
                int row = f >> 4, c4 = (f & 15) * 4;
                av[r] = *(const float4*)(A + (size_t)(m0 + row) * lda + k0 + c4);
                bv[r] = *(const float4*)(B + (size_t)(k0 + row) * ldb + n0 + c4);
            }
        }

#pragma unroll
        for (int ks = 0; ks < 4; ks++) {
            uint32_t aoff = ((mblk + (lane & 15)) * 72 + ks * 16 + ((lane >> 4) << 3)) * 2;
            uint32_t ah0, ah1, ah2, ah3, al0, al1, al2, al3;
            ldsm_x4(ah0, ah1, ah2, ah3, Ahb + aoff);
            ldsm_x4(al0, al1, al2, al3, Alb + aoff);
#pragma unroll
            for (int nb = 0; nb < 2; nb++) {
                uint32_t boff = ((ks * 16 + (lane & 15)) * 72 + nhalf + nb * 16 + ((lane >> 4) << 3)) * 2;
                uint32_t bh0, bh1, bh2, bh3, bl0, bl1, bl2, bl3;
                ldsm_x4_t(bh0, bh1, bh2, bh3, Bhb + boff);
                ldsm_x4_t(bl0, bl1, bl2, bl3, Blb + boff);
                float* cl = c[nb * 2];
                float* ch = c[nb * 2 + 1];
                mma_bf16(cl[0], cl[1], cl[2], cl[3], ah0, ah1, ah2, ah3, bh0, bh1);
                mma_bf16(cl[0], cl[1], cl[2], cl[3], ah0, ah1, ah2, ah3, bl0, bl1);
                mma_bf16(cl[0], cl[1], cl[2], cl[3], al0, al1, al2, al3, bh0, bh1);
                mma_bf16(ch[0], ch[1], ch[2], ch[3], ah0, ah1, ah2, ah3, bh2, bh3);
                mma_bf16(ch[0], ch[1], ch[2], ch[3], ah0, ah1, ah2, ah3, bl2, bl3);
                mma_bf16(ch[0], ch[1], ch[2], ch[3], al0, al1, al2, al3, bh2, bh3);
            }
        }
    }
    int r = lane >> 2, cc = 2 * (lane & 3);
#pragma unroll
    for (int nb = 0; nb < 4; nb++) {
        int n = n0 + nhalf + nb * 8 + cc;
        float b0 = bias ? bias[n] : 0.f;
        float b1 = bias ? bias[n + 1] : 0.f;
        float* p0 = C + (size_t)(m0 + mblk + r) * ldc + n;
        float* p1 = C + (size_t)(m0 + mblk + r + 8) * ldc + n;
        float2 o0 = make_float2(c[nb][0] + b0, c[nb][1] + b1);
        float2 o1 = make_float2(c[nb][2] + b0, c[nb][3] + b1);
        if (accum) {
            float2 e0 = *(float2*)p0, e1 = *(float2*)p1;
            o0.x += e0.x; o0.y += e0.y; o1.x += e1.x; o1.y += e1.y;
        }
        *(float2*)p0 = o0;
        *(float2*)p1 = o1;
    }
}

// ---------------- K2: qk scores via bf16 mma ----------------
__global__ __launch_bounds__(256) void qk_mma_kernel(
        const __nv_bfloat16* __restrict__ Q, const __nv_bfloat16* __restrict__ K) {
    __shared__ __align__(16) uint16_t Qs[64 * 72];   // [i][e]
    __shared__ __align__(16) uint16_t Ks[64 * 72];   // [j][e]
    int h = blockIdx.z, i0 = blockIdx.y * 64, j0 = blockIdx.x * 64;
    int t = threadIdx.x, lane = t & 31, w = t >> 5;
    int iblk = (w & 3) * 16, jhalf = (w >> 2) * 32;
    uint32_t Qb = sptr(Qs), Kb = sptr(Ks);

#pragma unroll
    for (int r = 0; r < 2; r++) {
        int f = r * 256 + t;
        int row = f >> 3, c8 = (f & 7) * 8;
        *(uint4*)&Qs[row * 72 + c8] = *(const uint4*)(Q + (size_t)(i0 + row) * DM + h * DK + c8);
        *(uint4*)&Ks[row * 72 + c8] = *(const uint4*)(K + (size_t)(j0 + row) * DM + h * DK + c8);
    }
    __syncthreads();

    float c[4][4] = {};
#pragma unroll
    for (int ks = 0; ks < 4; ks++) {
        uint32_t a0, a1, a2, a3;
        ldsm_x4(a0, a1, a2, a3, Qb + ((iblk + (lane & 15)) * 72 + ks * 16 + ((lane >> 4) << 3)) * 2);
#pragma unroll
        for (int nb = 0; nb < 2; nb++) {
            uint32_t b0, b1, b2, b3;
            int row = jhalf + nb * 16 + ((lane & 7) | ((lane >> 1) & 8));
            int col = ks * 16 + ((lane & 8) ? 8 : 0);
            ldsm_x4(b0, b1, b2, b3, Kb + (row * 72 + col) * 2);
            mma_bf16(c[nb*2][0], c[nb*2][1], c[nb*2][2], c[nb*2][3], a0, a1, a2, a3, b0, b1);
            mma_bf16(c[nb*2+1][0], c[nb*2+1][1], c[nb*2+1][2], c[nb*2+1][3], a0, a1, a2, a3, b2, b3);
        }
    }
    int r = lane >> 2, cc = 2 * (lane & 3);
#pragma unroll
    for (int nb = 0; nb < 4; nb++) {
        int j = j0 + jhalf + nb * 8 + cc;
        *(float2*)(g_scores + (size_t)(i0 + iblk + r) * NH + h * N_TOK + j)     = make_float2(c[nb][0], c[nb][1]);
        *(float2*)(g_scores + (size_t)(i0 + iblk + r + 8) * NH + h * N_TOK + j) = make_float2(c[nb][2], c[nb][3]);
    }
}

// ---------------- K3: fused structure-scores + softmax + acct + combine --
// pass 1: logits + softmax -> p (g_scores AND p_sh, normalized)
// pass 2: acc_t = p @ S (re-reads CTA's S slice, now L2-hot), then
//         outpre = acc_t @ Wsv + bsv  (accv added later by fgemm accum).
// smem layout (bytes):
//   region A [0, 32768): pass1 S_sh(18432)+W_sh(9216)+q_sh(1152)+bsk(256);
//                        pass2 partials [16][512]; epilogue Wsv[64][64]
//   p_sh     [32768, 65536): [8 h][1024 j] normalized p
//   tsh      [65536, 67584): acc_t [8 h][64 e]
#define SS2_P    32768
#define SS2_T    65536
#define SS2_SMEM 67584
__global__ __launch_bounds__(256, 2) void sscore_kernel(
        const float* __restrict__ S,
        const __nv_bfloat16* __restrict__ qb,
        const float* __restrict__ Wsk,
        const float* __restrict__ bsk,
        const float* __restrict__ Wsv,
        const float* __restrict__ bsv) {
    extern __shared__ __align__(16) char dyn[];
    uint16_t* S_sh  = (uint16_t*)dyn;              // [128 j][72 c]
    uint16_t* W_sh  = (uint16_t*)(dyn + 18432);    // [64 e][72 c]
    uint16_t* q_sh  = (uint16_t*)(dyn + 27648);    // [8 h][72 e]
    float*    bsk_sh = (float*)(dyn + 28800);      // 64
    float*    p_sh  = (float*)(dyn + SS2_P);       // [8 h][1024 j]
    float*    tsh   = (float*)(dyn + SS2_T);       // [512]

    const int i    = blockIdx.x;
    const int t    = threadIdx.x;
    const int lane = t & 31;
    const int w    = t >> 5;

#pragma unroll
    for (int r = 0; r < 16; r++) {
        int f = r * 256 + t;
        int c = f >> 6, e = f & 63;
        __nv_bfloat16 b = __float2bfloat16(Wsk[f]);
        W_sh[e * 72 + c] = *(uint16_t*)&b;
    }
    if (t < 64) {
        int h = t >> 3, e8 = (t & 7) * 8;
        *(uint4*)&q_sh[h * 72 + e8] = *(const uint4*)(qb + (size_t)i * DM + h * DK + e8);
        bsk_sh[t] = bsk[t];
    }
    __syncthreads();

    const uint32_t Sbase = sptr(S_sh);
    const uint32_t Wbase = sptr(W_sh);
    const uint32_t qbase = sptr(q_sh);
    const uint32_t offA = ((w * 16 + (lane & 15)) * 72 + ((lane >> 4) << 3)) * 2;
    const uint32_t offB = ((lane & 7) * 72 + (((lane >> 3) & 1) << 3)) * 2;
    const uint32_t offW = ((lane & 7) * 72 + (((lane >> 3) & 1) << 3)) * 2 + ((lane >> 4) << 5);

    uint32_t qf[4][2];
#pragma unroll
    for (int ek = 0; ek < 4; ek++)
        ldsm_x2(qf[ek][0], qf[ek][1], qbase + offB + ek * 32);

    const int ecol = 2 * (lane & 3);
    const float* Srow = S + (size_t)i * N_TOK * 64;
    const int prow = t >> 4;
    const int pc4  = (t & 15) * 4;

    // prefetch S tile 0 into registers
    float4 pf[8];
#pragma unroll
    for (int r = 0; r < 8; r++)
        pf[r] = *(const float4*)(Srow + (size_t)(r * 16 + prow) * 64 + pc4);

    for (int j0 = 0; j0 < N_TOK; j0 += 128) {
        __syncthreads();
#pragma unroll
        for (int r = 0; r < 8; r++) {
            int jj = r * 16 + prow;
            uint32_t lo = pack_bf16x2(pf[r].x, pf[r].y);
            uint32_t hi = pack_bf16x2(pf[r].z, pf[r].w);
            *(uint2*)&S_sh[jj * 72 + pc4] = make_uint2(lo, hi);
        }
        __syncthreads();

        if (j0 + 128 < N_TOK) {
            const float* Snext = Srow + (size_t)(j0 + 128) * 64;
#pragma unroll
            for (int r = 0; r < 8; r++)
                pf[r] = *(const float4*)(Snext + (size_t)(r * 16 + prow) * 64 + pc4);
        }

        uint32_t sa[4][4];
#pragma unroll
        for (int ck = 0; ck < 4; ck++)
            ldsm_x4(sa[ck][0], sa[ck][1], sa[ck][2], sa[ck][3], Sbase + offA + ck * 32);

        uint32_t skl[8], skh[8];
#pragma unroll
        for (int et = 0; et < 8; et++) {
            float c0 = 0.f, c1 = 0.f, c2 = 0.f, c3 = 0.f;
#pragma unroll
            for (int ck = 0; ck < 4; ck += 2) {
                uint32_t b0, b1, b2, b3;
                ldsm_x4(b0, b1, b2, b3, Wbase + offW + et * (8 * 72 * 2) + ck * 32);
                mma_bf16(c0, c1, c2, c3, sa[ck][0], sa[ck][1], sa[ck][2], sa[ck][3], b0, b1);
                mma_bf16(c0, c1, c2, c3, sa[ck+1][0], sa[ck+1][1], sa[ck+1][2], sa[ck+1][3], b2, b3);
            }
            float blo = bsk_sh[et * 8 + ecol];
            float bhi = bsk_sh[et * 8 + ecol + 1];
            c0 = fmaxf(c0 + blo, 0.f); c1 = fmaxf(c1 + bhi, 0.f);
            c2 = fmaxf(c2 + blo, 0.f); c3 = fmaxf(c3 + bhi, 0.f);
            skl[et] = pack_bf16x2(c0, c1);
            skh[et] = pack_bf16x2(c2, c3);
        }

        float s0 = 0.f, s1 = 0.f, s2 = 0.f, s3 = 0.f;
#pragma unroll
        for (int ek = 0; ek < 4; ek++)
            mma_bf16(s0, s1, s2, s3,
                     skl[2*ek], skh[2*ek], skl[2*ek+1], skh[2*ek+1],
                     qf[ek][0], qf[ek][1]);

        int jw = j0 + w * 16 + (lane >> 2);
        int h0 = 2 * (lane & 3);
        p_sh[h0 * N_TOK + jw]           = s0;
        p_sh[(h0 + 1) * N_TOK + jw]     = s1;
        p_sh[h0 * N_TOK + jw + 8]       = s2;
        p_sh[(h0 + 1) * N_TOK + jw + 8] = s3;
    }
    __syncthreads();

    // softmax: warp w owns row h=w; normalized p -> g_scores AND p_sh
    {
        float* row = p_sh + w * N_TOK;
        float* gsc = g_scores + (size_t)i * NH + w * N_TOK;
        float mx = -1e30f;
#pragma unroll
        for (int rr = 0; rr < 8; rr++) {
            int idx = rr * 128 + lane * 4;
            float4 g = *(const float4*)(gsc + idx);
            float4 p = *(float4*)(row + idx);
            p.x = (p.x + g.x) * SCALE; p.y = (p.y + g.y) * SCALE;
            p.z = (p.z + g.z) * SCALE; p.w = (p.w + g.w) * SCALE;
            *(float4*)(row + idx) = p;
            mx = fmaxf(mx, fmaxf(fmaxf(p.x, p.y), fmaxf(p.z, p.w)));
        }
#pragma unroll
        for (int o = 16; o; o >>= 1) mx = fmaxf(mx, __shfl_xor_sync(0xffffffffu, mx, o));
        float sum = 0.f;
#pragma unroll
        for (int rr = 0; rr < 8; rr++) {
            int idx = rr * 128 + lane * 4;
            float4 p = *(float4*)(row + idx);
            p.x = __expf(p.x - mx); p.y = __expf(p.y - mx);
            p.z = __expf(p.z - mx); p.w = __expf(p.w - mx);
            *(float4*)(row + idx) = p;
            sum += p.x + p.y + p.z + p.w;
        }
#pragma unroll
        for (int o = 16; o; o >>= 1) sum += __shfl_xor_sync(0xffffffffu, sum, o);
        float inv = 1.0f / sum;
#pragma unroll
        for (int rr = 0; rr < 8; rr++) {
            int idx = rr * 128 + lane * 4;
            float4 p = *(float4*)(row + idx);
            p.x *= inv; p.y *= inv; p.z *= inv; p.w *= inv;
            *(float4*)(row + idx) = p;           // normalized p for pass 2
            *(float4*)(gsc + idx) = p;           // for accv fgemm
        }
    }
    __syncthreads();   // p_sh final; region A free

    // ---- pass 2: acc_t[h][e] = sum_j p[h][j] * S[i][j][e] (S L2-hot) ----
    {
        const int e4b  = (t & 15) * 4;
        const int joff = t >> 4;
        float4 acc[8];
#pragma unroll
        for (int h = 0; h < 8; h++) acc[h] = make_float4(0.f, 0.f, 0.f, 0.f);

#pragma unroll 4
        for (int j = joff; j < N_TOK; j += 16) {
            float4 s = *(const float4*)(Srow + (size_t)j * 64 + e4b);
#pragma unroll
            for (int h = 0; h < 8; h++) {
                float p = p_sh[h * N_TOK + j];
                acc[h].x += p * s.x; acc[h].y += p * s.y;
                acc[h].z += p * s.z; acc[h].w += p * s.w;
            }
        }

        float* part = (float*)dyn;   // [16][512], overlays dead pass-1 tiles
#pragma unroll
        for (int h = 0; h < 8; h++)
            *(float4*)&part[joff * 512 + h * 64 + e4b] = acc[h];
        __syncthreads();

#pragma unroll
        for (int r = 0; r < 2; r++) {
            int o = r * 256 + t;   // h*64 + e
            float s = 0.f;
#pragma unroll
            for (int jo = 0; jo < 16; jo++) s += part[jo * 512 + o];
            tsh[o] = s;
        }
        __syncthreads();   // tsh ready; partials dead

        // Wsv [e][d] into region A
#pragma unroll
        for (int r = 0; r < 4; r++) {
            int f = r * 256 + t;
            *(float4*)&part[f * 4] = *(const float4*)(Wsv + f * 4);
        }
        __syncthreads();

        int d  = t & 63;
        int h0 = t >> 6;
        float bd = bsv[d];
#pragma unroll
        for (int r = 0; r < 2; r++) {
            int h = h0 + r * 4;
            float a = 0.f;
#pragma unroll 16
            for (int e = 0; e < 64; e++) a += tsh[h * 64 + e] * part[e * 64 + d];
            g_outpre[(size_t)i * DM + h * DK + d] = a + bd;
        }
    }
}

// ---------------- launch ----------------
extern "C" void kernel_launch(void* const* d_in, const int* in_sizes, int n_in,
                              void* d_out, int out_size) {
    const float* x   = (const float*)d_in[0];
    const float* S   = (const float*)d_in[1];
    const float* Wq  = (const float*)d_in[2];  const float* bq  = (const float*)d_in[3];
    const float* Wk  = (const float*)d_in[4];  const float* bk  = (const float*)d_in[5];
    const float* Wv  = (const float*)d_in[6];  const float* bv  = (const float*)d_in[7];
    const float* Wo  = (const float*)d_in[8];  const float* bo  = (const float*)d_in[9];
    const float* Wsk = (const float*)d_in[10]; const float* bsk = (const float*)d_in[11];
    const float* Wsv = (const float*)d_in[12]; const float* bsv = (const float*)d_in[13];
    float* out = (float*)d_out;

    void *pxb, *pwt, *pwt2, *pqb, *pkb, *pv, *pop, *psc;
    cudaGetSymbolAddress(&pxb, g_xb);
    cudaGetSymbolAddress(&pwt, g_wt);
    cudaGetSymbolAddress(&pwt2, g_wt2);
    cudaGetSymbolAddress(&pqb, g_qb);
    cudaGetSymbolAddress(&pkb, g_kb);
    cudaGetSymbolAddress(&pv,  g_v);
    cudaGetSymbolAddress(&pop, g_outpre);
    cudaGetSymbolAddress(&psc, g_scores);
    __nv_bfloat16* xb  = (__nv_bfloat16*)pxb;
    __nv_bfloat16* wt  = (__nv_bfloat16*)pwt;
    __nv_bfloat16* wt2 = (__nv_bfloat16*)pwt2;

    cudaFuncSetAttribute(sscore_kernel, cudaFuncAttributeMaxDynamicSharedMemorySize, SS2_SMEM);
    cudaFuncSetAttribute(fgemm_split_kernel, cudaFuncAttributeMaxDynamicSharedMemorySize, FG_SMEM);

    // x -> bf16 (logit path only)
    xconv_kernel<<<N_TOK * DM / 1024, 256>>>(x, xb);

    // q/k weight transposes and projections, merged into z=2 launches
    wtrans2_kernel<<<dim3(16, 16, 2), 256>>>(Wq, Wk, wt, wt2);
    proj2_gemm_bf16<<<dim3(DM / 64, N_TOK / 64, 2), 256>>>(
        xb, wt, wt2, bq, bk, (__nv_bfloat16*)pqb, (__nv_bfloat16*)pkb);

    // v projection: split-bf16 tensor-core GEMM (near-fp32 exact, pipelined)
    fgemm_split_kernel<<<dim3(DM / 64, N_TOK / 64), 256, FG_SMEM>>>(
        x, DM, 0, Wv, DM, 0, (float*)pv, DM, 0, DM, bv, 0);

    // qk scores (bf16 mma, fp32 out)
    qk_mma_kernel<<<dim3(16, 16, 8), 256>>>((const __nv_bfloat16*)pqb, (const __nv_bfloat16*)pkb);

    // structure scores + softmax + acct + combine -> p (g_scores) & outpre
    sscore_kernel<<<N_TOK, 256, SS2_SMEM>>>(S, (const __nv_bfloat16*)pqb, Wsk, bsk, Wsv, bsv);

    // acc_v = p @ v, accumulated directly into outpre (one z-slab per head)
    fgemm_split_kernel<<<dim3(1, 16, 8), 256, FG_SMEM>>>(
        (const float*)psc, NH, N_TOK,
        (const float*)pv,  DM, DK,
        (float*)pop,       DM, DK,
        N_TOK, nullptr, 1);

    // final output projection: split-bf16 GEMM (pipelined)
    fgemm_split_kernel<<<dim3(DM / 64, N_TOK / 64), 256, FG_SMEM>>>(
        (const float*)pop, DM, 0, Wo, DM, 0, out, DM, 0, DM, bo, 0);
}